// round 1
// baseline (speedup 1.0000x reference)
#include <cuda_runtime.h>
#include <cstdint>

#define NU_ 50000
#define NF_ 50000
#define NN_ 100000
#define D_ 64
#define H2_ 32
#define K_ 256
#define E_ 500000
#define EP_ 500000
#define EN_ 500000
#define NND_ (NN_*D_)
#define NUD_ (NU_*D_)
#define NFD_ (NF_*D_)

// ---------------- scratch (static device globals; no allocation) ----------------
__device__ float g_u[NUD_];
__device__ float g_f[NFD_];
__device__ float g_x[NND_];
__device__ float g_z[NND_];
__device__ float g_z2[NND_];
__device__ float g_aggP[NND_];
__device__ float g_aggN[NND_];
__device__ int   g_cntp[NN_];
__device__ int   g_cntn[NN_];
__device__ float g_maskF[E_];
__device__ float g_maskS[E_];
__device__ float g_w[E_];
__device__ float g_norm[E_];
__device__ float g_deg[NN_];
__device__ float g_acc[NND_];
__device__ float g_xkA[NND_];
__device__ float g_xkB[NND_];
__device__ float g_sums[4];   // [0]=sum|mask_feature|  [1]=sum|mask_semantic|

static inline int cdiv(int a, int b) { return (a + b - 1) / b; }

// ---------------- generic utility kernels ----------------
__global__ void k_zero(float4* __restrict__ p, int n4) {
    int i = blockIdx.x * blockDim.x + threadIdx.x;
    if (i < n4) p[i] = make_float4(0.f, 0.f, 0.f, 0.f);
}

__global__ void k_copy(float4* __restrict__ d, const float4* __restrict__ s, int n4) {
    int i = blockIdx.x * blockDim.x + threadIdx.x;
    if (i < n4) d[i] = s[i];
}

__global__ void k_addacc(float4* __restrict__ acc, const float4* __restrict__ xk, int n4) {
    int i = blockIdx.x * blockDim.x + threadIdx.x;
    if (i < n4) {
        float4 a = acc[i]; float4 b = xk[i];
        a.x += b.x; a.y += b.y; a.z += b.z; a.w += b.w;
        acc[i] = a;
    }
}

__device__ __forceinline__ float block_reduce_sum_256(float v) {
    __shared__ float sh[8];
    int lane = threadIdx.x & 31, w = threadIdx.x >> 5;
    #pragma unroll
    for (int o = 16; o > 0; o >>= 1) v += __shfl_down_sync(0xffffffffu, v, o);
    if (lane == 0) sh[w] = v;
    __syncthreads();
    if (w == 0) {
        v = (lane < 8) ? sh[lane] : 0.f;
        #pragma unroll
        for (int o = 4; o > 0; o >>= 1) v += __shfl_down_sync(0xffffffffu, v, o);
    }
    return v;  // valid on thread 0
}

// ---------------- feature GEMM: C[M,64] = relu(A[M,256] @ W[256,64] + b) ----------------
__global__ __launch_bounds__(256) void k_gemm_relu(
    const float* __restrict__ A, const float* __restrict__ W,
    const float* __restrict__ bias, float* __restrict__ C, int M)
{
    __shared__ __align__(16) float AsT[64][68];  // [k][m], padded
    __shared__ __align__(16) float Ws[64][64];   // [k][n]
    int tid = threadIdx.x;
    int r0 = blockIdx.x * 64;
    int tr = tid >> 4, tc = tid & 15;
    float acc[4][4];
    #pragma unroll
    for (int i = 0; i < 4; i++)
        #pragma unroll
        for (int j = 0; j < 4; j++) acc[i][j] = 0.f;

    for (int kc = 0; kc < K_; kc += 64) {
        #pragma unroll
        for (int it = 0; it < 16; it++) {
            int idx = tid + it * 256;
            int lr = idx >> 6, lk = idx & 63;
            int gr = r0 + lr;
            AsT[lk][lr] = (gr < M) ? A[(size_t)gr * K_ + kc + lk] : 0.f;
        }
        #pragma unroll
        for (int it = 0; it < 16; it++) {
            int idx = tid + it * 256;
            int lk = idx >> 6, n = idx & 63;
            Ws[lk][n] = W[(size_t)(kc + lk) * 64 + n];
        }
        __syncthreads();
        #pragma unroll 4
        for (int kk = 0; kk < 64; kk++) {
            float4 a4 = *reinterpret_cast<const float4*>(&AsT[kk][tr * 4]);
            float4 w4 = *reinterpret_cast<const float4*>(&Ws[kk][tc * 4]);
            float av[4] = {a4.x, a4.y, a4.z, a4.w};
            float wv[4] = {w4.x, w4.y, w4.z, w4.w};
            #pragma unroll
            for (int i = 0; i < 4; i++)
                #pragma unroll
                for (int j = 0; j < 4; j++)
                    acc[i][j] = fmaf(av[i], wv[j], acc[i][j]);
        }
        __syncthreads();
    }
    #pragma unroll
    for (int i = 0; i < 4; i++) {
        int row = r0 + tr * 4 + i;
        if (row < M) {
            #pragma unroll
            for (int j = 0; j < 4; j++) {
                int col = tc * 4 + j;
                float v = acc[i][j] + bias[col];
                C[(size_t)row * 64 + col] = v > 0.f ? v : 0.f;
            }
        }
    }
}

// ---------------- per-edge metric cosine similarity mask ----------------
__global__ __launch_bounds__(256) void k_edge_sim(const int* __restrict__ ei,
                                                  const float* __restrict__ mw)
{
    __shared__ float smw[4 * 64];
    if (threadIdx.x < 256) smw[threadIdx.x] = mw[threadIdx.x];
    __syncthreads();
    int t = blockIdx.x * 256 + threadIdx.x;
    float m = 0.f;
    if (t < E_) {
        int e0 = ei[t], e1 = ei[E_ + t];
        const float4* ur = reinterpret_cast<const float4*>(g_u) + (size_t)e0 * 16;
        const float4* fr = reinterpret_cast<const float4*>(g_f) + (size_t)e1 * 16;
        float aa[4] = {0,0,0,0}, bb[4] = {0,0,0,0}, ab[4] = {0,0,0,0};
        #pragma unroll 4
        for (int i4 = 0; i4 < 16; i4++) {
            float4 uv = ur[i4]; float4 fv = fr[i4];
            float us[4] = {uv.x, uv.y, uv.z, uv.w};
            float fs[4] = {fv.x, fv.y, fv.z, fv.w};
            #pragma unroll
            for (int c = 0; c < 4; c++) {
                int i = i4 * 4 + c;
                #pragma unroll
                for (int h = 0; h < 4; h++) {
                    float w  = smw[h * 64 + i];
                    float wa = w * us[c];
                    float wb = w * fs[c];
                    aa[h] = fmaf(wa, wa, aa[h]);
                    bb[h] = fmaf(wb, wb, bb[h]);
                    ab[h] = fmaf(wa, wb, ab[h]);
                }
            }
        }
        float sim = 0.f;
        #pragma unroll
        for (int h = 0; h < 4; h++) {
            float na = fmaxf(sqrtf(aa[h]), 1e-8f);
            float nb = fmaxf(sqrtf(bb[h]), 1e-8f);
            sim += ab[h] / (na * nb);
        }
        sim *= 0.25f;
        m = (sim < 0.3f) ? 0.f : sim;
        g_maskF[t] = m;
    }
    float tot = block_reduce_sum_256(fabsf(m));
    if (threadIdx.x == 0) atomicAdd(&g_sums[0], tot);
}

// ---------------- segment counts ----------------
__global__ void k_count(const int* __restrict__ dst, int n, int* __restrict__ cnt) {
    int t = blockIdx.x * blockDim.x + threadIdx.x;
    if (t < n) atomicAdd(&cnt[dst[t]], 1);
}

// ---------------- scatter-add feature rows (segment_sum) ----------------
__global__ __launch_bounds__(256) void k_scatter(const int* __restrict__ src,
                                                 const int* __restrict__ dst, int n,
                                                 const float* __restrict__ feat,
                                                 float* __restrict__ out)
{
    int e = blockIdx.x * 256 + threadIdx.x;
    if (e >= n) return;
    int s = src[e], d = dst[e];
    const float4* fs = reinterpret_cast<const float4*>(feat + (size_t)s * 64);
    float* ob = out + (size_t)d * 64;
    #pragma unroll
    for (int c = 0; c < 16; c++) {
        float4 v = fs[c];
        atomicAdd(ob + c * 4 + 0, v.x);
        atomicAdd(ob + c * 4 + 1, v.y);
        atomicAdd(ob + c * 4 + 2, v.z);
        atomicAdd(ob + c * 4 + 3, v.w);
    }
}

// ---------------- signed conv layer 1 node transform ----------------
__global__ __launch_bounds__(128) void k_layer1(
    const float* __restrict__ pl, const float* __restrict__ prw, const float* __restrict__ pb,
    const float* __restrict__ nl, const float* __restrict__ nrw, const float* __restrict__ nb)
{
    __shared__ float sPl[2048], sPr[2048], sNl[2048], sNr[2048];
    __shared__ float sPb[32], sNb[32];
    int tid = threadIdx.x;
    for (int i = tid; i < 2048; i += 128) {
        sPl[i] = pl[i]; sPr[i] = prw[i]; sNl[i] = nl[i]; sNr[i] = nrw[i];
    }
    if (tid < 32) { sPb[tid] = pb[tid]; sNb[tid] = nb[tid]; }
    __syncthreads();
    int n = blockIdx.x * 128 + tid;
    if (n >= NN_) return;
    float cpInv = 1.f / (float)max(g_cntp[n], 1);
    float cnInv = 1.f / (float)max(g_cntn[n], 1);
    float accP[32], accN[32];
    #pragma unroll
    for (int j = 0; j < 32; j++) { accP[j] = 0.f; accN[j] = 0.f; }
    const float4* xr = reinterpret_cast<const float4*>(g_x    + (size_t)n * 64);
    const float4* pr = reinterpret_cast<const float4*>(g_aggP + (size_t)n * 64);
    const float4* nr = reinterpret_cast<const float4*>(g_aggN + (size_t)n * 64);
    #pragma unroll 1
    for (int i4 = 0; i4 < 16; i4++) {
        float4 xv4 = xr[i4]; float4 mp4 = pr[i4]; float4 mn4 = nr[i4];
        float xs[4] = {xv4.x, xv4.y, xv4.z, xv4.w};
        float ms[4] = {mp4.x * cpInv, mp4.y * cpInv, mp4.z * cpInv, mp4.w * cpInv};
        float ns[4] = {mn4.x * cnInv, mn4.y * cnInv, mn4.z * cnInv, mn4.w * cnInv};
        #pragma unroll
        for (int c = 0; c < 4; c++) {
            int i = i4 * 4 + c;
            float xv = xs[c], mv = ms[c], nv = ns[c];
            const float* wpl = &sPl[i * 32];
            const float* wpr = &sPr[i * 32];
            const float* wnl = &sNl[i * 32];
            const float* wnr = &sNr[i * 32];
            #pragma unroll
            for (int j = 0; j < 32; j++) {
                accP[j] = fmaf(mv, wpl[j], fmaf(xv, wpr[j], accP[j]));
                accN[j] = fmaf(nv, wnl[j], fmaf(xv, wnr[j], accN[j]));
            }
        }
    }
    float* zr = g_z + (size_t)n * 64;
    #pragma unroll
    for (int j = 0; j < 32; j++) {
        float v = accP[j] + sPb[j]; zr[j]      = v > 0.f ? v : 0.f;
        v = accN[j] + sNb[j];       zr[32 + j] = v > 0.f ? v : 0.f;
    }
}

// ---------------- signed conv layers 2/3 node transform ----------------
__global__ __launch_bounds__(128) void k_layer23(
    const float* __restrict__ pl, const float* __restrict__ prw, const float* __restrict__ pb,
    const float* __restrict__ nl, const float* __restrict__ nrw, const float* __restrict__ nb,
    const float* __restrict__ zin, float* __restrict__ zout)
{
    __shared__ float sPl[2048], sNl[2048], sPr[1024], sNr[1024];
    __shared__ float sPb[32], sNb[32];
    int tid = threadIdx.x;
    for (int i = tid; i < 2048; i += 128) { sPl[i] = pl[i]; sNl[i] = nl[i]; }
    for (int i = tid; i < 1024; i += 128) { sPr[i] = prw[i]; sNr[i] = nrw[i]; }
    if (tid < 32) { sPb[tid] = pb[tid]; sNb[tid] = nb[tid]; }
    __syncthreads();
    int n = blockIdx.x * 128 + tid;
    if (n >= NN_) return;
    float cpInv = 1.f / (float)max(g_cntp[n], 1);
    float cnInv = 1.f / (float)max(g_cntn[n], 1);
    float accP[32], accN[32];
    #pragma unroll
    for (int j = 0; j < 32; j++) { accP[j] = 0.f; accN[j] = 0.f; }
    const float4* z4 = reinterpret_cast<const float4*>(zin    + (size_t)n * 64);
    const float4* aP = reinterpret_cast<const float4*>(g_aggP + (size_t)n * 64);
    const float4* aN = reinterpret_cast<const float4*>(g_aggN + (size_t)n * 64);
    #pragma unroll 1
    for (int i4 = 0; i4 < 8; i4++) {
        float4 zp4 = z4[i4], zn4 = z4[8 + i4];
        float4 aPlo4 = aP[i4], aPhi4 = aP[8 + i4];
        float4 aNlo4 = aN[i4], aNhi4 = aN[8 + i4];
        float zps[4] = {zp4.x, zp4.y, zp4.z, zp4.w};
        float zns[4] = {zn4.x, zn4.y, zn4.z, zn4.w};
        float aplo[4] = {aPlo4.x * cpInv, aPlo4.y * cpInv, aPlo4.z * cpInv, aPlo4.w * cpInv}; // ap[i]   = mean_pos(xp)
        float anlo[4] = {aPhi4.x * cpInv, aPhi4.y * cpInv, aPhi4.z * cpInv, aPhi4.w * cpInv}; // an[i]   = mean_pos(xn)
        float aphi[4] = {aNhi4.x * cnInv, aNhi4.y * cnInv, aNhi4.z * cnInv, aNhi4.w * cnInv}; // ap[i+32]= mean_neg(xn)
        float anhi[4] = {aNlo4.x * cnInv, aNlo4.y * cnInv, aNlo4.z * cnInv, aNlo4.w * cnInv}; // an[i+32]= mean_neg(xp)
        #pragma unroll
        for (int c = 0; c < 4; c++) {
            int i = i4 * 4 + c;
            const float* wPlo = &sPl[i * 32];
            const float* wPhi = &sPl[(i + 32) * 32];
            const float* wNlo = &sNl[i * 32];
            const float* wNhi = &sNl[(i + 32) * 32];
            const float* wPr  = &sPr[i * 32];
            const float* wNr  = &sNr[i * 32];
            float apl = aplo[c], aph = aphi[c], anl_ = anlo[c], anh = anhi[c];
            float xpv = zps[c], xnv = zns[c];
            #pragma unroll
            for (int j = 0; j < 32; j++) {
                accP[j] = fmaf(apl, wPlo[j], fmaf(aph, wPhi[j], fmaf(xpv, wPr[j], accP[j])));
                accN[j] = fmaf(anl_, wNlo[j], fmaf(anh, wNhi[j], fmaf(xnv, wNr[j], accN[j])));
            }
        }
    }
    float* zr = zout + (size_t)n * 64;
    #pragma unroll
    for (int j = 0; j < 32; j++) {
        float v = accP[j] + sPb[j]; zr[j]      = v > 0.f ? v : 0.f;
        v = accN[j] + sNb[j];       zr[32 + j] = v > 0.f ? v : 0.f;
    }
}

// ---------------- per-edge classifier -> semantic mask ----------------
__global__ __launch_bounds__(256) void k_val(const int* __restrict__ ei,
                                             const float* __restrict__ lw,
                                             const float* __restrict__ lb)
{
    __shared__ float slw[384];
    for (int i = threadIdx.x; i < 384; i += 256) slw[i] = lw[i];
    __syncthreads();
    int t = blockIdx.x * 256 + threadIdx.x;
    float m = 0.f;
    if (t < E_) {
        int e0 = ei[t], e1 = ei[E_ + t];
        float l0 = lb[0], l1 = lb[1], l2 = lb[2];
        const float4* za = reinterpret_cast<const float4*>(g_z + (size_t)e0 * 64);
        const float4* zb = reinterpret_cast<const float4*>(g_z + (size_t)e1 * 64);
        #pragma unroll 4
        for (int i4 = 0; i4 < 16; i4++) {
            float4 a4 = za[i4]; float4 b4 = zb[i4];
            float as[4] = {a4.x, a4.y, a4.z, a4.w};
            float bs[4] = {b4.x, b4.y, b4.z, b4.w};
            #pragma unroll
            for (int c = 0; c < 4; c++) {
                int i = i4 * 4 + c;
                l0 = fmaf(as[c], slw[i * 3 + 0], fmaf(bs[c], slw[(64 + i) * 3 + 0], l0));
                l1 = fmaf(as[c], slw[i * 3 + 1], fmaf(bs[c], slw[(64 + i) * 3 + 1], l1));
                l2 = fmaf(as[c], slw[i * 3 + 2], fmaf(bs[c], slw[(64 + i) * 3 + 2], l2));
            }
        }
        int cls = 0; float best = l0;
        if (l1 > best) { best = l1; cls = 1; }
        if (l2 > best) { cls = 2; }
        m = (float)(cls - 1);
        g_maskS[t] = m;
    }
    float tot = block_reduce_sum_256(fabsf(m));
    if (threadIdx.x == 0) atomicAdd(&g_sums[1], tot);
}

// ---------------- mask fusion -> binary edge weight + degree ----------------
__global__ void k_fuse(const int* __restrict__ ei, const float* __restrict__ fw) {
    int t = blockIdx.x * blockDim.x + threadIdx.x;
    if (t >= E_) return;
    float w0 = fw[0], w1 = fw[1], w2 = fw[2];
    float mx = fmaxf(w0, fmaxf(w1, w2));
    float x0 = expf(w0 - mx), x1 = expf(w1 - mx), x2 = expf(w2 - mx);
    float si = 1.f / (x0 + x1 + x2);
    float Sf = fmaxf(g_sums[0], 1e-12f);
    float Ss = fmaxf(g_sums[1], 1e-12f);
    float fused = x0 * si * (1.0f / (float)E_)
                + x1 * si * g_maskF[t] / Sf
                + x2 * si * g_maskS[t] / Ss;
    float w = (fused > 0.5f) ? 1.f : 0.f;
    g_w[t] = w;
    if (w != 0.f) atomicAdd(&g_deg[ei[t]], w);
}

__global__ void k_normc(const int* __restrict__ ei) {
    int t = blockIdx.x * blockDim.x + threadIdx.x;
    if (t >= E_) return;
    float w = g_w[t];
    if (w == 0.f) { g_norm[t] = 0.f; return; }
    int a = ei[t], b = ei[E_ + t];
    float d0 = g_deg[a], d1 = g_deg[b];
    float dis0 = d0 > 0.f ? rsqrtf(fmaxf(d0, 1e-12f)) : 0.f;
    float dis1 = d1 > 0.f ? rsqrtf(fmaxf(d1, 1e-12f)) : 0.f;
    g_norm[t] = dis0 * w * dis1;
}

// ---------------- LightGCN propagation hop (skips zero-weight edges) ----------------
__global__ __launch_bounds__(256) void k_prop(const int* __restrict__ ei,
                                              const float* __restrict__ xin,
                                              float* __restrict__ xout)
{
    int e = blockIdx.x * 256 + threadIdx.x;
    if (e >= E_) return;
    float nv = g_norm[e];
    if (nv == 0.f) return;
    int d = ei[e], s = ei[E_ + e];
    const float4* xs = reinterpret_cast<const float4*>(xin + (size_t)s * 64);
    float* ob = xout + (size_t)d * 64;
    #pragma unroll
    for (int c = 0; c < 16; c++) {
        float4 v = xs[c];
        atomicAdd(ob + c * 4 + 0, nv * v.x);
        atomicAdd(ob + c * 4 + 1, nv * v.y);
        atomicAdd(ob + c * 4 + 2, nv * v.z);
        atomicAdd(ob + c * 4 + 3, nv * v.w);
    }
}

// ---------------- final output assembly ----------------
__global__ void k_output(float* __restrict__ out,
                         const float* __restrict__ lgu, const float* __restrict__ lgi)
{
    int t = blockIdx.x * blockDim.x + threadIdx.x;
    if (t >= NND_) return;
    if (t < NUD_) {
        out[t]         = g_acc[t] * 0.25f;
        out[NUD_ + t]  = lgu[t];
    } else {
        int j = t - NUD_;
        out[2 * NUD_ + j]        = g_acc[t] * 0.25f;
        out[2 * NUD_ + NFD_ + j] = lgi[j];
    }
}

// ---------------- host orchestration ----------------
extern "C" void kernel_launch(void* const* d_in, const int* in_sizes, int n_in,
                              void* d_out, int out_size)
{
    (void)in_sizes; (void)n_in; (void)out_size;
    const float* user_feat = (const float*)d_in[0];
    const float* food_feat = (const float*)d_in[1];
    const int*   edge      = (const int*)d_in[2];
    const int*   pedge     = (const int*)d_in[3];
    const int*   nedge     = (const int*)d_in[4];
    const float* W_user    = (const float*)d_in[5];
    const float* b_user    = (const float*)d_in[6];
    const float* W_food    = (const float*)d_in[7];
    const float* b_food    = (const float*)d_in[8];
    const float* metric    = (const float*)d_in[9];
    const float* fusion    = (const float*)d_in[10];
    const float* sg_u      = (const float*)d_in[11];
    const float* sg_i      = (const float*)d_in[12];
    const float* c1pl      = (const float*)d_in[13];
    const float* c1pr      = (const float*)d_in[14];
    const float* c1pb      = (const float*)d_in[15];
    const float* c1nl      = (const float*)d_in[16];
    const float* c1nr      = (const float*)d_in[17];
    const float* c1nb      = (const float*)d_in[18];
    const float* cspl      = (const float*)d_in[19];
    const float* cspr      = (const float*)d_in[20];
    const float* cspb      = (const float*)d_in[21];
    const float* csnl      = (const float*)d_in[22];
    const float* csnr      = (const float*)d_in[23];
    const float* csnb      = (const float*)d_in[24];
    const float* linw      = (const float*)d_in[25];
    const float* linb      = (const float*)d_in[26];
    const float* lg_u      = (const float*)d_in[27];
    const float* lg_i      = (const float*)d_in[28];
    float* out = (float*)d_out;

    float *pu, *pf, *px, *pz, *pz2, *paggP, *paggN, *pacc, *pxkA, *pxkB, *psums, *pdeg;
    int *pcntp, *pcntn;
    cudaGetSymbolAddress((void**)&pu,    g_u);
    cudaGetSymbolAddress((void**)&pf,    g_f);
    cudaGetSymbolAddress((void**)&px,    g_x);
    cudaGetSymbolAddress((void**)&pz,    g_z);
    cudaGetSymbolAddress((void**)&pz2,   g_z2);
    cudaGetSymbolAddress((void**)&paggP, g_aggP);
    cudaGetSymbolAddress((void**)&paggN, g_aggN);
    cudaGetSymbolAddress((void**)&pacc,  g_acc);
    cudaGetSymbolAddress((void**)&pxkA,  g_xkA);
    cudaGetSymbolAddress((void**)&pxkB,  g_xkB);
    cudaGetSymbolAddress((void**)&psums, g_sums);
    cudaGetSymbolAddress((void**)&pdeg,  g_deg);
    cudaGetSymbolAddress((void**)&pcntp, g_cntp);
    cudaGetSymbolAddress((void**)&pcntn, g_cntn);

    const int ZB = 256;
    // zero accumulators
    k_zero<<<1, 32>>>((float4*)psums, 1);
    k_zero<<<cdiv(NN_ / 4, ZB), ZB>>>((float4*)pcntp, NN_ / 4);
    k_zero<<<cdiv(NN_ / 4, ZB), ZB>>>((float4*)pcntn, NN_ / 4);
    k_zero<<<cdiv(NN_ / 4, ZB), ZB>>>((float4*)pdeg,  NN_ / 4);
    k_zero<<<cdiv(NND_ / 4, ZB), ZB>>>((float4*)paggP, NND_ / 4);
    k_zero<<<cdiv(NND_ / 4, ZB), ZB>>>((float4*)paggN, NND_ / 4);

    // feature GEMMs
    k_gemm_relu<<<cdiv(NU_, 64), 256>>>(user_feat, W_user, b_user, pu, NU_);
    k_gemm_relu<<<cdiv(NF_, 64), 256>>>(food_feat, W_food, b_food, pf, NF_);

    // feature-similarity mask
    k_edge_sim<<<cdiv(E_, 256), 256>>>(edge, metric);

    // signed-graph conv: x = concat(sg_users, sg_items)
    k_copy<<<cdiv(NUD_ / 4, ZB), ZB>>>((float4*)px, (const float4*)sg_u, NUD_ / 4);
    k_copy<<<cdiv(NFD_ / 4, ZB), ZB>>>((float4*)(px + NUD_), (const float4*)sg_i, NFD_ / 4);
    k_count<<<cdiv(EP_, 256), 256>>>(pedge + EP_, EP_, pcntp);
    k_count<<<cdiv(EN_, 256), 256>>>(nedge + EN_, EN_, pcntn);

    // layer 1
    k_scatter<<<cdiv(EP_, 256), 256>>>(pedge, pedge + EP_, EP_, px, paggP);
    k_scatter<<<cdiv(EN_, 256), 256>>>(nedge, nedge + EN_, EN_, px, paggN);
    k_layer1<<<cdiv(NN_, 128), 128>>>(c1pl, c1pr, c1pb, c1nl, c1nr, c1nb);

    // layer 2
    k_zero<<<cdiv(NND_ / 4, ZB), ZB>>>((float4*)paggP, NND_ / 4);
    k_zero<<<cdiv(NND_ / 4, ZB), ZB>>>((float4*)paggN, NND_ / 4);
    k_scatter<<<cdiv(EP_, 256), 256>>>(pedge, pedge + EP_, EP_, pz, paggP);
    k_scatter<<<cdiv(EN_, 256), 256>>>(nedge, nedge + EN_, EN_, pz, paggN);
    k_layer23<<<cdiv(NN_, 128), 128>>>(cspl, cspr, cspb, csnl, csnr, csnb, pz, pz2);

    // layer 3
    k_zero<<<cdiv(NND_ / 4, ZB), ZB>>>((float4*)paggP, NND_ / 4);
    k_zero<<<cdiv(NND_ / 4, ZB), ZB>>>((float4*)paggN, NND_ / 4);
    k_scatter<<<cdiv(EP_, 256), 256>>>(pedge, pedge + EP_, EP_, pz2, paggP);
    k_scatter<<<cdiv(EN_, 256), 256>>>(nedge, nedge + EN_, EN_, pz2, paggN);
    k_layer23<<<cdiv(NN_, 128), 128>>>(cspl + 2048, cspr + 1024, cspb + 32,
                                       csnl + 2048, csnr + 1024, csnb + 32, pz2, pz);

    // semantic mask + fusion + edge weights
    k_val<<<cdiv(E_, 256), 256>>>(edge, linw, linb);
    k_fuse<<<cdiv(E_, 256), 256>>>(edge, fusion);
    k_normc<<<cdiv(E_, 256), 256>>>(edge);

    // LightGCN propagation: acc = emb; 3 hops
    k_copy<<<cdiv(NUD_ / 4, ZB), ZB>>>((float4*)pacc, (const float4*)lg_u, NUD_ / 4);
    k_copy<<<cdiv(NFD_ / 4, ZB), ZB>>>((float4*)(pacc + NUD_), (const float4*)lg_i, NFD_ / 4);
    k_copy<<<cdiv(NUD_ / 4, ZB), ZB>>>((float4*)pxkA, (const float4*)lg_u, NUD_ / 4);
    k_copy<<<cdiv(NFD_ / 4, ZB), ZB>>>((float4*)(pxkA + NUD_), (const float4*)lg_i, NFD_ / 4);

    k_zero<<<cdiv(NND_ / 4, ZB), ZB>>>((float4*)pxkB, NND_ / 4);
    k_prop<<<cdiv(E_, 256), 256>>>(edge, pxkA, pxkB);
    k_addacc<<<cdiv(NND_ / 4, ZB), ZB>>>((float4*)pacc, (const float4*)pxkB, NND_ / 4);

    k_zero<<<cdiv(NND_ / 4, ZB), ZB>>>((float4*)pxkA, NND_ / 4);
    k_prop<<<cdiv(E_, 256), 256>>>(edge, pxkB, pxkA);
    k_addacc<<<cdiv(NND_ / 4, ZB), ZB>>>((float4*)pacc, (const float4*)pxkA, NND_ / 4);

    k_zero<<<cdiv(NND_ / 4, ZB), ZB>>>((float4*)pxkB, NND_ / 4);
    k_prop<<<cdiv(E_, 256), 256>>>(edge, pxkA, pxkB);
    k_addacc<<<cdiv(NND_ / 4, ZB), ZB>>>((float4*)pacc, (const float4*)pxkB, NND_ / 4);

    // write output: [final_users, lg_users, final_items, lg_items]
    k_output<<<cdiv(NND_, 256), 256>>>(out, lg_u, lg_i);
}

// round 2
// speedup vs baseline: 1.9088x; 1.9088x over previous
#include <cuda_runtime.h>
#include <cstdint>

#define NU_ 50000
#define NF_ 50000
#define NN_ 100000
#define D_ 64
#define H2_ 32
#define K_ 256
#define E_ 500000
#define EP_ 500000
#define EN_ 500000
#define NND_ (NN_*D_)
#define NUD_ (NU_*D_)
#define NFD_ (NF_*D_)

// ---------------- scratch (static device globals; no allocation) ----------------
__device__ float g_u[NUD_];
__device__ float g_f[NFD_];
__device__ float g_x[NND_];
__device__ float g_z[NND_];
__device__ float g_z2[NND_];
__device__ float g_aggP[NND_];
__device__ float g_aggN[NND_];
__device__ int   g_cntp[NN_];
__device__ int   g_cntn[NN_];
__device__ int   g_offP[NN_ + 1];
__device__ int   g_offN[NN_ + 1];
__device__ int   g_cur[NN_];
__device__ int   g_adjP[EP_];
__device__ int   g_adjN[EN_];
__device__ int   g_bsum[128];
__device__ float g_maskF[E_];
__device__ float g_maskS[E_];
__device__ float g_w[E_];
__device__ float g_norm[E_];
__device__ float g_deg[NN_];
__device__ float g_acc[NND_];
__device__ float g_xkA[NND_];
__device__ float g_xkB[NND_];
__device__ float g_sums[4];   // [0]=sum|mask_feature|  [1]=sum|mask_semantic|

static inline int cdiv(int a, int b) { return (a + b - 1) / b; }

// ---------------- generic utility kernels ----------------
__global__ void k_zero(float4* __restrict__ p, int n4) {
    int i = blockIdx.x * blockDim.x + threadIdx.x;
    if (i < n4) p[i] = make_float4(0.f, 0.f, 0.f, 0.f);
}

__global__ void k_copy(float4* __restrict__ d, const float4* __restrict__ s, int n4) {
    int i = blockIdx.x * blockDim.x + threadIdx.x;
    if (i < n4) d[i] = s[i];
}

__global__ void k_addacc(float4* __restrict__ acc, const float4* __restrict__ xk, int n4) {
    int i = blockIdx.x * blockDim.x + threadIdx.x;
    if (i < n4) {
        float4 a = acc[i]; float4 b = xk[i];
        a.x += b.x; a.y += b.y; a.z += b.z; a.w += b.w;
        acc[i] = a;
    }
}

__device__ __forceinline__ float block_reduce_sum_256(float v) {
    __shared__ float sh[8];
    int lane = threadIdx.x & 31, w = threadIdx.x >> 5;
    #pragma unroll
    for (int o = 16; o > 0; o >>= 1) v += __shfl_down_sync(0xffffffffu, v, o);
    if (lane == 0) sh[w] = v;
    __syncthreads();
    if (w == 0) {
        v = (lane < 8) ? sh[lane] : 0.f;
        #pragma unroll
        for (int o = 4; o > 0; o >>= 1) v += __shfl_down_sync(0xffffffffu, v, o);
    }
    return v;  // valid on thread 0
}

// ---------------- CSR build: count -> scan -> fill ----------------
__global__ void k_count(const int* __restrict__ dst, int n, int* __restrict__ cnt) {
    int t = blockIdx.x * blockDim.x + threadIdx.x;
    if (t < n) atomicAdd(&cnt[dst[t]], 1);
}

__device__ __forceinline__ int warp_scan_incl(int v, int lane) {
    #pragma unroll
    for (int o = 1; o < 32; o <<= 1) {
        int u = __shfl_up_sync(0xffffffffu, v, o);
        if (lane >= o) v += u;
    }
    return v;
}

// per-block exclusive scan of cnt -> out, block totals -> bsum
__global__ __launch_bounds__(1024) void k_scan1(const int* __restrict__ cnt,
                                                int* __restrict__ out,
                                                int* __restrict__ bsum, int n)
{
    __shared__ int wsum[32];
    int t = threadIdx.x, lane = t & 31, w = t >> 5;
    int i = blockIdx.x * 1024 + t;
    int v = (i < n) ? cnt[i] : 0;
    int s = warp_scan_incl(v, lane);
    if (lane == 31) wsum[w] = s;
    __syncthreads();
    if (w == 0) {
        int x = (lane < 32) ? wsum[lane] : 0;
        x = warp_scan_incl(x, lane);
        wsum[lane] = x;
    }
    __syncthreads();
    int base = (w > 0) ? wsum[w - 1] : 0;
    if (i < n) out[i] = base + s - v;      // exclusive
    if (t == 1023) bsum[blockIdx.x] = base + s;  // block total
}

// exclusive scan of block sums in place (single block, <=128 sums)
__global__ __launch_bounds__(128) void k_scan2(int* __restrict__ bsum, int nb) {
    __shared__ int wsum[4];
    int t = threadIdx.x, lane = t & 31, w = t >> 5;
    int v = (t < nb) ? bsum[t] : 0;
    int s = warp_scan_incl(v, lane);
    if (lane == 31) wsum[w] = s;
    __syncthreads();
    int add = 0;
    #pragma unroll
    for (int k = 0; k < 4; k++) if (k < w) add += wsum[k];
    if (t < nb) bsum[t] = add + s - v;     // exclusive, in place
}

__global__ __launch_bounds__(1024) void k_scan3(int* __restrict__ out,
                                                const int* __restrict__ bsum, int n)
{
    int i = blockIdx.x * 1024 + threadIdx.x;
    if (i < n) out[i] += bsum[blockIdx.x];
}

__global__ void k_settail(int* __restrict__ off, int v) {
    if (threadIdx.x == 0) off[NN_] = v;
}

__global__ void k_fill(const int* __restrict__ src, const int* __restrict__ dst, int n,
                       int* __restrict__ cur, int* __restrict__ adj)
{
    int e = blockIdx.x * blockDim.x + threadIdx.x;
    if (e < n) {
        int d = dst[e];
        int slot = atomicAdd(&cur[d], 1);
        adj[slot] = src[e];
    }
}

// ---------------- warp-per-node segment MEAN gather (no float atomics) ----------------
__global__ __launch_bounds__(256) void k_gather(const int* __restrict__ off,
                                                const int* __restrict__ adj,
                                                const float* __restrict__ feat,
                                                float* __restrict__ outm)
{
    int g = blockIdx.x * 256 + threadIdx.x;
    int node = g >> 5, lane = g & 31;
    if (node >= NN_) return;
    int s = off[node], e = off[node + 1];
    float2 acc = make_float2(0.f, 0.f);
    const float2* base = reinterpret_cast<const float2*>(feat);
    for (int k = s; k < e; k++) {
        int sr = adj[k];
        float2 v = base[(size_t)sr * 32 + lane];
        acc.x += v.x; acc.y += v.y;
    }
    float inv = 1.f / (float)max(e - s, 1);
    reinterpret_cast<float2*>(outm)[(size_t)node * 32 + lane] =
        make_float2(acc.x * inv, acc.y * inv);
}

// ---------------- feature GEMM: C[M,64] = relu(A[M,256] @ W[256,64] + b) ----------------
__global__ __launch_bounds__(256) void k_gemm_relu(
    const float* __restrict__ A, const float* __restrict__ W,
    const float* __restrict__ bias, float* __restrict__ C, int M)
{
    __shared__ __align__(16) float AsT[64][68];  // [k][m], padded
    __shared__ __align__(16) float Ws[64][64];   // [k][n]
    int tid = threadIdx.x;
    int r0 = blockIdx.x * 64;
    int tr = tid >> 4, tc = tid & 15;
    float acc[4][4];
    #pragma unroll
    for (int i = 0; i < 4; i++)
        #pragma unroll
        for (int j = 0; j < 4; j++) acc[i][j] = 0.f;

    for (int kc = 0; kc < K_; kc += 64) {
        #pragma unroll
        for (int it = 0; it < 16; it++) {
            int idx = tid + it * 256;
            int lr = idx >> 6, lk = idx & 63;
            int gr = r0 + lr;
            AsT[lk][lr] = (gr < M) ? A[(size_t)gr * K_ + kc + lk] : 0.f;
        }
        #pragma unroll
        for (int it = 0; it < 16; it++) {
            int idx = tid + it * 256;
            int lk = idx >> 6, n = idx & 63;
            Ws[lk][n] = W[(size_t)(kc + lk) * 64 + n];
        }
        __syncthreads();
        #pragma unroll 4
        for (int kk = 0; kk < 64; kk++) {
            float4 a4 = *reinterpret_cast<const float4*>(&AsT[kk][tr * 4]);
            float4 w4 = *reinterpret_cast<const float4*>(&Ws[kk][tc * 4]);
            float av[4] = {a4.x, a4.y, a4.z, a4.w};
            float wv[4] = {w4.x, w4.y, w4.z, w4.w};
            #pragma unroll
            for (int i = 0; i < 4; i++)
                #pragma unroll
                for (int j = 0; j < 4; j++)
                    acc[i][j] = fmaf(av[i], wv[j], acc[i][j]);
        }
        __syncthreads();
    }
    #pragma unroll
    for (int i = 0; i < 4; i++) {
        int row = r0 + tr * 4 + i;
        if (row < M) {
            #pragma unroll
            for (int j = 0; j < 4; j++) {
                int col = tc * 4 + j;
                float v = acc[i][j] + bias[col];
                C[(size_t)row * 64 + col] = v > 0.f ? v : 0.f;
            }
        }
    }
}

// ---------------- per-edge metric cosine similarity mask ----------------
__global__ __launch_bounds__(256) void k_edge_sim(const int* __restrict__ ei,
                                                  const float* __restrict__ mw)
{
    __shared__ float smw[4 * 64];
    if (threadIdx.x < 256) smw[threadIdx.x] = mw[threadIdx.x];
    __syncthreads();
    int t = blockIdx.x * 256 + threadIdx.x;
    float m = 0.f;
    if (t < E_) {
        int e0 = ei[t], e1 = ei[E_ + t];
        const float4* ur = reinterpret_cast<const float4*>(g_u) + (size_t)e0 * 16;
        const float4* fr = reinterpret_cast<const float4*>(g_f) + (size_t)e1 * 16;
        float aa[4] = {0,0,0,0}, bb[4] = {0,0,0,0}, ab[4] = {0,0,0,0};
        #pragma unroll 4
        for (int i4 = 0; i4 < 16; i4++) {
            float4 uv = ur[i4]; float4 fv = fr[i4];
            float us[4] = {uv.x, uv.y, uv.z, uv.w};
            float fs[4] = {fv.x, fv.y, fv.z, fv.w};
            #pragma unroll
            for (int c = 0; c < 4; c++) {
                int i = i4 * 4 + c;
                #pragma unroll
                for (int h = 0; h < 4; h++) {
                    float w  = smw[h * 64 + i];
                    float wa = w * us[c];
                    float wb = w * fs[c];
                    aa[h] = fmaf(wa, wa, aa[h]);
                    bb[h] = fmaf(wb, wb, bb[h]);
                    ab[h] = fmaf(wa, wb, ab[h]);
                }
            }
        }
        float sim = 0.f;
        #pragma unroll
        for (int h = 0; h < 4; h++) {
            float na = fmaxf(sqrtf(aa[h]), 1e-8f);
            float nb = fmaxf(sqrtf(bb[h]), 1e-8f);
            sim += ab[h] / (na * nb);
        }
        sim *= 0.25f;
        m = (sim < 0.3f) ? 0.f : sim;
        g_maskF[t] = m;
    }
    float tot = block_reduce_sum_256(fabsf(m));
    if (threadIdx.x == 0) atomicAdd(&g_sums[0], tot);
}

// ---------------- signed conv layer 1 node transform (agg arrays hold MEANS) ----------------
__global__ __launch_bounds__(128) void k_layer1(
    const float* __restrict__ pl, const float* __restrict__ prw, const float* __restrict__ pb,
    const float* __restrict__ nl, const float* __restrict__ nrw, const float* __restrict__ nb)
{
    __shared__ float sPl[2048], sPr[2048], sNl[2048], sNr[2048];
    __shared__ float sPb[32], sNb[32];
    int tid = threadIdx.x;
    for (int i = tid; i < 2048; i += 128) {
        sPl[i] = pl[i]; sPr[i] = prw[i]; sNl[i] = nl[i]; sNr[i] = nrw[i];
    }
    if (tid < 32) { sPb[tid] = pb[tid]; sNb[tid] = nb[tid]; }
    __syncthreads();
    int n = blockIdx.x * 128 + tid;
    if (n >= NN_) return;
    float accP[32], accN[32];
    #pragma unroll
    for (int j = 0; j < 32; j++) { accP[j] = 0.f; accN[j] = 0.f; }
    const float4* xr = reinterpret_cast<const float4*>(g_x    + (size_t)n * 64);
    const float4* pr = reinterpret_cast<const float4*>(g_aggP + (size_t)n * 64);
    const float4* nr = reinterpret_cast<const float4*>(g_aggN + (size_t)n * 64);
    #pragma unroll 1
    for (int i4 = 0; i4 < 16; i4++) {
        float4 xv4 = xr[i4]; float4 mp4 = pr[i4]; float4 mn4 = nr[i4];
        float xs[4] = {xv4.x, xv4.y, xv4.z, xv4.w};
        float ms[4] = {mp4.x, mp4.y, mp4.z, mp4.w};
        float ns[4] = {mn4.x, mn4.y, mn4.z, mn4.w};
        #pragma unroll
        for (int c = 0; c < 4; c++) {
            int i = i4 * 4 + c;
            float xv = xs[c], mv = ms[c], nv = ns[c];
            const float* wpl = &sPl[i * 32];
            const float* wpr = &sPr[i * 32];
            const float* wnl = &sNl[i * 32];
            const float* wnr = &sNr[i * 32];
            #pragma unroll
            for (int j = 0; j < 32; j++) {
                accP[j] = fmaf(mv, wpl[j], fmaf(xv, wpr[j], accP[j]));
                accN[j] = fmaf(nv, wnl[j], fmaf(xv, wnr[j], accN[j]));
            }
        }
    }
    float* zr = g_z + (size_t)n * 64;
    #pragma unroll
    for (int j = 0; j < 32; j++) {
        float v = accP[j] + sPb[j]; zr[j]      = v > 0.f ? v : 0.f;
        v = accN[j] + sNb[j];       zr[32 + j] = v > 0.f ? v : 0.f;
    }
}

// ---------------- signed conv layers 2/3 node transform (agg arrays hold MEANS) ----------------
__global__ __launch_bounds__(128) void k_layer23(
    const float* __restrict__ pl, const float* __restrict__ prw, const float* __restrict__ pb,
    const float* __restrict__ nl, const float* __restrict__ nrw, const float* __restrict__ nb,
    const float* __restrict__ zin, float* __restrict__ zout)
{
    __shared__ float sPl[2048], sNl[2048], sPr[1024], sNr[1024];
    __shared__ float sPb[32], sNb[32];
    int tid = threadIdx.x;
    for (int i = tid; i < 2048; i += 128) { sPl[i] = pl[i]; sNl[i] = nl[i]; }
    for (int i = tid; i < 1024; i += 128) { sPr[i] = prw[i]; sNr[i] = nrw[i]; }
    if (tid < 32) { sPb[tid] = pb[tid]; sNb[tid] = nb[tid]; }
    __syncthreads();
    int n = blockIdx.x * 128 + tid;
    if (n >= NN_) return;
    float accP[32], accN[32];
    #pragma unroll
    for (int j = 0; j < 32; j++) { accP[j] = 0.f; accN[j] = 0.f; }
    const float4* z4 = reinterpret_cast<const float4*>(zin    + (size_t)n * 64);
    const float4* aP = reinterpret_cast<const float4*>(g_aggP + (size_t)n * 64);
    const float4* aN = reinterpret_cast<const float4*>(g_aggN + (size_t)n * 64);
    #pragma unroll 1
    for (int i4 = 0; i4 < 8; i4++) {
        float4 zp4 = z4[i4], zn4 = z4[8 + i4];
        float4 aPlo4 = aP[i4], aPhi4 = aP[8 + i4];
        float4 aNlo4 = aN[i4], aNhi4 = aN[8 + i4];
        float zps[4] = {zp4.x, zp4.y, zp4.z, zp4.w};
        float zns[4] = {zn4.x, zn4.y, zn4.z, zn4.w};
        float aplo[4] = {aPlo4.x, aPlo4.y, aPlo4.z, aPlo4.w};  // mean_pos(xp)
        float anlo[4] = {aPhi4.x, aPhi4.y, aPhi4.z, aPhi4.w};  // mean_pos(xn)
        float aphi[4] = {aNhi4.x, aNhi4.y, aNhi4.z, aNhi4.w};  // mean_neg(xn)
        float anhi[4] = {aNlo4.x, aNlo4.y, aNlo4.z, aNlo4.w};  // mean_neg(xp)
        #pragma unroll
        for (int c = 0; c < 4; c++) {
            int i = i4 * 4 + c;
            const float* wPlo = &sPl[i * 32];
            const float* wPhi = &sPl[(i + 32) * 32];
            const float* wNlo = &sNl[i * 32];
            const float* wNhi = &sNl[(i + 32) * 32];
            const float* wPr  = &sPr[i * 32];
            const float* wNr  = &sNr[i * 32];
            float apl = aplo[c], aph = aphi[c], anl_ = anlo[c], anh = anhi[c];
            float xpv = zps[c], xnv = zns[c];
            #pragma unroll
            for (int j = 0; j < 32; j++) {
                accP[j] = fmaf(apl, wPlo[j], fmaf(aph, wPhi[j], fmaf(xpv, wPr[j], accP[j])));
                accN[j] = fmaf(anl_, wNlo[j], fmaf(anh, wNhi[j], fmaf(xnv, wNr[j], accN[j])));
            }
        }
    }
    float* zr = zout + (size_t)n * 64;
    #pragma unroll
    for (int j = 0; j < 32; j++) {
        float v = accP[j] + sPb[j]; zr[j]      = v > 0.f ? v : 0.f;
        v = accN[j] + sNb[j];       zr[32 + j] = v > 0.f ? v : 0.f;
    }
}

// ---------------- per-edge classifier -> semantic mask ----------------
__global__ __launch_bounds__(256) void k_val(const int* __restrict__ ei,
                                             const float* __restrict__ lw,
                                             const float* __restrict__ lb)
{
    __shared__ float slw[384];
    for (int i = threadIdx.x; i < 384; i += 256) slw[i] = lw[i];
    __syncthreads();
    int t = blockIdx.x * 256 + threadIdx.x;
    float m = 0.f;
    if (t < E_) {
        int e0 = ei[t], e1 = ei[E_ + t];
        float l0 = lb[0], l1 = lb[1], l2 = lb[2];
        const float4* za = reinterpret_cast<const float4*>(g_z + (size_t)e0 * 64);
        const float4* zb = reinterpret_cast<const float4*>(g_z + (size_t)e1 * 64);
        #pragma unroll 4
        for (int i4 = 0; i4 < 16; i4++) {
            float4 a4 = za[i4]; float4 b4 = zb[i4];
            float as[4] = {a4.x, a4.y, a4.z, a4.w};
            float bs[4] = {b4.x, b4.y, b4.z, b4.w};
            #pragma unroll
            for (int c = 0; c < 4; c++) {
                int i = i4 * 4 + c;
                l0 = fmaf(as[c], slw[i * 3 + 0], fmaf(bs[c], slw[(64 + i) * 3 + 0], l0));
                l1 = fmaf(as[c], slw[i * 3 + 1], fmaf(bs[c], slw[(64 + i) * 3 + 1], l1));
                l2 = fmaf(as[c], slw[i * 3 + 2], fmaf(bs[c], slw[(64 + i) * 3 + 2], l2));
            }
        }
        int cls = 0; float best = l0;
        if (l1 > best) { best = l1; cls = 1; }
        if (l2 > best) { cls = 2; }
        m = (float)(cls - 1);
        g_maskS[t] = m;
    }
    float tot = block_reduce_sum_256(fabsf(m));
    if (threadIdx.x == 0) atomicAdd(&g_sums[1], tot);
}

// ---------------- mask fusion -> binary edge weight + degree ----------------
__global__ void k_fuse(const int* __restrict__ ei, const float* __restrict__ fw) {
    int t = blockIdx.x * blockDim.x + threadIdx.x;
    if (t >= E_) return;
    float w0 = fw[0], w1 = fw[1], w2 = fw[2];
    float mx = fmaxf(w0, fmaxf(w1, w2));
    float x0 = expf(w0 - mx), x1 = expf(w1 - mx), x2 = expf(w2 - mx);
    float si = 1.f / (x0 + x1 + x2);
    float Sf = fmaxf(g_sums[0], 1e-12f);
    float Ss = fmaxf(g_sums[1], 1e-12f);
    float fused = x0 * si * (1.0f / (float)E_)
                + x1 * si * g_maskF[t] / Sf
                + x2 * si * g_maskS[t] / Ss;
    float w = (fused > 0.5f) ? 1.f : 0.f;
    g_w[t] = w;
    if (w != 0.f) atomicAdd(&g_deg[ei[t]], w);
}

__global__ void k_normc(const int* __restrict__ ei) {
    int t = blockIdx.x * blockDim.x + threadIdx.x;
    if (t >= E_) return;
    float w = g_w[t];
    if (w == 0.f) { g_norm[t] = 0.f; return; }
    int a = ei[t], b = ei[E_ + t];
    float d0 = g_deg[a], d1 = g_deg[b];
    float dis0 = d0 > 0.f ? rsqrtf(fmaxf(d0, 1e-12f)) : 0.f;
    float dis1 = d1 > 0.f ? rsqrtf(fmaxf(d1, 1e-12f)) : 0.f;
    g_norm[t] = dis0 * w * dis1;
}

// ---------------- LightGCN propagation hop (skips zero-weight edges) ----------------
__global__ __launch_bounds__(256) void k_prop(const int* __restrict__ ei,
                                              const float* __restrict__ xin,
                                              float* __restrict__ xout)
{
    int e = blockIdx.x * 256 + threadIdx.x;
    if (e >= E_) return;
    float nv = g_norm[e];
    if (nv == 0.f) return;
    int d = ei[e], s = ei[E_ + e];
    const float4* xs = reinterpret_cast<const float4*>(xin + (size_t)s * 64);
    float* ob = xout + (size_t)d * 64;
    #pragma unroll
    for (int c = 0; c < 16; c++) {
        float4 v = xs[c];
        atomicAdd(ob + c * 4 + 0, nv * v.x);
        atomicAdd(ob + c * 4 + 1, nv * v.y);
        atomicAdd(ob + c * 4 + 2, nv * v.z);
        atomicAdd(ob + c * 4 + 3, nv * v.w);
    }
}

// ---------------- final output assembly ----------------
__global__ void k_output(float* __restrict__ out,
                         const float* __restrict__ lgu, const float* __restrict__ lgi)
{
    int t = blockIdx.x * blockDim.x + threadIdx.x;
    if (t >= NND_) return;
    if (t < NUD_) {
        out[t]         = g_acc[t] * 0.25f;
        out[NUD_ + t]  = lgu[t];
    } else {
        int j = t - NUD_;
        out[2 * NUD_ + j]        = g_acc[t] * 0.25f;
        out[2 * NUD_ + NFD_ + j] = lgi[j];
    }
}

// ---------------- host orchestration ----------------
extern "C" void kernel_launch(void* const* d_in, const int* in_sizes, int n_in,
                              void* d_out, int out_size)
{
    (void)in_sizes; (void)n_in; (void)out_size;
    const float* user_feat = (const float*)d_in[0];
    const float* food_feat = (const float*)d_in[1];
    const int*   edge      = (const int*)d_in[2];
    const int*   pedge     = (const int*)d_in[3];
    const int*   nedge     = (const int*)d_in[4];
    const float* W_user    = (const float*)d_in[5];
    const float* b_user    = (const float*)d_in[6];
    const float* W_food    = (const float*)d_in[7];
    const float* b_food    = (const float*)d_in[8];
    const float* metric    = (const float*)d_in[9];
    const float* fusion    = (const float*)d_in[10];
    const float* sg_u      = (const float*)d_in[11];
    const float* sg_i      = (const float*)d_in[12];
    const float* c1pl      = (const float*)d_in[13];
    const float* c1pr      = (const float*)d_in[14];
    const float* c1pb      = (const float*)d_in[15];
    const float* c1nl      = (const float*)d_in[16];
    const float* c1nr      = (const float*)d_in[17];
    const float* c1nb      = (const float*)d_in[18];
    const float* cspl      = (const float*)d_in[19];
    const float* cspr      = (const float*)d_in[20];
    const float* cspb      = (const float*)d_in[21];
    const float* csnl      = (const float*)d_in[22];
    const float* csnr      = (const float*)d_in[23];
    const float* csnb      = (const float*)d_in[24];
    const float* linw      = (const float*)d_in[25];
    const float* linb      = (const float*)d_in[26];
    const float* lg_u      = (const float*)d_in[27];
    const float* lg_i      = (const float*)d_in[28];
    float* out = (float*)d_out;

    float *pu, *pf, *px, *pz, *pz2, *paggP, *paggN, *pacc, *pxkA, *pxkB, *psums, *pdeg;
    int *pcntp, *pcntn, *poffP, *poffN, *pcur, *padjP, *padjN, *pbsum;
    cudaGetSymbolAddress((void**)&pu,    g_u);
    cudaGetSymbolAddress((void**)&pf,    g_f);
    cudaGetSymbolAddress((void**)&px,    g_x);
    cudaGetSymbolAddress((void**)&pz,    g_z);
    cudaGetSymbolAddress((void**)&pz2,   g_z2);
    cudaGetSymbolAddress((void**)&paggP, g_aggP);
    cudaGetSymbolAddress((void**)&paggN, g_aggN);
    cudaGetSymbolAddress((void**)&pacc,  g_acc);
    cudaGetSymbolAddress((void**)&pxkA,  g_xkA);
    cudaGetSymbolAddress((void**)&pxkB,  g_xkB);
    cudaGetSymbolAddress((void**)&psums, g_sums);
    cudaGetSymbolAddress((void**)&pdeg,  g_deg);
    cudaGetSymbolAddress((void**)&pcntp, g_cntp);
    cudaGetSymbolAddress((void**)&pcntn, g_cntn);
    cudaGetSymbolAddress((void**)&poffP, g_offP);
    cudaGetSymbolAddress((void**)&poffN, g_offN);
    cudaGetSymbolAddress((void**)&pcur,  g_cur);
    cudaGetSymbolAddress((void**)&padjP, g_adjP);
    cudaGetSymbolAddress((void**)&padjN, g_adjN);
    cudaGetSymbolAddress((void**)&pbsum, g_bsum);

    const int ZB = 256;
    const int SB = cdiv(NN_, 1024);   // 98 scan blocks

    // zero accumulators
    k_zero<<<1, 32>>>((float4*)psums, 1);
    k_zero<<<cdiv(NN_ / 4, ZB), ZB>>>((float4*)pcntp, NN_ / 4);
    k_zero<<<cdiv(NN_ / 4, ZB), ZB>>>((float4*)pcntn, NN_ / 4);
    k_zero<<<cdiv(NN_ / 4, ZB), ZB>>>((float4*)pdeg,  NN_ / 4);

    // feature GEMMs + feature-similarity mask
    k_gemm_relu<<<cdiv(NU_, 64), 256>>>(user_feat, W_user, b_user, pu, NU_);
    k_gemm_relu<<<cdiv(NF_, 64), 256>>>(food_feat, W_food, b_food, pf, NF_);
    k_edge_sim<<<cdiv(E_, 256), 256>>>(edge, metric);

    // x = concat(sg_users, sg_items)
    k_copy<<<cdiv(NUD_ / 4, ZB), ZB>>>((float4*)px, (const float4*)sg_u, NUD_ / 4);
    k_copy<<<cdiv(NFD_ / 4, ZB), ZB>>>((float4*)(px + NUD_), (const float4*)sg_i, NFD_ / 4);

    // ---- CSR build: pos ----
    k_count<<<cdiv(EP_, 256), 256>>>(pedge + EP_, EP_, pcntp);
    k_scan1<<<SB, 1024>>>(pcntp, poffP, pbsum, NN_);
    k_scan2<<<1, 128>>>(pbsum, SB);
    k_scan3<<<SB, 1024>>>(poffP, pbsum, NN_);
    k_settail<<<1, 32>>>(poffP, EP_);
    k_copy<<<cdiv(NN_ / 4, ZB), ZB>>>((float4*)pcur, (const float4*)poffP, NN_ / 4);
    k_fill<<<cdiv(EP_, 256), 256>>>(pedge, pedge + EP_, EP_, pcur, padjP);

    // ---- CSR build: neg ----
    k_count<<<cdiv(EN_, 256), 256>>>(nedge + EN_, EN_, pcntn);
    k_scan1<<<SB, 1024>>>(pcntn, poffN, pbsum, NN_);
    k_scan2<<<1, 128>>>(pbsum, SB);
    k_scan3<<<SB, 1024>>>(poffN, pbsum, NN_);
    k_settail<<<1, 32>>>(poffN, EN_);
    k_copy<<<cdiv(NN_ / 4, ZB), ZB>>>((float4*)pcur, (const float4*)poffN, NN_ / 4);
    k_fill<<<cdiv(EN_, 256), 256>>>(nedge, nedge + EN_, EN_, pcur, padjN);

    const int GG = cdiv(NN_ * 32, 256);  // gather grid (warp per node)

    // layer 1
    k_gather<<<GG, 256>>>(poffP, padjP, px, paggP);
    k_gather<<<GG, 256>>>(poffN, padjN, px, paggN);
    k_layer1<<<cdiv(NN_, 128), 128>>>(c1pl, c1pr, c1pb, c1nl, c1nr, c1nb);

    // layer 2
    k_gather<<<GG, 256>>>(poffP, padjP, pz, paggP);
    k_gather<<<GG, 256>>>(poffN, padjN, pz, paggN);
    k_layer23<<<cdiv(NN_, 128), 128>>>(cspl, cspr, cspb, csnl, csnr, csnb, pz, pz2);

    // layer 3
    k_gather<<<GG, 256>>>(poffP, padjP, pz2, paggP);
    k_gather<<<GG, 256>>>(poffN, padjN, pz2, paggN);
    k_layer23<<<cdiv(NN_, 128), 128>>>(cspl + 2048, cspr + 1024, cspb + 32,
                                       csnl + 2048, csnr + 1024, csnb + 32, pz2, pz);

    // semantic mask + fusion + edge weights
    k_val<<<cdiv(E_, 256), 256>>>(edge, linw, linb);
    k_fuse<<<cdiv(E_, 256), 256>>>(edge, fusion);
    k_normc<<<cdiv(E_, 256), 256>>>(edge);

    // LightGCN propagation: acc = emb; 3 hops
    k_copy<<<cdiv(NUD_ / 4, ZB), ZB>>>((float4*)pacc, (const float4*)lg_u, NUD_ / 4);
    k_copy<<<cdiv(NFD_ / 4, ZB), ZB>>>((float4*)(pacc + NUD_), (const float4*)lg_i, NFD_ / 4);
    k_copy<<<cdiv(NUD_ / 4, ZB), ZB>>>((float4*)pxkA, (const float4*)lg_u, NUD_ / 4);
    k_copy<<<cdiv(NFD_ / 4, ZB), ZB>>>((float4*)(pxkA + NUD_), (const float4*)lg_i, NFD_ / 4);

    k_zero<<<cdiv(NND_ / 4, ZB), ZB>>>((float4*)pxkB, NND_ / 4);
    k_prop<<<cdiv(E_, 256), 256>>>(edge, pxkA, pxkB);
    k_addacc<<<cdiv(NND_ / 4, ZB), ZB>>>((float4*)pacc, (const float4*)pxkB, NND_ / 4);

    k_zero<<<cdiv(NND_ / 4, ZB), ZB>>>((float4*)pxkA, NND_ / 4);
    k_prop<<<cdiv(E_, 256), 256>>>(edge, pxkB, pxkA);
    k_addacc<<<cdiv(NND_ / 4, ZB), ZB>>>((float4*)pacc, (const float4*)pxkA, NND_ / 4);

    k_zero<<<cdiv(NND_ / 4, ZB), ZB>>>((float4*)pxkB, NND_ / 4);
    k_prop<<<cdiv(E_, 256), 256>>>(edge, pxkA, pxkB);
    k_addacc<<<cdiv(NND_ / 4, ZB), ZB>>>((float4*)pacc, (const float4*)pxkB, NND_ / 4);

    // write output: [final_users, lg_users, final_items, lg_items]
    k_output<<<cdiv(NND_, 256), 256>>>(out, lg_u, lg_i);
}

// round 5
// speedup vs baseline: 1.9468x; 1.0199x over previous
#include <cuda_runtime.h>
#include <cstdint>

#define NU_ 50000
#define NF_ 50000
#define NN_ 100000
#define D_ 64
#define H2_ 32
#define K_ 256
#define E_ 500000
#define EP_ 500000
#define EN_ 500000
#define NND_ (NN_*D_)
#define NUD_ (NU_*D_)
#define NFD_ (NF_*D_)

typedef unsigned long long u64;

// ---------------- f32x2 packed-math helpers ----------------
__device__ __forceinline__ u64 pk2(float lo, float hi) {
    u64 r; asm("mov.b64 %0, {%1,%2};" : "=l"(r) : "f"(lo), "f"(hi)); return r;
}
__device__ __forceinline__ u64 dup2(float v) {
    u64 r; asm("mov.b64 %0, {%1,%1};" : "=l"(r) : "f"(v)); return r;
}
__device__ __forceinline__ void up2(u64 v, float& lo, float& hi) {
    asm("mov.b64 {%0,%1}, %2;" : "=f"(lo), "=f"(hi) : "l"(v));
}
__device__ __forceinline__ u64 fma2(u64 a, u64 b, u64 c) {
    u64 d; asm("fma.rn.f32x2 %0, %1, %2, %3;" : "=l"(d) : "l"(a), "l"(b), "l"(c)); return d;
}
__device__ __forceinline__ u64 mul2(u64 a, u64 b) {
    u64 d; asm("mul.rn.f32x2 %0, %1, %2;" : "=l"(d) : "l"(a), "l"(b)); return d;
}

// ---------------- scratch (static device globals; no allocation) ----------------
__device__ float g_u[NUD_];
__device__ float g_f[NFD_];
__device__ float g_x[NND_];
__device__ float g_z[NND_];
__device__ float g_z2[NND_];
__device__ float g_aggP[NND_];
__device__ float g_aggN[NND_];
__device__ int   g_cntp[NN_];
__device__ int   g_cntn[NN_];
__device__ int   g_offP[NN_ + 1];
__device__ int   g_offN[NN_ + 1];
__device__ int   g_curP[NN_];
__device__ int   g_curN[NN_];
__device__ int   g_adjP[EP_];
__device__ int   g_adjN[EN_];
__device__ int   g_bsum[256];     // [2][128]
__device__ float g_maskF[E_];
__device__ float g_maskS[E_];
__device__ float g_w[E_];
__device__ float g_norm[E_];
__device__ float g_deg[NN_];
__device__ float g_acc[NND_];
__device__ float g_xkA[NND_];
__device__ float g_xkB[NND_];
__device__ float g_sums[4];       // [0]=sum|mask_feature|  [1]=sum|mask_semantic|

static inline int cdiv(int a, int b) { return (a + b - 1) / b; }

// ---------------- fused init: zero counters/deg/sums, set CSR tails ----------------
__global__ void k_init() {
    int t = blockIdx.x * blockDim.x + threadIdx.x;
    if (t < NN_) { g_cntp[t] = 0; g_cntn[t] = 0; g_deg[t] = 0.f; }
    if (t == 0) {
        g_sums[0] = 0.f; g_sums[1] = 0.f; g_sums[2] = 0.f; g_sums[3] = 0.f;
        g_offP[NN_] = EP_; g_offN[NN_] = EN_;
    }
}

// ---------------- x = concat(sg_users, sg_items) ----------------
__global__ void k_copyx(const float4* __restrict__ su, const float4* __restrict__ si) {
    int i = blockIdx.x * blockDim.x + threadIdx.x;
    if (i >= NND_ / 4) return;
    reinterpret_cast<float4*>(g_x)[i] = (i < NUD_ / 4) ? su[i] : si[i - NUD_ / 4];
}

// acc = emb, xkA = emb, xkB = 0
__global__ void k_copyemb(const float4* __restrict__ lu, const float4* __restrict__ li) {
    int i = blockIdx.x * blockDim.x + threadIdx.x;
    if (i >= NND_ / 4) return;
    float4 v = (i < NUD_ / 4) ? lu[i] : li[i - NUD_ / 4];
    reinterpret_cast<float4*>(g_acc)[i] = v;
    reinterpret_cast<float4*>(g_xkA)[i] = v;
    reinterpret_cast<float4*>(g_xkB)[i] = make_float4(0.f, 0.f, 0.f, 0.f);
}

// acc += xk ; zbuf = 0
__global__ void k_accz(const float4* __restrict__ xk, float4* __restrict__ zbuf) {
    int i = blockIdx.x * blockDim.x + threadIdx.x;
    if (i >= NND_ / 4) return;
    float4 a = reinterpret_cast<float4*>(g_acc)[i];
    float4 b = xk[i];
    a.x += b.x; a.y += b.y; a.z += b.z; a.w += b.w;
    reinterpret_cast<float4*>(g_acc)[i] = a;
    zbuf[i] = make_float4(0.f, 0.f, 0.f, 0.f);
}

__device__ __forceinline__ float block_reduce_sum_256(float v) {
    __shared__ float sh[8];
    int lane = threadIdx.x & 31, w = threadIdx.x >> 5;
    #pragma unroll
    for (int o = 16; o > 0; o >>= 1) v += __shfl_down_sync(0xffffffffu, v, o);
    if (lane == 0) sh[w] = v;
    __syncthreads();
    if (w == 0) {
        v = (lane < 8) ? sh[lane] : 0.f;
        #pragma unroll
        for (int o = 4; o > 0; o >>= 1) v += __shfl_down_sync(0xffffffffu, v, o);
    }
    return v;
}

// ---------------- CSR build: count(both) -> scan(dual) -> fill(both) ----------------
__global__ void k_countboth(const int* __restrict__ pe, const int* __restrict__ ne) {
    int t = blockIdx.x * blockDim.x + threadIdx.x;
    if (t < EP_) atomicAdd(&g_cntp[pe[EP_ + t]], 1);
    else if (t < EP_ + EN_) atomicAdd(&g_cntn[ne[EN_ + (t - EP_)]], 1);
}

__device__ __forceinline__ int warp_scan_incl(int v, int lane) {
    #pragma unroll
    for (int o = 1; o < 32; o <<= 1) {
        int u = __shfl_up_sync(0xffffffffu, v, o);
        if (lane >= o) v += u;
    }
    return v;
}

__global__ __launch_bounds__(1024) void k_scan1() {
    __shared__ int wsum[32];
    int y = blockIdx.y;
    const int* cnt = y ? g_cntn : g_cntp;
    int* out = y ? g_offN : g_offP;
    int t = threadIdx.x, lane = t & 31, w = t >> 5;
    int i = blockIdx.x * 1024 + t;
    int v = (i < NN_) ? cnt[i] : 0;
    int s = warp_scan_incl(v, lane);
    if (lane == 31) wsum[w] = s;
    __syncthreads();
    if (w == 0) {
        int x = wsum[lane];
        x = warp_scan_incl(x, lane);
        wsum[lane] = x;
    }
    __syncthreads();
    int base = (w > 0) ? wsum[w - 1] : 0;
    if (i < NN_) out[i] = base + s - v;
    if (t == 1023) g_bsum[y * 128 + blockIdx.x] = base + s;
}

__global__ __launch_bounds__(128) void k_scan2(int nb) {
    __shared__ int wsum[4];
    int* bsum = g_bsum + blockIdx.x * 128;
    int t = threadIdx.x, lane = t & 31, w = t >> 5;
    int v = (t < nb) ? bsum[t] : 0;
    int s = warp_scan_incl(v, lane);
    if (lane == 31) wsum[w] = s;
    __syncthreads();
    int add = 0;
    #pragma unroll
    for (int k = 0; k < 4; k++) if (k < w) add += wsum[k];
    if (t < nb) bsum[t] = add + s - v;
}

__global__ __launch_bounds__(1024) void k_scan3() {
    int y = blockIdx.y;
    int* out = y ? g_offN : g_offP;
    int i = blockIdx.x * 1024 + threadIdx.x;
    if (i < NN_) out[i] += g_bsum[y * 128 + blockIdx.x];
}

__global__ void k_copycur() {
    int i = blockIdx.x * blockDim.x + threadIdx.x;
    if (i < NN_ / 4) {
        reinterpret_cast<int4*>(g_curP)[i] = reinterpret_cast<const int4*>(g_offP)[i];
        reinterpret_cast<int4*>(g_curN)[i] = reinterpret_cast<const int4*>(g_offN)[i];
    }
}

__global__ void k_fillboth(const int* __restrict__ pe, const int* __restrict__ ne) {
    int t = blockIdx.x * blockDim.x + threadIdx.x;
    if (t < EP_) {
        int d = pe[EP_ + t];
        int slot = atomicAdd(&g_curP[d], 1);
        g_adjP[slot] = pe[t];
    } else if (t < EP_ + EN_) {
        int u = t - EP_;
        int d = ne[EN_ + u];
        int slot = atomicAdd(&g_curN[d], 1);
        g_adjN[slot] = ne[u];
    }
}

// ---------------- dual warp-per-node segment MEAN gather ----------------
__global__ __launch_bounds__(256) void k_gather2(const float* __restrict__ feat) {
    int y = blockIdx.y;
    const int* off = y ? g_offN : g_offP;
    const int* adj = y ? g_adjN : g_adjP;
    float* outm = y ? g_aggN : g_aggP;
    int g = blockIdx.x * 256 + threadIdx.x;
    int node = g >> 5, lane = g & 31;
    if (node >= NN_) return;
    int s = off[node], e = off[node + 1];
    float2 acc = make_float2(0.f, 0.f);
    const float2* base = reinterpret_cast<const float2*>(feat);
    for (int k = s; k < e; k++) {
        int sr = adj[k];
        float2 v = base[(size_t)sr * 32 + lane];
        acc.x += v.x; acc.y += v.y;
    }
    float inv = 1.f / (float)max(e - s, 1);
    reinterpret_cast<float2*>(outm)[(size_t)node * 32 + lane] =
        make_float2(acc.x * inv, acc.y * inv);
}

// ---------------- feature GEMM: C[M,64] = relu(A[M,256] @ W[256,64] + b), f32x2 ----------------
__global__ __launch_bounds__(256) void k_gemm_relu(
    const float* __restrict__ A, const float* __restrict__ W,
    const float* __restrict__ bias, float* __restrict__ C, int M)
{
    __shared__ __align__(16) float AsT[64][68];  // [k][m], padded
    __shared__ __align__(16) float Ws[64][64];   // [k][n]
    int tid = threadIdx.x;
    int r0 = blockIdx.x * 64;
    int tr = tid >> 4, tc = tid & 15;
    u64 acc2[4][2];
    #pragma unroll
    for (int i = 0; i < 4; i++) { acc2[i][0] = 0ull; acc2[i][1] = 0ull; }

    for (int kc = 0; kc < K_; kc += 64) {
        #pragma unroll
        for (int it = 0; it < 16; it++) {
            int idx = tid + it * 256;
            int lr = idx >> 6, lk = idx & 63;
            int gr = r0 + lr;
            AsT[lk][lr] = (gr < M) ? A[(size_t)gr * K_ + kc + lk] : 0.f;
        }
        #pragma unroll
        for (int it = 0; it < 16; it++) {
            int idx = tid + it * 256;
            int lk = idx >> 6, n = idx & 63;
            Ws[lk][n] = W[(size_t)(kc + lk) * 64 + n];
        }
        __syncthreads();
        #pragma unroll 4
        for (int kk = 0; kk < 64; kk++) {
            float4 a4 = *reinterpret_cast<const float4*>(&AsT[kk][tr * 4]);
            const u64* w2 = reinterpret_cast<const u64*>(&Ws[kk][tc * 4]);
            u64 wlo = w2[0], whi = w2[1];
            u64 a0 = dup2(a4.x), a1 = dup2(a4.y), a2 = dup2(a4.z), a3 = dup2(a4.w);
            acc2[0][0] = fma2(a0, wlo, acc2[0][0]); acc2[0][1] = fma2(a0, whi, acc2[0][1]);
            acc2[1][0] = fma2(a1, wlo, acc2[1][0]); acc2[1][1] = fma2(a1, whi, acc2[1][1]);
            acc2[2][0] = fma2(a2, wlo, acc2[2][0]); acc2[2][1] = fma2(a2, whi, acc2[2][1]);
            acc2[3][0] = fma2(a3, wlo, acc2[3][0]); acc2[3][1] = fma2(a3, whi, acc2[3][1]);
        }
        __syncthreads();
    }
    #pragma unroll
    for (int i = 0; i < 4; i++) {
        int row = r0 + tr * 4 + i;
        if (row < M) {
            float v0, v1, v2, v3;
            up2(acc2[i][0], v0, v1);
            up2(acc2[i][1], v2, v3);
            int col = tc * 4;
            v0 += bias[col + 0]; v1 += bias[col + 1];
            v2 += bias[col + 2]; v3 += bias[col + 3];
            float4 o = make_float4(v0 > 0.f ? v0 : 0.f, v1 > 0.f ? v1 : 0.f,
                                   v2 > 0.f ? v2 : 0.f, v3 > 0.f ? v3 : 0.f);
            *reinterpret_cast<float4*>(&C[(size_t)row * 64 + col]) = o;
        }
    }
}

// ---------------- per-edge metric cosine similarity mask (f32x2, h-pairs) ----------------
__global__ __launch_bounds__(256) void k_edge_sim(const int* __restrict__ ei,
                                                  const float* __restrict__ mw)
{
    __shared__ __align__(8) float smw2[256];  // [i][h] transposed
    if (threadIdx.x < 256) {
        int i = threadIdx.x >> 2, h = threadIdx.x & 3;
        smw2[threadIdx.x] = mw[h * 64 + i];
    }
    __syncthreads();
    int t = blockIdx.x * 256 + threadIdx.x;
    float m = 0.f;
    if (t < E_) {
        int e0 = ei[t], e1 = ei[E_ + t];
        const float4* ur = reinterpret_cast<const float4*>(g_u) + (size_t)e0 * 16;
        const float4* fr = reinterpret_cast<const float4*>(g_f) + (size_t)e1 * 16;
        u64 aa01 = 0ull, aa23 = 0ull, bb01 = 0ull, bb23 = 0ull, ab01 = 0ull, ab23 = 0ull;
        const u64* w2 = reinterpret_cast<const u64*>(smw2);
        #pragma unroll 4
        for (int i4 = 0; i4 < 16; i4++) {
            float4 uv = ur[i4]; float4 fv = fr[i4];
            float us[4] = {uv.x, uv.y, uv.z, uv.w};
            float fs[4] = {fv.x, fv.y, fv.z, fv.w};
            #pragma unroll
            for (int c = 0; c < 4; c++) {
                int i = i4 * 4 + c;
                u64 w01 = w2[i * 2], w23 = w2[i * 2 + 1];
                u64 u2v = dup2(us[c]), f2v = dup2(fs[c]);
                u64 wa01 = mul2(w01, u2v), wa23 = mul2(w23, u2v);
                u64 wb01 = mul2(w01, f2v), wb23 = mul2(w23, f2v);
                aa01 = fma2(wa01, wa01, aa01); aa23 = fma2(wa23, wa23, aa23);
                bb01 = fma2(wb01, wb01, bb01); bb23 = fma2(wb23, wb23, bb23);
                ab01 = fma2(wa01, wb01, ab01); ab23 = fma2(wa23, wb23, ab23);
            }
        }
        float aa[4], bb[4], ab[4];
        up2(aa01, aa[0], aa[1]); up2(aa23, aa[2], aa[3]);
        up2(bb01, bb[0], bb[1]); up2(bb23, bb[2], bb[3]);
        up2(ab01, ab[0], ab[1]); up2(ab23, ab[2], ab[3]);
        float sim = 0.f;
        #pragma unroll
        for (int h = 0; h < 4; h++) {
            float na = fmaxf(sqrtf(aa[h]), 1e-8f);
            float nb = fmaxf(sqrtf(bb[h]), 1e-8f);
            sim += ab[h] / (na * nb);
        }
        sim *= 0.25f;
        m = (sim < 0.3f) ? 0.f : sim;
        g_maskF[t] = m;
    }
    float tot = block_reduce_sum_256(fabsf(m));
    if (threadIdx.x == 0) atomicAdd(&g_sums[0], tot);
}

// ---------------- signed conv layer 1 node transform (f32x2) ----------------
__global__ __launch_bounds__(128) void k_layer1(
    const float* __restrict__ pl, const float* __restrict__ prw, const float* __restrict__ pb,
    const float* __restrict__ nl, const float* __restrict__ nrw, const float* __restrict__ nb)
{
    __shared__ __align__(8) float sPl[2048], sPr[2048], sNl[2048], sNr[2048];
    __shared__ float sPb[32], sNb[32];
    int tid = threadIdx.x;
    for (int i = tid; i < 2048; i += 128) {
        sPl[i] = pl[i]; sPr[i] = prw[i]; sNl[i] = nl[i]; sNr[i] = nrw[i];
    }
    if (tid < 32) { sPb[tid] = pb[tid]; sNb[tid] = nb[tid]; }
    __syncthreads();
    int n = blockIdx.x * 128 + tid;
    if (n >= NN_) return;
    u64 accP[16], accN[16];
    #pragma unroll
    for (int j = 0; j < 16; j++) { accP[j] = 0ull; accN[j] = 0ull; }
    const float4* xr = reinterpret_cast<const float4*>(g_x    + (size_t)n * 64);
    const float4* pr = reinterpret_cast<const float4*>(g_aggP + (size_t)n * 64);
    const float4* nr = reinterpret_cast<const float4*>(g_aggN + (size_t)n * 64);
    #pragma unroll 1
    for (int i4 = 0; i4 < 16; i4++) {
        float4 xv4 = xr[i4]; float4 mp4 = pr[i4]; float4 mn4 = nr[i4];
        float xs[4] = {xv4.x, xv4.y, xv4.z, xv4.w};
        float ms[4] = {mp4.x, mp4.y, mp4.z, mp4.w};
        float ns[4] = {mn4.x, mn4.y, mn4.z, mn4.w};
        #pragma unroll
        for (int c = 0; c < 4; c++) {
            int i = i4 * 4 + c;
            u64 xv2 = dup2(xs[c]), mv2 = dup2(ms[c]), nv2 = dup2(ns[c]);
            const u64* wpl = reinterpret_cast<const u64*>(&sPl[i * 32]);
            const u64* wpr = reinterpret_cast<const u64*>(&sPr[i * 32]);
            const u64* wnl = reinterpret_cast<const u64*>(&sNl[i * 32]);
            const u64* wnr = reinterpret_cast<const u64*>(&sNr[i * 32]);
            #pragma unroll
            for (int j = 0; j < 16; j++) {
                accP[j] = fma2(mv2, wpl[j], fma2(xv2, wpr[j], accP[j]));
                accN[j] = fma2(nv2, wnl[j], fma2(xv2, wnr[j], accN[j]));
            }
        }
    }
    float* zr = g_z + (size_t)n * 64;
    #pragma unroll
    for (int j = 0; j < 16; j++) {
        float p0, p1, n0, n1;
        up2(accP[j], p0, p1); up2(accN[j], n0, n1);
        p0 += sPb[2 * j]; p1 += sPb[2 * j + 1];
        n0 += sNb[2 * j]; n1 += sNb[2 * j + 1];
        zr[2 * j]          = p0 > 0.f ? p0 : 0.f;
        zr[2 * j + 1]      = p1 > 0.f ? p1 : 0.f;
        zr[32 + 2 * j]     = n0 > 0.f ? n0 : 0.f;
        zr[32 + 2 * j + 1] = n1 > 0.f ? n1 : 0.f;
    }
}

// ---------------- signed conv layers 2/3 node transform (f32x2) ----------------
__global__ __launch_bounds__(128) void k_layer23(
    const float* __restrict__ pl, const float* __restrict__ prw, const float* __restrict__ pb,
    const float* __restrict__ nl, const float* __restrict__ nrw, const float* __restrict__ nb,
    const float* __restrict__ zin, float* __restrict__ zout)
{
    __shared__ __align__(8) float sPl[2048], sNl[2048], sPr[1024], sNr[1024];
    __shared__ float sPb[32], sNb[32];
    int tid = threadIdx.x;
    for (int i = tid; i < 2048; i += 128) { sPl[i] = pl[i]; sNl[i] = nl[i]; }
    for (int i = tid; i < 1024; i += 128) { sPr[i] = prw[i]; sNr[i] = nrw[i]; }
    if (tid < 32) { sPb[tid] = pb[tid]; sNb[tid] = nb[tid]; }
    __syncthreads();
    int n = blockIdx.x * 128 + tid;
    if (n >= NN_) return;
    u64 accP[16], accN[16];
    #pragma unroll
    for (int j = 0; j < 16; j++) { accP[j] = 0ull; accN[j] = 0ull; }
    const float4* z4 = reinterpret_cast<const float4*>(zin    + (size_t)n * 64);
    const float4* aP = reinterpret_cast<const float4*>(g_aggP + (size_t)n * 64);
    const float4* aN = reinterpret_cast<const float4*>(g_aggN + (size_t)n * 64);
    #pragma unroll 1
    for (int i4 = 0; i4 < 8; i4++) {
        float4 zp4 = z4[i4], zn4 = z4[8 + i4];
        float4 aPlo4 = aP[i4], aPhi4 = aP[8 + i4];
        float4 aNlo4 = aN[i4], aNhi4 = aN[8 + i4];
        float zps[4] = {zp4.x, zp4.y, zp4.z, zp4.w};
        float zns[4] = {zn4.x, zn4.y, zn4.z, zn4.w};
        float aplo[4] = {aPlo4.x, aPlo4.y, aPlo4.z, aPlo4.w};  // mean_pos(xp)
        float anlo[4] = {aPhi4.x, aPhi4.y, aPhi4.z, aPhi4.w};  // mean_pos(xn)
        float aphi[4] = {aNhi4.x, aNhi4.y, aNhi4.z, aNhi4.w};  // mean_neg(xn)
        float anhi[4] = {aNlo4.x, aNlo4.y, aNlo4.z, aNlo4.w};  // mean_neg(xp)
        #pragma unroll
        for (int c = 0; c < 4; c++) {
            int i = i4 * 4 + c;
            const u64* wPlo = reinterpret_cast<const u64*>(&sPl[i * 32]);
            const u64* wPhi = reinterpret_cast<const u64*>(&sPl[(i + 32) * 32]);
            const u64* wNlo = reinterpret_cast<const u64*>(&sNl[i * 32]);
            const u64* wNhi = reinterpret_cast<const u64*>(&sNl[(i + 32) * 32]);
            const u64* wPr  = reinterpret_cast<const u64*>(&sPr[i * 32]);
            const u64* wNr  = reinterpret_cast<const u64*>(&sNr[i * 32]);
            u64 apl = dup2(aplo[c]), aph = dup2(aphi[c]);
            u64 anl_ = dup2(anlo[c]), anh = dup2(anhi[c]);
            u64 xp2 = dup2(zps[c]), xn2 = dup2(zns[c]);
            #pragma unroll
            for (int j = 0; j < 16; j++) {
                accP[j] = fma2(apl, wPlo[j], fma2(aph, wPhi[j], fma2(xp2, wPr[j], accP[j])));
                accN[j] = fma2(anl_, wNlo[j], fma2(anh, wNhi[j], fma2(xn2, wNr[j], accN[j])));
            }
        }
    }
    float* zr = zout + (size_t)n * 64;
    #pragma unroll
    for (int j = 0; j < 16; j++) {
        float p0, p1, n0, n1;
        up2(accP[j], p0, p1); up2(accN[j], n0, n1);
        p0 += sPb[2 * j]; p1 += sPb[2 * j + 1];
        n0 += sNb[2 * j]; n1 += sNb[2 * j + 1];
        zr[2 * j]          = p0 > 0.f ? p0 : 0.f;
        zr[2 * j + 1]      = p1 > 0.f ? p1 : 0.f;
        zr[32 + 2 * j]     = n0 > 0.f ? n0 : 0.f;
        zr[32 + 2 * j + 1] = n1 > 0.f ? n1 : 0.f;
    }
}

// ---------------- per-edge classifier -> semantic mask (f32x2 on l0,l1) ----------------
__global__ __launch_bounds__(256) void k_val(const int* __restrict__ ei,
                                             const float* __restrict__ lw,
                                             const float* __restrict__ lb)
{
    __shared__ __align__(8) u64 sl01[128];
    __shared__ float sl2[128];
    if (threadIdx.x < 128) {
        int i = threadIdx.x;
        sl01[i] = pk2(lw[i * 3 + 0], lw[i * 3 + 1]);
        sl2[i]  = lw[i * 3 + 2];
    }
    __syncthreads();
    int t = blockIdx.x * 256 + threadIdx.x;
    float m = 0.f;
    if (t < E_) {
        int e0 = ei[t], e1 = ei[E_ + t];
        u64 l01 = pk2(lb[0], lb[1]);
        float l2 = lb[2];
        const float4* za = reinterpret_cast<const float4*>(g_z + (size_t)e0 * 64);
        const float4* zb = reinterpret_cast<const float4*>(g_z + (size_t)e1 * 64);
        #pragma unroll 4
        for (int i4 = 0; i4 < 16; i4++) {
            float4 a4 = za[i4]; float4 b4 = zb[i4];
            float as[4] = {a4.x, a4.y, a4.z, a4.w};
            float bs[4] = {b4.x, b4.y, b4.z, b4.w};
            #pragma unroll
            for (int c = 0; c < 4; c++) {
                int i = i4 * 4 + c;
                u64 a2 = dup2(as[c]), b2 = dup2(bs[c]);
                l01 = fma2(a2, sl01[i], fma2(b2, sl01[64 + i], l01));
                l2 = fmaf(as[c], sl2[i], fmaf(bs[c], sl2[64 + i], l2));
            }
        }
        float l0, l1;
        up2(l01, l0, l1);
        int cls = 0; float best = l0;
        if (l1 > best) { best = l1; cls = 1; }
        if (l2 > best) { cls = 2; }
        m = (float)(cls - 1);
        g_maskS[t] = m;
    }
    float tot = block_reduce_sum_256(fabsf(m));
    if (threadIdx.x == 0) atomicAdd(&g_sums[1], tot);
}

// ---------------- mask fusion -> binary edge weight + degree ----------------
__global__ void k_fuse(const int* __restrict__ ei, const float* __restrict__ fw) {
    int t = blockIdx.x * blockDim.x + threadIdx.x;
    if (t >= E_) return;
    float w0 = fw[0], w1 = fw[1], w2 = fw[2];
    float mx = fmaxf(w0, fmaxf(w1, w2));
    float x0 = expf(w0 - mx), x1 = expf(w1 - mx), x2 = expf(w2 - mx);
    float si = 1.f / (x0 + x1 + x2);
    float Sf = fmaxf(g_sums[0], 1e-12f);
    float Ss = fmaxf(g_sums[1], 1e-12f);
    float fused = x0 * si * (1.0f / (float)E_)
                + x1 * si * g_maskF[t] / Sf
                + x2 * si * g_maskS[t] / Ss;
    float w = (fused > 0.5f) ? 1.f : 0.f;
    g_w[t] = w;
    if (w != 0.f) atomicAdd(&g_deg[ei[t]], w);
}

__global__ void k_normc(const int* __restrict__ ei) {
    int t = blockIdx.x * blockDim.x + threadIdx.x;
    if (t >= E_) return;
    float w = g_w[t];
    if (w == 0.f) { g_norm[t] = 0.f; return; }
    int a = ei[t], b = ei[E_ + t];
    float d0 = g_deg[a], d1 = g_deg[b];
    float dis0 = d0 > 0.f ? rsqrtf(fmaxf(d0, 1e-12f)) : 0.f;
    float dis1 = d1 > 0.f ? rsqrtf(fmaxf(d1, 1e-12f)) : 0.f;
    g_norm[t] = dis0 * w * dis1;
}

// ---------------- LightGCN propagation hop (skips zero-weight edges) ----------------
__global__ __launch_bounds__(256) void k_prop(const int* __restrict__ ei,
                                              const float* __restrict__ xin,
                                              float* __restrict__ xout)
{
    int e = blockIdx.x * 256 + threadIdx.x;
    if (e >= E_) return;
    float nv = g_norm[e];
    if (nv == 0.f) return;
    int d = ei[e], s = ei[E_ + e];
    const float4* xs = reinterpret_cast<const float4*>(xin + (size_t)s * 64);
    float* ob = xout + (size_t)d * 64;
    #pragma unroll
    for (int c = 0; c < 16; c++) {
        float4 v = xs[c];
        atomicAdd(ob + c * 4 + 0, nv * v.x);
        atomicAdd(ob + c * 4 + 1, nv * v.y);
        atomicAdd(ob + c * 4 + 2, nv * v.z);
        atomicAdd(ob + c * 4 + 3, nv * v.w);
    }
}

// ---------------- final output: out = (acc + xkB) / 4 ; plus emb passthrough ----------------
__global__ void k_output(float* __restrict__ out,
                         const float* __restrict__ lgu, const float* __restrict__ lgi)
{
    int t = blockIdx.x * blockDim.x + threadIdx.x;
    if (t >= NND_) return;
    float fv = (g_acc[t] + g_xkB[t]) * 0.25f;
    if (t < NUD_) {
        out[t]        = fv;
        out[NUD_ + t] = lgu[t];
    } else {
        int j = t - NUD_;
        out[2 * NUD_ + j]        = fv;
        out[2 * NUD_ + NFD_ + j] = lgi[j];
    }
}

// ---------------- host orchestration ----------------
extern "C" void kernel_launch(void* const* d_in, const int* in_sizes, int n_in,
                              void* d_out, int out_size)
{
    (void)in_sizes; (void)n_in; (void)out_size;
    const float* user_feat = (const float*)d_in[0];
    const float* food_feat = (const float*)d_in[1];
    const int*   edge      = (const int*)d_in[2];
    const int*   pedge     = (const int*)d_in[3];
    const int*   nedge     = (const int*)d_in[4];
    const float* W_user    = (const float*)d_in[5];
    const float* b_user    = (const float*)d_in[6];
    const float* W_food    = (const float*)d_in[7];
    const float* b_food    = (const float*)d_in[8];
    const float* metric    = (const float*)d_in[9];
    const float* fusion    = (const float*)d_in[10];
    const float* sg_u      = (const float*)d_in[11];
    const float* sg_i      = (const float*)d_in[12];
    const float* c1pl      = (const float*)d_in[13];
    const float* c1pr      = (const float*)d_in[14];
    const float* c1pb      = (const float*)d_in[15];
    const float* c1nl      = (const float*)d_in[16];
    const float* c1nr      = (const float*)d_in[17];
    const float* c1nb      = (const float*)d_in[18];
    const float* cspl      = (const float*)d_in[19];
    const float* cspr      = (const float*)d_in[20];
    const float* cspb      = (const float*)d_in[21];
    const float* csnl      = (const float*)d_in[22];
    const float* csnr      = (const float*)d_in[23];
    const float* csnb      = (const float*)d_in[24];
    const float* linw      = (const float*)d_in[25];
    const float* linb      = (const float*)d_in[26];
    const float* lg_u      = (const float*)d_in[27];
    const float* lg_i      = (const float*)d_in[28];
    float* out = (float*)d_out;

    float *pu, *pf, *px, *pz, *pz2, *pxkA, *pxkB;
    cudaGetSymbolAddress((void**)&pu,   g_u);
    cudaGetSymbolAddress((void**)&pf,   g_f);
    cudaGetSymbolAddress((void**)&px,   g_x);
    cudaGetSymbolAddress((void**)&pz,   g_z);
    cudaGetSymbolAddress((void**)&pz2,  g_z2);
    cudaGetSymbolAddress((void**)&pxkA, g_xkA);
    cudaGetSymbolAddress((void**)&pxkB, g_xkB);

    const int SB = cdiv(NN_, 1024);   // 98 scan blocks per sign

    // init: counters, deg, sums, CSR tails
    k_init<<<cdiv(NN_, 256), 256>>>();

    // feature GEMMs + feature-similarity mask
    k_gemm_relu<<<cdiv(NU_, 64), 256>>>(user_feat, W_user, b_user, pu, NU_);
    k_gemm_relu<<<cdiv(NF_, 64), 256>>>(food_feat, W_food, b_food, pf, NF_);
    k_edge_sim<<<cdiv(E_, 256), 256>>>(edge, metric);

    // x = concat(sg_users, sg_items)
    k_copyx<<<cdiv(NND_ / 4, 256), 256>>>((const float4*)sg_u, (const float4*)sg_i);

    // CSR build (both signs)
    k_countboth<<<cdiv(EP_ + EN_, 256), 256>>>(pedge, nedge);
    k_scan1<<<dim3(SB, 2), 1024>>>();
    k_scan2<<<2, 128>>>(SB);
    k_scan3<<<dim3(SB, 2), 1024>>>();
    k_copycur<<<cdiv(NN_ / 4, 256), 256>>>();
    k_fillboth<<<cdiv(EP_ + EN_, 256), 256>>>(pedge, nedge);

    const int GG = cdiv(NN_ * 32, 256);  // gather grid (warp per node)

    // layer 1
    k_gather2<<<dim3(GG, 2), 256>>>(px);
    k_layer1<<<cdiv(NN_, 128), 128>>>(c1pl, c1pr, c1pb, c1nl, c1nr, c1nb);
    // layer 2
    k_gather2<<<dim3(GG, 2), 256>>>(pz);
    k_layer23<<<cdiv(NN_, 128), 128>>>(cspl, cspr, cspb, csnl, csnr, csnb, pz, pz2);
    // layer 3
    k_gather2<<<dim3(GG, 2), 256>>>(pz2);
    k_layer23<<<cdiv(NN_, 128), 128>>>(cspl + 2048, cspr + 1024, cspb + 32,
                                       csnl + 2048, csnr + 1024, csnb + 32, pz2, pz);

    // semantic mask + fusion + edge weights
    k_val<<<cdiv(E_, 256), 256>>>(edge, linw, linb);
    k_fuse<<<cdiv(E_, 256), 256>>>(edge, fusion);
    k_normc<<<cdiv(E_, 256), 256>>>(edge);

    // LightGCN: acc = emb, xkA = emb, xkB = 0; 3 hops with fused acc+zero
    k_copyemb<<<cdiv(NND_ / 4, 256), 256>>>((const float4*)lg_u, (const float4*)lg_i);
    k_prop<<<cdiv(E_, 256), 256>>>(edge, pxkA, pxkB);
    k_accz<<<cdiv(NND_ / 4, 256), 256>>>((const float4*)pxkB, (float4*)pxkA);
    k_prop<<<cdiv(E_, 256), 256>>>(edge, pxkB, pxkA);
    k_accz<<<cdiv(NND_ / 4, 256), 256>>>((const float4*)pxkA, (float4*)pxkB);
    k_prop<<<cdiv(E_, 256), 256>>>(edge, pxkA, pxkB);

    // out = (acc + xkB)/4 ; [final_users, lg_users, final_items, lg_items]
    k_output<<<cdiv(NND_, 256), 256>>>(out, lg_u, lg_i);
}

// round 6
// speedup vs baseline: 2.5124x; 1.2905x over previous
#include <cuda_runtime.h>
#include <cuda_bf16.h>
#include <cstdint>

#define NU_ 50000
#define NF_ 50000
#define NN_ 100000
#define D_ 64
#define H2_ 32
#define K_ 256
#define E_ 500000
#define EP_ 500000
#define EN_ 500000
#define NND_ (NN_*D_)
#define NUD_ (NU_*D_)
#define NFD_ (NF_*D_)

typedef unsigned long long u64;
typedef unsigned int u32;

// ---------------- f32x2 packed-math helpers ----------------
__device__ __forceinline__ u64 pk2(float lo, float hi) {
    u64 r; asm("mov.b64 %0, {%1,%2};" : "=l"(r) : "f"(lo), "f"(hi)); return r;
}
__device__ __forceinline__ u64 dup2(float v) {
    u64 r; asm("mov.b64 %0, {%1,%1};" : "=l"(r) : "f"(v)); return r;
}
__device__ __forceinline__ void up2(u64 v, float& lo, float& hi) {
    asm("mov.b64 {%0,%1}, %2;" : "=f"(lo), "=f"(hi) : "l"(v));
}
__device__ __forceinline__ u64 fma2(u64 a, u64 b, u64 c) {
    u64 d; asm("fma.rn.f32x2 %0, %1, %2, %3;" : "=l"(d) : "l"(a), "l"(b), "l"(c)); return d;
}
__device__ __forceinline__ u64 mul2(u64 a, u64 b) {
    u64 d; asm("mul.rn.f32x2 %0, %1, %2;" : "=l"(d) : "l"(a), "l"(b)); return d;
}
__device__ __forceinline__ float2 bf2f(u32 w) {
    __nv_bfloat162 h = *reinterpret_cast<__nv_bfloat162*>(&w);
    return __bfloat1622float2(h);
}
__device__ __forceinline__ u32 f2bf(float a, float b) {
    __nv_bfloat162 h = __floats2bfloat162_rn(a, b);
    return *reinterpret_cast<u32*>(&h);
}

// ---------------- scratch (static device globals; no allocation) ----------------
__device__ unsigned short g_u16[NUD_];   // bf16 user features (sim only)
__device__ unsigned short g_f16[NFD_];   // bf16 food features (sim only)
__device__ float g_nau[NU_ * 4];         // per-user per-head norms
__device__ float g_naf[NF_ * 4];         // per-food per-head norms
__device__ float g_x[NND_];
__device__ float g_z[NND_];
__device__ float g_z2[NND_];
__device__ unsigned short g_zb[NND_];    // bf16 final z (val only)
__device__ float g_aggP[NND_];
__device__ float g_aggN[NND_];
__device__ int   g_cntp[NN_];
__device__ int   g_cntn[NN_];
__device__ int   g_offP[NN_ + 1];
__device__ int   g_offN[NN_ + 1];
__device__ int   g_curP[NN_];
__device__ int   g_curN[NN_];
__device__ int   g_adjP[EP_];
__device__ int   g_adjN[EN_];
__device__ int   g_bsum[256];            // [2][128]
__device__ float g_maskF[E_];
__device__ float g_maskS[E_];
__device__ float g_w[E_];
__device__ float g_norm[E_];
__device__ float g_deg[NN_];
__device__ float g_acc[NND_];
__device__ float g_xkA[NND_];
__device__ float g_xkB[NND_];
__device__ float g_sums[4];

static inline int cdiv(int a, int b) { return (a + b - 1) / b; }

// ---------------- fused init: counters/deg/sums/tails + copyx + copyemb ----------------
__global__ void k_init_all(const float4* __restrict__ su, const float4* __restrict__ si,
                           const float4* __restrict__ lu, const float4* __restrict__ li)
{
    int i = blockIdx.x * blockDim.x + threadIdx.x;
    if (i < NND_ / 4) {
        float4 xv = (i < NUD_ / 4) ? su[i] : si[i - NUD_ / 4];
        reinterpret_cast<float4*>(g_x)[i] = xv;
        float4 ev = (i < NUD_ / 4) ? lu[i] : li[i - NUD_ / 4];
        reinterpret_cast<float4*>(g_acc)[i] = ev;
        reinterpret_cast<float4*>(g_xkA)[i] = ev;
        reinterpret_cast<float4*>(g_xkB)[i] = make_float4(0.f, 0.f, 0.f, 0.f);
    }
    if (i < NN_) { g_cntp[i] = 0; g_cntn[i] = 0; g_deg[i] = 0.f; }
    if (i == 0) {
        g_sums[0] = 0.f; g_sums[1] = 0.f; g_sums[2] = 0.f; g_sums[3] = 0.f;
        g_offP[NN_] = EP_; g_offN[NN_] = EN_;
    }
}

// acc += xk ; zbuf = 0
__global__ void k_accz(const float4* __restrict__ xk, float4* __restrict__ zbuf) {
    int i = blockIdx.x * blockDim.x + threadIdx.x;
    if (i >= NND_ / 4) return;
    float4 a = reinterpret_cast<float4*>(g_acc)[i];
    float4 b = xk[i];
    a.x += b.x; a.y += b.y; a.z += b.z; a.w += b.w;
    reinterpret_cast<float4*>(g_acc)[i] = a;
    zbuf[i] = make_float4(0.f, 0.f, 0.f, 0.f);
}

__device__ __forceinline__ float block_reduce_sum_256(float v) {
    __shared__ float sh[8];
    int lane = threadIdx.x & 31, w = threadIdx.x >> 5;
    #pragma unroll
    for (int o = 16; o > 0; o >>= 1) v += __shfl_down_sync(0xffffffffu, v, o);
    if (lane == 0) sh[w] = v;
    __syncthreads();
    if (w == 0) {
        v = (lane < 8) ? sh[lane] : 0.f;
        #pragma unroll
        for (int o = 4; o > 0; o >>= 1) v += __shfl_down_sync(0xffffffffu, v, o);
    }
    return v;
}

// ---------------- CSR build ----------------
__global__ void k_countboth(const int* __restrict__ pe, const int* __restrict__ ne) {
    int t = blockIdx.x * blockDim.x + threadIdx.x;
    if (t < EP_) atomicAdd(&g_cntp[pe[EP_ + t]], 1);
    else if (t < EP_ + EN_) atomicAdd(&g_cntn[ne[EN_ + (t - EP_)]], 1);
}

__device__ __forceinline__ int warp_scan_incl(int v, int lane) {
    #pragma unroll
    for (int o = 1; o < 32; o <<= 1) {
        int u = __shfl_up_sync(0xffffffffu, v, o);
        if (lane >= o) v += u;
    }
    return v;
}

__global__ __launch_bounds__(1024) void k_scan1() {
    __shared__ int wsum[32];
    int y = blockIdx.y;
    const int* cnt = y ? g_cntn : g_cntp;
    int* out = y ? g_offN : g_offP;
    int t = threadIdx.x, lane = t & 31, w = t >> 5;
    int i = blockIdx.x * 1024 + t;
    int v = (i < NN_) ? cnt[i] : 0;
    int s = warp_scan_incl(v, lane);
    if (lane == 31) wsum[w] = s;
    __syncthreads();
    if (w == 0) {
        int x = wsum[lane];
        x = warp_scan_incl(x, lane);
        wsum[lane] = x;
    }
    __syncthreads();
    int base = (w > 0) ? wsum[w - 1] : 0;
    if (i < NN_) out[i] = base + s - v;
    if (t == 1023) g_bsum[y * 128 + blockIdx.x] = base + s;
}

__global__ __launch_bounds__(128) void k_scan2(int nb) {
    __shared__ int wsum[4];
    int* bsum = g_bsum + blockIdx.x * 128;
    int t = threadIdx.x, lane = t & 31, w = t >> 5;
    int v = (t < nb) ? bsum[t] : 0;
    int s = warp_scan_incl(v, lane);
    if (lane == 31) wsum[w] = s;
    __syncthreads();
    int add = 0;
    #pragma unroll
    for (int k = 0; k < 4; k++) if (k < w) add += wsum[k];
    if (t < nb) bsum[t] = add + s - v;
}

// scan finalize + cur copy fused
__global__ __launch_bounds__(1024) void k_scan3() {
    int y = blockIdx.y;
    int* out = y ? g_offN : g_offP;
    int* cur = y ? g_curN : g_curP;
    int i = blockIdx.x * 1024 + threadIdx.x;
    if (i < NN_) {
        int v = out[i] + g_bsum[y * 128 + blockIdx.x];
        out[i] = v;
        cur[i] = v;
    }
}

__global__ void k_fillboth(const int* __restrict__ pe, const int* __restrict__ ne) {
    int t = blockIdx.x * blockDim.x + threadIdx.x;
    if (t < EP_) {
        int d = pe[EP_ + t];
        int slot = atomicAdd(&g_curP[d], 1);
        g_adjP[slot] = pe[t];
    } else if (t < EP_ + EN_) {
        int u = t - EP_;
        int d = ne[EN_ + u];
        int slot = atomicAdd(&g_curN[d], 1);
        g_adjN[slot] = ne[u];
    }
}

// ---------------- dual warp-per-node segment MEAN gather ----------------
__global__ __launch_bounds__(256) void k_gather2(const float* __restrict__ feat) {
    int y = blockIdx.y;
    const int* off = y ? g_offN : g_offP;
    const int* adj = y ? g_adjN : g_adjP;
    float* outm = y ? g_aggN : g_aggP;
    int g = blockIdx.x * 256 + threadIdx.x;
    int node = g >> 5, lane = g & 31;
    if (node >= NN_) return;
    int s = off[node], e = off[node + 1];
    float2 acc = make_float2(0.f, 0.f);
    const float2* base = reinterpret_cast<const float2*>(feat);
    for (int k = s; k < e; k++) {
        int sr = adj[k];
        float2 v = base[(size_t)sr * 32 + lane];
        acc.x += v.x; acc.y += v.y;
    }
    float inv = 1.f / (float)max(e - s, 1);
    reinterpret_cast<float2*>(outm)[(size_t)node * 32 + lane] =
        make_float2(acc.x * inv, acc.y * inv);
}

// ---------------- merged feature GEMM (user+food via blockIdx.y), bf16 out + norms ----------------
__global__ __launch_bounds__(256) void k_gemm_relu(
    const float* __restrict__ Au, const float* __restrict__ Wu, const float* __restrict__ bu,
    const float* __restrict__ Af, const float* __restrict__ Wf, const float* __restrict__ bf,
    const float* __restrict__ mw)
{
    __shared__ __align__(16) float AsT[64][68];
    __shared__ __align__(16) float Ws[64][64];
    __shared__ float sW[256];
    int yb = blockIdx.y;
    const float* A = yb ? Af : Au;
    const float* W = yb ? Wf : Wu;
    const float* bias = yb ? bf : bu;
    unsigned short* C = yb ? g_f16 : g_u16;
    float* NA = yb ? g_naf : g_nau;
    const int M = yb ? NF_ : NU_;

    int tid = threadIdx.x;
    if (tid < 256) sW[tid] = mw[tid];
    int r0 = blockIdx.x * 64;
    int tr = tid >> 4, tc = tid & 15;
    u64 acc2[4][2];
    #pragma unroll
    for (int i = 0; i < 4; i++) { acc2[i][0] = 0ull; acc2[i][1] = 0ull; }

    for (int kc = 0; kc < K_; kc += 64) {
        #pragma unroll
        for (int it = 0; it < 16; it++) {
            int idx = tid + it * 256;
            int lr = idx >> 6, lk = idx & 63;
            int gr = r0 + lr;
            AsT[lk][lr] = (gr < M) ? A[(size_t)gr * K_ + kc + lk] : 0.f;
        }
        #pragma unroll
        for (int it = 0; it < 16; it++) {
            int idx = tid + it * 256;
            int lk = idx >> 6, n = idx & 63;
            Ws[lk][n] = W[(size_t)(kc + lk) * 64 + n];
        }
        __syncthreads();
        #pragma unroll 4
        for (int kk = 0; kk < 64; kk++) {
            float4 a4 = *reinterpret_cast<const float4*>(&AsT[kk][tr * 4]);
            const u64* w2 = reinterpret_cast<const u64*>(&Ws[kk][tc * 4]);
            u64 wlo = w2[0], whi = w2[1];
            u64 a0 = dup2(a4.x), a1 = dup2(a4.y), a2 = dup2(a4.z), a3 = dup2(a4.w);
            acc2[0][0] = fma2(a0, wlo, acc2[0][0]); acc2[0][1] = fma2(a0, whi, acc2[0][1]);
            acc2[1][0] = fma2(a1, wlo, acc2[1][0]); acc2[1][1] = fma2(a1, whi, acc2[1][1]);
            acc2[2][0] = fma2(a2, wlo, acc2[2][0]); acc2[2][1] = fma2(a2, whi, acc2[2][1]);
            acc2[3][0] = fma2(a3, wlo, acc2[3][0]); acc2[3][1] = fma2(a3, whi, acc2[3][1]);
        }
        __syncthreads();
    }
    int col = tc * 4;
    #pragma unroll
    for (int i = 0; i < 4; i++) {
        int row = r0 + tr * 4 + i;
        float v0, v1, v2, v3;
        up2(acc2[i][0], v0, v1);
        up2(acc2[i][1], v2, v3);
        v0 += bias[col + 0]; v1 += bias[col + 1];
        v2 += bias[col + 2]; v3 += bias[col + 3];
        v0 = v0 > 0.f ? v0 : 0.f; v1 = v1 > 0.f ? v1 : 0.f;
        v2 = v2 > 0.f ? v2 : 0.f; v3 = v3 > 0.f ? v3 : 0.f;
        // per-head weighted squared-norm partials, reduce over 16 lanes (one row group)
        float p[4];
        #pragma unroll
        for (int h = 0; h < 4; h++) {
            float w0 = sW[h * 64 + col + 0] * v0;
            float w1 = sW[h * 64 + col + 1] * v1;
            float w2_ = sW[h * 64 + col + 2] * v2;
            float w3 = sW[h * 64 + col + 3] * v3;
            p[h] = w0 * w0 + w1 * w1 + w2_ * w2_ + w3 * w3;
            #pragma unroll
            for (int o = 8; o > 0; o >>= 1)
                p[h] += __shfl_down_sync(0xffffffffu, p[h], o, 16);
        }
        if (row < M) {
            u32 w0 = f2bf(v0, v1), w1 = f2bf(v2, v3);
            *reinterpret_cast<uint2*>(&reinterpret_cast<u32*>(C)[(size_t)row * 32 + tc * 2]) =
                make_uint2(w0, w1);
            if (tc == 0) {
                float4 na = make_float4(fmaxf(sqrtf(p[0]), 1e-8f), fmaxf(sqrtf(p[1]), 1e-8f),
                                        fmaxf(sqrtf(p[2]), 1e-8f), fmaxf(sqrtf(p[3]), 1e-8f));
                *reinterpret_cast<float4*>(&NA[(size_t)row * 4]) = na;
            }
        }
    }
}

// ---------------- per-edge similarity mask: bf16 rows + precomputed norms ----------------
__global__ __launch_bounds__(256) void k_edge_sim(const int* __restrict__ ei,
                                                  const float* __restrict__ mw)
{
    __shared__ __align__(8) u64 swsq[4][32];   // [h][i-pair] = (w^2 at 2i, 2i+1)
    if (threadIdx.x < 128) {
        int h = threadIdx.x >> 5, ip = threadIdx.x & 31;
        float wa = mw[h * 64 + 2 * ip], wb = mw[h * 64 + 2 * ip + 1];
        swsq[h][ip] = pk2(wa * wa, wb * wb);
    }
    __syncthreads();
    int t = blockIdx.x * 256 + threadIdx.x;
    float m = 0.f;
    if (t < E_) {
        int e0 = ei[t], e1 = ei[E_ + t];
        const uint4* ur = reinterpret_cast<const uint4*>(g_u16) + (size_t)e0 * 8;
        const uint4* fr = reinterpret_cast<const uint4*>(g_f16) + (size_t)e1 * 8;
        float4 na = *reinterpret_cast<const float4*>(&g_nau[(size_t)e0 * 4]);
        float4 nb = *reinterpret_cast<const float4*>(&g_naf[(size_t)e1 * 4]);
        u64 d0 = 0ull, d1 = 0ull, d2 = 0ull, d3 = 0ull;
        #pragma unroll
        for (int k = 0; k < 8; k++) {
            uint4 uu = ur[k], ff = fr[k];
            u32 uw[4] = {uu.x, uu.y, uu.z, uu.w};
            u32 fw[4] = {ff.x, ff.y, ff.z, ff.w};
            #pragma unroll
            for (int w = 0; w < 4; w++) {
                float2 ul = bf2f(uw[w]), fl = bf2f(fw[w]);
                u64 uf = mul2(pk2(ul.x, ul.y), pk2(fl.x, fl.y));
                int ip = k * 4 + w;
                d0 = fma2(uf, swsq[0][ip], d0);
                d1 = fma2(uf, swsq[1][ip], d1);
                d2 = fma2(uf, swsq[2][ip], d2);
                d3 = fma2(uf, swsq[3][ip], d3);
            }
        }
        float a, b;
        float dh0, dh1, dh2, dh3;
        up2(d0, a, b); dh0 = a + b;
        up2(d1, a, b); dh1 = a + b;
        up2(d2, a, b); dh2 = a + b;
        up2(d3, a, b); dh3 = a + b;
        float sim = __fdividef(dh0, na.x * nb.x) + __fdividef(dh1, na.y * nb.y)
                  + __fdividef(dh2, na.z * nb.z) + __fdividef(dh3, na.w * nb.w);
        sim *= 0.25f;
        m = (sim < 0.3f) ? 0.f : sim;
        g_maskF[t] = m;
    }
    float tot = block_reduce_sum_256(fabsf(m));
    if (threadIdx.x == 0) atomicAdd(&g_sums[0], tot);
}

// ---------------- signed conv layer 1 node transform (f32x2) ----------------
__global__ __launch_bounds__(128) void k_layer1(
    const float* __restrict__ pl, const float* __restrict__ prw, const float* __restrict__ pb,
    const float* __restrict__ nl, const float* __restrict__ nrw, const float* __restrict__ nb)
{
    __shared__ __align__(8) float sPl[2048], sPr[2048], sNl[2048], sNr[2048];
    __shared__ float sPb[32], sNb[32];
    int tid = threadIdx.x;
    for (int i = tid; i < 2048; i += 128) {
        sPl[i] = pl[i]; sPr[i] = prw[i]; sNl[i] = nl[i]; sNr[i] = nrw[i];
    }
    if (tid < 32) { sPb[tid] = pb[tid]; sNb[tid] = nb[tid]; }
    __syncthreads();
    int n = blockIdx.x * 128 + tid;
    if (n >= NN_) return;
    u64 accP[16], accN[16];
    #pragma unroll
    for (int j = 0; j < 16; j++) { accP[j] = 0ull; accN[j] = 0ull; }
    const float4* xr = reinterpret_cast<const float4*>(g_x    + (size_t)n * 64);
    const float4* pr = reinterpret_cast<const float4*>(g_aggP + (size_t)n * 64);
    const float4* nr = reinterpret_cast<const float4*>(g_aggN + (size_t)n * 64);
    #pragma unroll 1
    for (int i4 = 0; i4 < 16; i4++) {
        float4 xv4 = xr[i4]; float4 mp4 = pr[i4]; float4 mn4 = nr[i4];
        float xs[4] = {xv4.x, xv4.y, xv4.z, xv4.w};
        float ms[4] = {mp4.x, mp4.y, mp4.z, mp4.w};
        float ns[4] = {mn4.x, mn4.y, mn4.z, mn4.w};
        #pragma unroll
        for (int c = 0; c < 4; c++) {
            int i = i4 * 4 + c;
            u64 xv2 = dup2(xs[c]), mv2 = dup2(ms[c]), nv2 = dup2(ns[c]);
            const u64* wpl = reinterpret_cast<const u64*>(&sPl[i * 32]);
            const u64* wpr = reinterpret_cast<const u64*>(&sPr[i * 32]);
            const u64* wnl = reinterpret_cast<const u64*>(&sNl[i * 32]);
            const u64* wnr = reinterpret_cast<const u64*>(&sNr[i * 32]);
            #pragma unroll
            for (int j = 0; j < 16; j++) {
                accP[j] = fma2(mv2, wpl[j], fma2(xv2, wpr[j], accP[j]));
                accN[j] = fma2(nv2, wnl[j], fma2(xv2, wnr[j], accN[j]));
            }
        }
    }
    float* zr = g_z + (size_t)n * 64;
    #pragma unroll
    for (int j = 0; j < 16; j++) {
        float p0, p1, n0, n1;
        up2(accP[j], p0, p1); up2(accN[j], n0, n1);
        p0 += sPb[2 * j]; p1 += sPb[2 * j + 1];
        n0 += sNb[2 * j]; n1 += sNb[2 * j + 1];
        zr[2 * j]          = p0 > 0.f ? p0 : 0.f;
        zr[2 * j + 1]      = p1 > 0.f ? p1 : 0.f;
        zr[32 + 2 * j]     = n0 > 0.f ? n0 : 0.f;
        zr[32 + 2 * j + 1] = n1 > 0.f ? n1 : 0.f;
    }
}

// ---------------- signed conv layers 2/3 node transform (f32x2); OUTBF=1 -> bf16 out ----------------
template<int OUTBF>
__global__ __launch_bounds__(128) void k_layer23(
    const float* __restrict__ pl, const float* __restrict__ prw, const float* __restrict__ pb,
    const float* __restrict__ nl, const float* __restrict__ nrw, const float* __restrict__ nb,
    const float* __restrict__ zin, float* __restrict__ zout)
{
    __shared__ __align__(8) float sPl[2048], sNl[2048], sPr[1024], sNr[1024];
    __shared__ float sPb[32], sNb[32];
    int tid = threadIdx.x;
    for (int i = tid; i < 2048; i += 128) { sPl[i] = pl[i]; sNl[i] = nl[i]; }
    for (int i = tid; i < 1024; i += 128) { sPr[i] = prw[i]; sNr[i] = nrw[i]; }
    if (tid < 32) { sPb[tid] = pb[tid]; sNb[tid] = nb[tid]; }
    __syncthreads();
    int n = blockIdx.x * 128 + tid;
    if (n >= NN_) return;
    u64 accP[16], accN[16];
    #pragma unroll
    for (int j = 0; j < 16; j++) { accP[j] = 0ull; accN[j] = 0ull; }
    const float4* z4 = reinterpret_cast<const float4*>(zin    + (size_t)n * 64);
    const float4* aP = reinterpret_cast<const float4*>(g_aggP + (size_t)n * 64);
    const float4* aN = reinterpret_cast<const float4*>(g_aggN + (size_t)n * 64);
    #pragma unroll 1
    for (int i4 = 0; i4 < 8; i4++) {
        float4 zp4 = z4[i4], zn4 = z4[8 + i4];
        float4 aPlo4 = aP[i4], aPhi4 = aP[8 + i4];
        float4 aNlo4 = aN[i4], aNhi4 = aN[8 + i4];
        float zps[4] = {zp4.x, zp4.y, zp4.z, zp4.w};
        float zns[4] = {zn4.x, zn4.y, zn4.z, zn4.w};
        float aplo[4] = {aPlo4.x, aPlo4.y, aPlo4.z, aPlo4.w};
        float anlo[4] = {aPhi4.x, aPhi4.y, aPhi4.z, aPhi4.w};
        float aphi[4] = {aNhi4.x, aNhi4.y, aNhi4.z, aNhi4.w};
        float anhi[4] = {aNlo4.x, aNlo4.y, aNlo4.z, aNlo4.w};
        #pragma unroll
        for (int c = 0; c < 4; c++) {
            int i = i4 * 4 + c;
            const u64* wPlo = reinterpret_cast<const u64*>(&sPl[i * 32]);
            const u64* wPhi = reinterpret_cast<const u64*>(&sPl[(i + 32) * 32]);
            const u64* wNlo = reinterpret_cast<const u64*>(&sNl[i * 32]);
            const u64* wNhi = reinterpret_cast<const u64*>(&sNl[(i + 32) * 32]);
            const u64* wPr  = reinterpret_cast<const u64*>(&sPr[i * 32]);
            const u64* wNr  = reinterpret_cast<const u64*>(&sNr[i * 32]);
            u64 apl = dup2(aplo[c]), aph = dup2(aphi[c]);
            u64 anl_ = dup2(anlo[c]), anh = dup2(anhi[c]);
            u64 xp2 = dup2(zps[c]), xn2 = dup2(zns[c]);
            #pragma unroll
            for (int j = 0; j < 16; j++) {
                accP[j] = fma2(apl, wPlo[j], fma2(aph, wPhi[j], fma2(xp2, wPr[j], accP[j])));
                accN[j] = fma2(anl_, wNlo[j], fma2(anh, wNhi[j], fma2(xn2, wNr[j], accN[j])));
            }
        }
    }
    if (OUTBF) {
        u32* zr = reinterpret_cast<u32*>(g_zb) + (size_t)n * 32;
        #pragma unroll
        for (int j = 0; j < 16; j++) {
            float p0, p1, n0, n1;
            up2(accP[j], p0, p1); up2(accN[j], n0, n1);
            p0 += sPb[2 * j]; p1 += sPb[2 * j + 1];
            n0 += sNb[2 * j]; n1 += sNb[2 * j + 1];
            p0 = p0 > 0.f ? p0 : 0.f; p1 = p1 > 0.f ? p1 : 0.f;
            n0 = n0 > 0.f ? n0 : 0.f; n1 = n1 > 0.f ? n1 : 0.f;
            zr[j]      = f2bf(p0, p1);
            zr[16 + j] = f2bf(n0, n1);
        }
    } else {
        float* zr = zout + (size_t)n * 64;
        #pragma unroll
        for (int j = 0; j < 16; j++) {
            float p0, p1, n0, n1;
            up2(accP[j], p0, p1); up2(accN[j], n0, n1);
            p0 += sPb[2 * j]; p1 += sPb[2 * j + 1];
            n0 += sNb[2 * j]; n1 += sNb[2 * j + 1];
            zr[2 * j]          = p0 > 0.f ? p0 : 0.f;
            zr[2 * j + 1]      = p1 > 0.f ? p1 : 0.f;
            zr[32 + 2 * j]     = n0 > 0.f ? n0 : 0.f;
            zr[32 + 2 * j + 1] = n1 > 0.f ? n1 : 0.f;
        }
    }
}

// ---------------- per-edge classifier -> semantic mask (bf16 z rows) ----------------
__global__ __launch_bounds__(256) void k_val(const int* __restrict__ ei,
                                             const float* __restrict__ lw,
                                             const float* __restrict__ lb)
{
    __shared__ __align__(8) u64 sl01[128];
    __shared__ float sl2[128];
    if (threadIdx.x < 128) {
        int i = threadIdx.x;
        sl01[i] = pk2(lw[i * 3 + 0], lw[i * 3 + 1]);
        sl2[i]  = lw[i * 3 + 2];
    }
    __syncthreads();
    int t = blockIdx.x * 256 + threadIdx.x;
    float m = 0.f;
    if (t < E_) {
        int e0 = ei[t], e1 = ei[E_ + t];
        u64 l01 = pk2(lb[0], lb[1]);
        float l2 = lb[2];
        const uint4* za = reinterpret_cast<const uint4*>(g_zb) + (size_t)e0 * 8;
        const uint4* zb = reinterpret_cast<const uint4*>(g_zb) + (size_t)e1 * 8;
        #pragma unroll
        for (int k = 0; k < 8; k++) {
            uint4 aa = za[k], bb = zb[k];
            u32 aw[4] = {aa.x, aa.y, aa.z, aa.w};
            u32 bw[4] = {bb.x, bb.y, bb.z, bb.w};
            #pragma unroll
            for (int w = 0; w < 4; w++) {
                int idx = k * 4 + w;            // word index 0..31, cols (2idx, 2idx+1)
                float2 al = bf2f(aw[w]), bl = bf2f(bw[w]);
                l01 = fma2(dup2(al.x), sl01[2 * idx],
                      fma2(dup2(al.y), sl01[2 * idx + 1],
                      fma2(dup2(bl.x), sl01[64 + 2 * idx],
                      fma2(dup2(bl.y), sl01[64 + 2 * idx + 1], l01))));
                l2 = fmaf(al.x, sl2[2 * idx],
                     fmaf(al.y, sl2[2 * idx + 1],
                     fmaf(bl.x, sl2[64 + 2 * idx],
                     fmaf(bl.y, sl2[64 + 2 * idx + 1], l2))));
            }
        }
        float l0, l1;
        up2(l01, l0, l1);
        int cls = 0; float best = l0;
        if (l1 > best) { best = l1; cls = 1; }
        if (l2 > best) { cls = 2; }
        m = (float)(cls - 1);
        g_maskS[t] = m;
    }
    float tot = block_reduce_sum_256(fabsf(m));
    if (threadIdx.x == 0) atomicAdd(&g_sums[1], tot);
}

// ---------------- mask fusion -> binary edge weight + degree ----------------
__global__ void k_fuse(const int* __restrict__ ei, const float* __restrict__ fw) {
    int t = blockIdx.x * blockDim.x + threadIdx.x;
    if (t >= E_) return;
    float w0 = fw[0], w1 = fw[1], w2 = fw[2];
    float mx = fmaxf(w0, fmaxf(w1, w2));
    float x0 = expf(w0 - mx), x1 = expf(w1 - mx), x2 = expf(w2 - mx);
    float si = 1.f / (x0 + x1 + x2);
    float Sf = fmaxf(g_sums[0], 1e-12f);
    float Ss = fmaxf(g_sums[1], 1e-12f);
    float fused = x0 * si * (1.0f / (float)E_)
                + x1 * si * g_maskF[t] / Sf
                + x2 * si * g_maskS[t] / Ss;
    float w = (fused > 0.5f) ? 1.f : 0.f;
    g_w[t] = w;
    if (w != 0.f) atomicAdd(&g_deg[ei[t]], w);
}

__global__ void k_normc(const int* __restrict__ ei) {
    int t = blockIdx.x * blockDim.x + threadIdx.x;
    if (t >= E_) return;
    float w = g_w[t];
    if (w == 0.f) { g_norm[t] = 0.f; return; }
    int a = ei[t], b = ei[E_ + t];
    float d0 = g_deg[a], d1 = g_deg[b];
    float dis0 = d0 > 0.f ? rsqrtf(fmaxf(d0, 1e-12f)) : 0.f;
    float dis1 = d1 > 0.f ? rsqrtf(fmaxf(d1, 1e-12f)) : 0.f;
    g_norm[t] = dis0 * w * dis1;
}

// ---------------- LightGCN propagation hop (skips zero-weight edges) ----------------
__global__ __launch_bounds__(256) void k_prop(const int* __restrict__ ei,
                                              const float* __restrict__ xin,
                                              float* __restrict__ xout)
{
    int e = blockIdx.x * 256 + threadIdx.x;
    if (e >= E_) return;
    float nv = g_norm[e];
    if (nv == 0.f) return;
    int d = ei[e], s = ei[E_ + e];
    const float4* xs = reinterpret_cast<const float4*>(xin + (size_t)s * 64);
    float* ob = xout + (size_t)d * 64;
    #pragma unroll
    for (int c = 0; c < 16; c++) {
        float4 v = xs[c];
        atomicAdd(ob + c * 4 + 0, nv * v.x);
        atomicAdd(ob + c * 4 + 1, nv * v.y);
        atomicAdd(ob + c * 4 + 2, nv * v.z);
        atomicAdd(ob + c * 4 + 3, nv * v.w);
    }
}

// ---------------- final output: out = (acc + xkB)/4 + emb passthrough ----------------
__global__ void k_output(float* __restrict__ out,
                         const float* __restrict__ lgu, const float* __restrict__ lgi)
{
    int t = blockIdx.x * blockDim.x + threadIdx.x;
    if (t >= NND_) return;
    float fv = (g_acc[t] + g_xkB[t]) * 0.25f;
    if (t < NUD_) {
        out[t]        = fv;
        out[NUD_ + t] = lgu[t];
    } else {
        int j = t - NUD_;
        out[2 * NUD_ + j]        = fv;
        out[2 * NUD_ + NFD_ + j] = lgi[j];
    }
}

// ---------------- host orchestration ----------------
extern "C" void kernel_launch(void* const* d_in, const int* in_sizes, int n_in,
                              void* d_out, int out_size)
{
    (void)in_sizes; (void)n_in; (void)out_size;
    const float* user_feat = (const float*)d_in[0];
    const float* food_feat = (const float*)d_in[1];
    const int*   edge      = (const int*)d_in[2];
    const int*   pedge     = (const int*)d_in[3];
    const int*   nedge     = (const int*)d_in[4];
    const float* W_user    = (const float*)d_in[5];
    const float* b_user    = (const float*)d_in[6];
    const float* W_food    = (const float*)d_in[7];
    const float* b_food    = (const float*)d_in[8];
    const float* metric    = (const float*)d_in[9];
    const float* fusion    = (const float*)d_in[10];
    const float* sg_u      = (const float*)d_in[11];
    const float* sg_i      = (const float*)d_in[12];
    const float* c1pl      = (const float*)d_in[13];
    const float* c1pr      = (const float*)d_in[14];
    const float* c1pb      = (const float*)d_in[15];
    const float* c1nl      = (const float*)d_in[16];
    const float* c1nr      = (const float*)d_in[17];
    const float* c1nb      = (const float*)d_in[18];
    const float* cspl      = (const float*)d_in[19];
    const float* cspr      = (const float*)d_in[20];
    const float* cspb      = (const float*)d_in[21];
    const float* csnl      = (const float*)d_in[22];
    const float* csnr      = (const float*)d_in[23];
    const float* csnb      = (const float*)d_in[24];
    const float* linw      = (const float*)d_in[25];
    const float* linb      = (const float*)d_in[26];
    const float* lg_u      = (const float*)d_in[27];
    const float* lg_i      = (const float*)d_in[28];
    float* out = (float*)d_out;

    float *px, *pz, *pz2, *pxkA, *pxkB;
    cudaGetSymbolAddress((void**)&px,   g_x);
    cudaGetSymbolAddress((void**)&pz,   g_z);
    cudaGetSymbolAddress((void**)&pz2,  g_z2);
    cudaGetSymbolAddress((void**)&pxkA, g_xkA);
    cudaGetSymbolAddress((void**)&pxkB, g_xkB);

    const int SB = cdiv(NN_, 1024);

    // side stream + events for fork-join overlap (host objects; leaked, few calls)
    cudaStream_t s1;
    cudaStreamCreateWithFlags(&s1, cudaStreamNonBlocking);
    cudaEvent_t evFork, evJoin;
    cudaEventCreateWithFlags(&evFork, cudaEventDisableTiming);
    cudaEventCreateWithFlags(&evJoin, cudaEventDisableTiming);

    // fused init (x, acc, xkA, xkB, counters, sums, tails)
    k_init_all<<<cdiv(NND_ / 4, 256), 256>>>((const float4*)sg_u, (const float4*)sg_i,
                                             (const float4*)lg_u, (const float4*)lg_i);
    cudaEventRecord(evFork, 0);
    cudaStreamWaitEvent(s1, evFork, 0);

    // ---- branch A (stream 0): GEMMs + edge similarity ----
    k_gemm_relu<<<dim3(cdiv(NU_, 64), 2), 256>>>(user_feat, W_user, b_user,
                                                 food_feat, W_food, b_food, metric);
    k_edge_sim<<<cdiv(E_, 256), 256>>>(edge, metric);

    // ---- branch B (stream s1): CSR + signed conv + classifier ----
    k_countboth<<<cdiv(EP_ + EN_, 256), 256, 0, s1>>>(pedge, nedge);
    k_scan1<<<dim3(SB, 2), 1024, 0, s1>>>();
    k_scan2<<<2, 128, 0, s1>>>(SB);
    k_scan3<<<dim3(SB, 2), 1024, 0, s1>>>();
    k_fillboth<<<cdiv(EP_ + EN_, 256), 256, 0, s1>>>(pedge, nedge);

    const int GG = cdiv(NN_ * 32, 256);
    k_gather2<<<dim3(GG, 2), 256, 0, s1>>>(px);
    k_layer1<<<cdiv(NN_, 128), 128, 0, s1>>>(c1pl, c1pr, c1pb, c1nl, c1nr, c1nb);
    k_gather2<<<dim3(GG, 2), 256, 0, s1>>>(pz);
    k_layer23<0><<<cdiv(NN_, 128), 128, 0, s1>>>(cspl, cspr, cspb, csnl, csnr, csnb, pz, pz2);
    k_gather2<<<dim3(GG, 2), 256, 0, s1>>>(pz2);
    k_layer23<1><<<cdiv(NN_, 128), 128, 0, s1>>>(cspl + 2048, cspr + 1024, cspb + 32,
                                                 csnl + 2048, csnr + 1024, csnb + 32, pz2, pz);
    k_val<<<cdiv(E_, 256), 256, 0, s1>>>(edge, linw, linb);
    cudaEventRecord(evJoin, s1);
    cudaStreamWaitEvent(0, evJoin, 0);

    // ---- join: fusion + propagation + output (stream 0) ----
    k_fuse<<<cdiv(E_, 256), 256>>>(edge, fusion);
    k_normc<<<cdiv(E_, 256), 256>>>(edge);

    k_prop<<<cdiv(E_, 256), 256>>>(edge, pxkA, pxkB);
    k_accz<<<cdiv(NND_ / 4, 256), 256>>>((const float4*)pxkB, (float4*)pxkA);
    k_prop<<<cdiv(E_, 256), 256>>>(edge, pxkB, pxkA);
    k_accz<<<cdiv(NND_ / 4, 256), 256>>>((const float4*)pxkA, (float4*)pxkB);
    k_prop<<<cdiv(E_, 256), 256>>>(edge, pxkA, pxkB);

    k_output<<<cdiv(NND_, 256), 256>>>(out, lg_u, lg_i);
}

// round 7
// speedup vs baseline: 2.7738x; 1.1040x over previous
#include <cuda_runtime.h>
#include <cuda_bf16.h>
#include <cstdint>

#define NU_ 50000
#define NF_ 50000
#define NN_ 100000
#define D_ 64
#define H2_ 32
#define K_ 256
#define E_ 500000
#define EP_ 500000
#define EN_ 500000
#define NND_ (NN_*D_)
#define NUD_ (NU_*D_)
#define NFD_ (NF_*D_)

typedef unsigned long long u64;
typedef unsigned int u32;

// ---------------- f32x2 / bf16 helpers ----------------
__device__ __forceinline__ u64 pk2(float lo, float hi) {
    u64 r; asm("mov.b64 %0, {%1,%2};" : "=l"(r) : "f"(lo), "f"(hi)); return r;
}
__device__ __forceinline__ u64 dup2(float v) {
    u64 r; asm("mov.b64 %0, {%1,%1};" : "=l"(r) : "f"(v)); return r;
}
__device__ __forceinline__ void up2(u64 v, float& lo, float& hi) {
    asm("mov.b64 {%0,%1}, %2;" : "=f"(lo), "=f"(hi) : "l"(v));
}
__device__ __forceinline__ u64 fma2(u64 a, u64 b, u64 c) {
    u64 d; asm("fma.rn.f32x2 %0, %1, %2, %3;" : "=l"(d) : "l"(a), "l"(b), "l"(c)); return d;
}
__device__ __forceinline__ u64 mul2(u64 a, u64 b) {
    u64 d; asm("mul.rn.f32x2 %0, %1, %2;" : "=l"(d) : "l"(a), "l"(b)); return d;
}
__device__ __forceinline__ float2 bf2f(u32 w) {
    __nv_bfloat162 h = *reinterpret_cast<__nv_bfloat162*>(&w);
    return __bfloat1622float2(h);
}
__device__ __forceinline__ u32 f2bf(float a, float b) {
    __nv_bfloat162 h = __floats2bfloat162_rn(a, b);
    return *reinterpret_cast<u32*>(&h);
}

// ---------------- scratch (static device globals; no allocation) ----------------
__device__ unsigned short g_u16[NUD_];   // bf16 user features (sim only)
__device__ unsigned short g_f16[NFD_];   // bf16 food features (sim only)
__device__ float g_nau[NU_ * 4];         // per-user per-head norms
__device__ float g_naf[NF_ * 4];         // per-food per-head norms
__device__ unsigned short g_zA[NND_];    // bf16 z (layers 1,3 out; val reads this)
__device__ unsigned short g_zB[NND_];    // bf16 z (layer 2 out)
__device__ unsigned short g_aggP16[NND_];
__device__ unsigned short g_aggN16[NND_];
__device__ int   g_cntp[NN_];
__device__ int   g_cntn[NN_];
__device__ int   g_offP[NN_ + 1];
__device__ int   g_offN[NN_ + 1];
__device__ int   g_curP[NN_];
__device__ int   g_curN[NN_];
__device__ int   g_adjP[EP_];
__device__ int   g_adjN[EN_];
__device__ int   g_bsum[256];            // [2][128]
__device__ float g_maskF[E_];
__device__ float g_maskS[E_];
__device__ float g_w[E_];
__device__ float g_norm[E_];
__device__ float g_deg[NN_];
__device__ float g_xkA[NND_];            // hop-1 result
__device__ float g_xkB[NND_];            // hop-2 result
__device__ float g_xkC[NND_];            // hop-3 result
__device__ float g_sums[4];

static inline int cdiv(int a, int b) { return (a + b - 1) / b; }

// ---------------- fused init: zero hop buffers + counters + sums + tails ----------------
__global__ void k_init() {
    int i = blockIdx.x * blockDim.x + threadIdx.x;
    if (i < NND_ / 4) {
        float4 z4 = make_float4(0.f, 0.f, 0.f, 0.f);
        reinterpret_cast<float4*>(g_xkA)[i] = z4;
        reinterpret_cast<float4*>(g_xkB)[i] = z4;
        reinterpret_cast<float4*>(g_xkC)[i] = z4;
    }
    if (i < NN_) { g_cntp[i] = 0; g_cntn[i] = 0; g_deg[i] = 0.f; }
    if (i == 0) {
        g_sums[0] = 0.f; g_sums[1] = 0.f; g_sums[2] = 0.f; g_sums[3] = 0.f;
        g_offP[NN_] = EP_; g_offN[NN_] = EN_;
    }
}

__device__ __forceinline__ float block_reduce_sum_256(float v) {
    __shared__ float sh[8];
    int lane = threadIdx.x & 31, w = threadIdx.x >> 5;
    #pragma unroll
    for (int o = 16; o > 0; o >>= 1) v += __shfl_down_sync(0xffffffffu, v, o);
    if (lane == 0) sh[w] = v;
    __syncthreads();
    if (w == 0) {
        v = (lane < 8) ? sh[lane] : 0.f;
        #pragma unroll
        for (int o = 4; o > 0; o >>= 1) v += __shfl_down_sync(0xffffffffu, v, o);
    }
    return v;
}

// ---------------- CSR build ----------------
__global__ void k_countboth(const int* __restrict__ pe, const int* __restrict__ ne) {
    int t = blockIdx.x * blockDim.x + threadIdx.x;
    if (t < EP_) atomicAdd(&g_cntp[pe[EP_ + t]], 1);
    else if (t < EP_ + EN_) atomicAdd(&g_cntn[ne[EN_ + (t - EP_)]], 1);
}

__device__ __forceinline__ int warp_scan_incl(int v, int lane) {
    #pragma unroll
    for (int o = 1; o < 32; o <<= 1) {
        int u = __shfl_up_sync(0xffffffffu, v, o);
        if (lane >= o) v += u;
    }
    return v;
}

__global__ __launch_bounds__(1024) void k_scan1() {
    __shared__ int wsum[32];
    int y = blockIdx.y;
    const int* cnt = y ? g_cntn : g_cntp;
    int* out = y ? g_offN : g_offP;
    int t = threadIdx.x, lane = t & 31, w = t >> 5;
    int i = blockIdx.x * 1024 + t;
    int v = (i < NN_) ? cnt[i] : 0;
    int s = warp_scan_incl(v, lane);
    if (lane == 31) wsum[w] = s;
    __syncthreads();
    if (w == 0) {
        int x = wsum[lane];
        x = warp_scan_incl(x, lane);
        wsum[lane] = x;
    }
    __syncthreads();
    int base = (w > 0) ? wsum[w - 1] : 0;
    if (i < NN_) out[i] = base + s - v;
    if (t == 1023) g_bsum[y * 128 + blockIdx.x] = base + s;
}

__global__ __launch_bounds__(128) void k_scan2(int nb) {
    __shared__ int wsum[4];
    int* bsum = g_bsum + blockIdx.x * 128;
    int t = threadIdx.x, lane = t & 31, w = t >> 5;
    int v = (t < nb) ? bsum[t] : 0;
    int s = warp_scan_incl(v, lane);
    if (lane == 31) wsum[w] = s;
    __syncthreads();
    int add = 0;
    #pragma unroll
    for (int k = 0; k < 4; k++) if (k < w) add += wsum[k];
    if (t < nb) bsum[t] = add + s - v;
}

__global__ __launch_bounds__(1024) void k_scan3() {
    int y = blockIdx.y;
    int* out = y ? g_offN : g_offP;
    int* cur = y ? g_curN : g_curP;
    int i = blockIdx.x * 1024 + threadIdx.x;
    if (i < NN_) {
        int v = out[i] + g_bsum[y * 128 + blockIdx.x];
        out[i] = v;
        cur[i] = v;
    }
}

__global__ void k_fillboth(const int* __restrict__ pe, const int* __restrict__ ne) {
    int t = blockIdx.x * blockDim.x + threadIdx.x;
    if (t < EP_) {
        int d = pe[EP_ + t];
        int slot = atomicAdd(&g_curP[d], 1);
        g_adjP[slot] = pe[t];
    } else if (t < EP_ + EN_) {
        int u = t - EP_;
        int d = ne[EN_ + u];
        int slot = atomicAdd(&g_curN[d], 1);
        g_adjN[slot] = ne[u];
    }
}

// ---------------- dual warp-per-node segment MEAN gather -> bf16 agg ----------------
// FIRST=1: source is fp32 sg_u/sg_i tables; FIRST=0: source is a bf16 z table.
template<int FIRST>
__global__ __launch_bounds__(256) void k_gather2(const float* __restrict__ su,
                                                 const float* __restrict__ si,
                                                 const unsigned short* __restrict__ zsrc)
{
    int y = blockIdx.y;
    const int* off = y ? g_offN : g_offP;
    const int* adj = y ? g_adjN : g_adjP;
    u32* outm = reinterpret_cast<u32*>(y ? g_aggN16 : g_aggP16);
    int g = blockIdx.x * 256 + threadIdx.x;
    int node = g >> 5, lane = g & 31;
    if (node >= NN_) return;
    int s = off[node], e = off[node + 1];
    float2 acc = make_float2(0.f, 0.f);
    if (FIRST) {
        for (int k = s; k < e; k++) {
            int sr = adj[k];
            const float2* row = (sr < NU_)
                ? reinterpret_cast<const float2*>(su) + (size_t)sr * 32
                : reinterpret_cast<const float2*>(si) + (size_t)(sr - NU_) * 32;
            float2 v = row[lane];
            acc.x += v.x; acc.y += v.y;
        }
    } else {
        const u32* zb = reinterpret_cast<const u32*>(zsrc);
        for (int k = s; k < e; k++) {
            int sr = adj[k];
            float2 v = bf2f(zb[(size_t)sr * 32 + lane]);
            acc.x += v.x; acc.y += v.y;
        }
    }
    float inv = 1.f / (float)max(e - s, 1);
    outm[(size_t)node * 32 + lane] = f2bf(acc.x * inv, acc.y * inv);
}

// ---------------- merged feature GEMM (user+food via blockIdx.y), bf16 out + norms ----------------
__global__ __launch_bounds__(256) void k_gemm_relu(
    const float* __restrict__ Au, const float* __restrict__ Wu, const float* __restrict__ bu,
    const float* __restrict__ Af, const float* __restrict__ Wf, const float* __restrict__ bf,
    const float* __restrict__ mw)
{
    __shared__ __align__(16) float AsT[64][68];
    __shared__ __align__(16) float Ws[64][64];
    __shared__ float sW[256];
    int yb = blockIdx.y;
    const float* A = yb ? Af : Au;
    const float* W = yb ? Wf : Wu;
    const float* bias = yb ? bf : bu;
    unsigned short* C = yb ? g_f16 : g_u16;
    float* NA = yb ? g_naf : g_nau;
    const int M = yb ? NF_ : NU_;

    int tid = threadIdx.x;
    if (tid < 256) sW[tid] = mw[tid];
    int r0 = blockIdx.x * 64;
    int tr = tid >> 4, tc = tid & 15;
    u64 acc2[4][2];
    #pragma unroll
    for (int i = 0; i < 4; i++) { acc2[i][0] = 0ull; acc2[i][1] = 0ull; }

    for (int kc = 0; kc < K_; kc += 64) {
        #pragma unroll
        for (int it = 0; it < 16; it++) {
            int idx = tid + it * 256;
            int lr = idx >> 6, lk = idx & 63;
            int gr = r0 + lr;
            AsT[lk][lr] = (gr < M) ? A[(size_t)gr * K_ + kc + lk] : 0.f;
        }
        #pragma unroll
        for (int it = 0; it < 16; it++) {
            int idx = tid + it * 256;
            int lk = idx >> 6, n = idx & 63;
            Ws[lk][n] = W[(size_t)(kc + lk) * 64 + n];
        }
        __syncthreads();
        #pragma unroll 4
        for (int kk = 0; kk < 64; kk++) {
            float4 a4 = *reinterpret_cast<const float4*>(&AsT[kk][tr * 4]);
            const u64* w2 = reinterpret_cast<const u64*>(&Ws[kk][tc * 4]);
            u64 wlo = w2[0], whi = w2[1];
            u64 a0 = dup2(a4.x), a1 = dup2(a4.y), a2 = dup2(a4.z), a3 = dup2(a4.w);
            acc2[0][0] = fma2(a0, wlo, acc2[0][0]); acc2[0][1] = fma2(a0, whi, acc2[0][1]);
            acc2[1][0] = fma2(a1, wlo, acc2[1][0]); acc2[1][1] = fma2(a1, whi, acc2[1][1]);
            acc2[2][0] = fma2(a2, wlo, acc2[2][0]); acc2[2][1] = fma2(a2, whi, acc2[2][1]);
            acc2[3][0] = fma2(a3, wlo, acc2[3][0]); acc2[3][1] = fma2(a3, whi, acc2[3][1]);
        }
        __syncthreads();
    }
    int col = tc * 4;
    #pragma unroll
    for (int i = 0; i < 4; i++) {
        int row = r0 + tr * 4 + i;
        float v0, v1, v2, v3;
        up2(acc2[i][0], v0, v1);
        up2(acc2[i][1], v2, v3);
        v0 += bias[col + 0]; v1 += bias[col + 1];
        v2 += bias[col + 2]; v3 += bias[col + 3];
        v0 = v0 > 0.f ? v0 : 0.f; v1 = v1 > 0.f ? v1 : 0.f;
        v2 = v2 > 0.f ? v2 : 0.f; v3 = v3 > 0.f ? v3 : 0.f;
        float p[4];
        #pragma unroll
        for (int h = 0; h < 4; h++) {
            float w0 = sW[h * 64 + col + 0] * v0;
            float w1 = sW[h * 64 + col + 1] * v1;
            float w2_ = sW[h * 64 + col + 2] * v2;
            float w3 = sW[h * 64 + col + 3] * v3;
            p[h] = w0 * w0 + w1 * w1 + w2_ * w2_ + w3 * w3;
            #pragma unroll
            for (int o = 8; o > 0; o >>= 1)
                p[h] += __shfl_down_sync(0xffffffffu, p[h], o, 16);
        }
        if (row < M) {
            u32 w0 = f2bf(v0, v1), w1 = f2bf(v2, v3);
            *reinterpret_cast<uint2*>(&reinterpret_cast<u32*>(C)[(size_t)row * 32 + tc * 2]) =
                make_uint2(w0, w1);
            if (tc == 0) {
                float4 na = make_float4(fmaxf(sqrtf(p[0]), 1e-8f), fmaxf(sqrtf(p[1]), 1e-8f),
                                        fmaxf(sqrtf(p[2]), 1e-8f), fmaxf(sqrtf(p[3]), 1e-8f));
                *reinterpret_cast<float4*>(&NA[(size_t)row * 4]) = na;
            }
        }
    }
}

// ---------------- per-edge similarity mask: bf16 rows + precomputed norms ----------------
__global__ __launch_bounds__(256) void k_edge_sim(const int* __restrict__ ei,
                                                  const float* __restrict__ mw)
{
    __shared__ __align__(8) u64 swsq[4][32];
    if (threadIdx.x < 128) {
        int h = threadIdx.x >> 5, ip = threadIdx.x & 31;
        float wa = mw[h * 64 + 2 * ip], wb = mw[h * 64 + 2 * ip + 1];
        swsq[h][ip] = pk2(wa * wa, wb * wb);
    }
    __syncthreads();
    int t = blockIdx.x * 256 + threadIdx.x;
    float m = 0.f;
    if (t < E_) {
        int e0 = ei[t], e1 = ei[E_ + t];
        const uint4* ur = reinterpret_cast<const uint4*>(g_u16) + (size_t)e0 * 8;
        const uint4* fr = reinterpret_cast<const uint4*>(g_f16) + (size_t)e1 * 8;
        float4 na = *reinterpret_cast<const float4*>(&g_nau[(size_t)e0 * 4]);
        float4 nb = *reinterpret_cast<const float4*>(&g_naf[(size_t)e1 * 4]);
        u64 d0 = 0ull, d1 = 0ull, d2 = 0ull, d3 = 0ull;
        #pragma unroll
        for (int k = 0; k < 8; k++) {
            uint4 uu = ur[k], ff = fr[k];
            u32 uw[4] = {uu.x, uu.y, uu.z, uu.w};
            u32 fw[4] = {ff.x, ff.y, ff.z, ff.w};
            #pragma unroll
            for (int w = 0; w < 4; w++) {
                float2 ul = bf2f(uw[w]), fl = bf2f(fw[w]);
                u64 uf = mul2(pk2(ul.x, ul.y), pk2(fl.x, fl.y));
                int ip = k * 4 + w;
                d0 = fma2(uf, swsq[0][ip], d0);
                d1 = fma2(uf, swsq[1][ip], d1);
                d2 = fma2(uf, swsq[2][ip], d2);
                d3 = fma2(uf, swsq[3][ip], d3);
            }
        }
        float a, b;
        float dh0, dh1, dh2, dh3;
        up2(d0, a, b); dh0 = a + b;
        up2(d1, a, b); dh1 = a + b;
        up2(d2, a, b); dh2 = a + b;
        up2(d3, a, b); dh3 = a + b;
        float sim = __fdividef(dh0, na.x * nb.x) + __fdividef(dh1, na.y * nb.y)
                  + __fdividef(dh2, na.z * nb.z) + __fdividef(dh3, na.w * nb.w);
        sim *= 0.25f;
        m = (sim < 0.3f) ? 0.f : sim;
        g_maskF[t] = m;
    }
    float tot = block_reduce_sum_256(fabsf(m));
    if (threadIdx.x == 0) atomicAdd(&g_sums[0], tot);
}

// ---------------- signed conv layer 1 (x from sg tables fp32; agg bf16; out bf16 zA) ----------------
__global__ __launch_bounds__(128) void k_layer1(
    const float* __restrict__ pl, const float* __restrict__ prw, const float* __restrict__ pb,
    const float* __restrict__ nl, const float* __restrict__ nrw, const float* __restrict__ nb,
    const float* __restrict__ su, const float* __restrict__ si)
{
    __shared__ __align__(8) float sPl[2048], sPr[2048], sNl[2048], sNr[2048];
    __shared__ float sPb[32], sNb[32];
    int tid = threadIdx.x;
    for (int i = tid; i < 2048; i += 128) {
        sPl[i] = pl[i]; sPr[i] = prw[i]; sNl[i] = nl[i]; sNr[i] = nrw[i];
    }
    if (tid < 32) { sPb[tid] = pb[tid]; sNb[tid] = nb[tid]; }
    __syncthreads();
    int n = blockIdx.x * 128 + tid;
    if (n >= NN_) return;
    u64 accP[16], accN[16];
    #pragma unroll
    for (int j = 0; j < 16; j++) { accP[j] = 0ull; accN[j] = 0ull; }
    const float4* xr = (n < NU_)
        ? reinterpret_cast<const float4*>(su) + (size_t)n * 16
        : reinterpret_cast<const float4*>(si) + (size_t)(n - NU_) * 16;
    const uint2* pr = reinterpret_cast<const uint2*>(g_aggP16) + (size_t)n * 16;
    const uint2* nr = reinterpret_cast<const uint2*>(g_aggN16) + (size_t)n * 16;
    #pragma unroll 1
    for (int i4 = 0; i4 < 16; i4++) {
        float4 xv4 = xr[i4];
        uint2 mpw = pr[i4], mnw = nr[i4];
        float2 mplo = bf2f(mpw.x), mphi = bf2f(mpw.y);
        float2 mnlo = bf2f(mnw.x), mnhi = bf2f(mnw.y);
        float xs[4] = {xv4.x, xv4.y, xv4.z, xv4.w};
        float ms[4] = {mplo.x, mplo.y, mphi.x, mphi.y};
        float ns[4] = {mnlo.x, mnlo.y, mnhi.x, mnhi.y};
        #pragma unroll
        for (int c = 0; c < 4; c++) {
            int i = i4 * 4 + c;
            u64 xv2 = dup2(xs[c]), mv2 = dup2(ms[c]), nv2 = dup2(ns[c]);
            const u64* wpl = reinterpret_cast<const u64*>(&sPl[i * 32]);
            const u64* wpr = reinterpret_cast<const u64*>(&sPr[i * 32]);
            const u64* wnl = reinterpret_cast<const u64*>(&sNl[i * 32]);
            const u64* wnr = reinterpret_cast<const u64*>(&sNr[i * 32]);
            #pragma unroll
            for (int j = 0; j < 16; j++) {
                accP[j] = fma2(mv2, wpl[j], fma2(xv2, wpr[j], accP[j]));
                accN[j] = fma2(nv2, wnl[j], fma2(xv2, wnr[j], accN[j]));
            }
        }
    }
    u32* zr = reinterpret_cast<u32*>(g_zA) + (size_t)n * 32;
    #pragma unroll
    for (int j = 0; j < 16; j++) {
        float p0, p1, n0, n1;
        up2(accP[j], p0, p1); up2(accN[j], n0, n1);
        p0 += sPb[2 * j]; p1 += sPb[2 * j + 1];
        n0 += sNb[2 * j]; n1 += sNb[2 * j + 1];
        p0 = p0 > 0.f ? p0 : 0.f; p1 = p1 > 0.f ? p1 : 0.f;
        n0 = n0 > 0.f ? n0 : 0.f; n1 = n1 > 0.f ? n1 : 0.f;
        zr[j]      = f2bf(p0, p1);
        zr[16 + j] = f2bf(n0, n1);
    }
}

// ---------------- signed conv layers 2/3 (all bf16 in/out) ----------------
__global__ __launch_bounds__(128) void k_layer23(
    const float* __restrict__ pl, const float* __restrict__ prw, const float* __restrict__ pb,
    const float* __restrict__ nl, const float* __restrict__ nrw, const float* __restrict__ nb,
    const unsigned short* __restrict__ zin, unsigned short* __restrict__ zout)
{
    __shared__ __align__(8) float sPl[2048], sNl[2048], sPr[1024], sNr[1024];
    __shared__ float sPb[32], sNb[32];
    int tid = threadIdx.x;
    for (int i = tid; i < 2048; i += 128) { sPl[i] = pl[i]; sNl[i] = nl[i]; }
    for (int i = tid; i < 1024; i += 128) { sPr[i] = prw[i]; sNr[i] = nrw[i]; }
    if (tid < 32) { sPb[tid] = pb[tid]; sNb[tid] = nb[tid]; }
    __syncthreads();
    int n = blockIdx.x * 128 + tid;
    if (n >= NN_) return;
    u64 accP[16], accN[16];
    #pragma unroll
    for (int j = 0; j < 16; j++) { accP[j] = 0ull; accN[j] = 0ull; }
    const uint2* z2 = reinterpret_cast<const uint2*>(zin) + (size_t)n * 16;
    const uint2* aP = reinterpret_cast<const uint2*>(g_aggP16) + (size_t)n * 16;
    const uint2* aN = reinterpret_cast<const uint2*>(g_aggN16) + (size_t)n * 16;
    #pragma unroll 1
    for (int i4 = 0; i4 < 8; i4++) {
        uint2 zpw = z2[i4], znw = z2[8 + i4];
        uint2 aplw = aP[i4], aphw = aP[8 + i4];
        uint2 anlw = aN[i4], anhw = aN[8 + i4];
        float2 zp0 = bf2f(zpw.x), zp1 = bf2f(zpw.y);
        float2 zn0 = bf2f(znw.x), zn1 = bf2f(znw.y);
        float2 apl0 = bf2f(aplw.x), apl1 = bf2f(aplw.y);   // mean_pos(xp)
        float2 aph0 = bf2f(aphw.x), aph1 = bf2f(aphw.y);   // mean_pos(xn)
        float2 anl0 = bf2f(anlw.x), anl1 = bf2f(anlw.y);   // mean_neg(xp)
        float2 anh0 = bf2f(anhw.x), anh1 = bf2f(anhw.y);   // mean_neg(xn)
        float zps[4] = {zp0.x, zp0.y, zp1.x, zp1.y};
        float zns[4] = {zn0.x, zn0.y, zn1.x, zn1.y};
        float aplo[4] = {apl0.x, apl0.y, apl1.x, apl1.y};  // ap[i]    = mean_pos(xp)
        float anlo[4] = {aph0.x, aph0.y, aph1.x, aph1.y};  // an[i]    = mean_pos(xn)
        float aphi[4] = {anh0.x, anh0.y, anh1.x, anh1.y};  // ap[i+32] = mean_neg(xn)
        float anhi[4] = {anl0.x, anl0.y, anl1.x, anl1.y};  // an[i+32] = mean_neg(xp)
        #pragma unroll
        for (int c = 0; c < 4; c++) {
            int i = i4 * 4 + c;
            const u64* wPlo = reinterpret_cast<const u64*>(&sPl[i * 32]);
            const u64* wPhi = reinterpret_cast<const u64*>(&sPl[(i + 32) * 32]);
            const u64* wNlo = reinterpret_cast<const u64*>(&sNl[i * 32]);
            const u64* wNhi = reinterpret_cast<const u64*>(&sNl[(i + 32) * 32]);
            const u64* wPr  = reinterpret_cast<const u64*>(&sPr[i * 32]);
            const u64* wNr  = reinterpret_cast<const u64*>(&sNr[i * 32]);
            u64 apl = dup2(aplo[c]), aph = dup2(aphi[c]);
            u64 anl_ = dup2(anlo[c]), anh = dup2(anhi[c]);
            u64 xp2 = dup2(zps[c]), xn2 = dup2(zns[c]);
            #pragma unroll
            for (int j = 0; j < 16; j++) {
                accP[j] = fma2(apl, wPlo[j], fma2(aph, wPhi[j], fma2(xp2, wPr[j], accP[j])));
                accN[j] = fma2(anl_, wNlo[j], fma2(anh, wNhi[j], fma2(xn2, wNr[j], accN[j])));
            }
        }
    }
    u32* zr = reinterpret_cast<u32*>(zout) + (size_t)n * 32;
    #pragma unroll
    for (int j = 0; j < 16; j++) {
        float p0, p1, n0, n1;
        up2(accP[j], p0, p1); up2(accN[j], n0, n1);
        p0 += sPb[2 * j]; p1 += sPb[2 * j + 1];
        n0 += sNb[2 * j]; n1 += sNb[2 * j + 1];
        p0 = p0 > 0.f ? p0 : 0.f; p1 = p1 > 0.f ? p1 : 0.f;
        n0 = n0 > 0.f ? n0 : 0.f; n1 = n1 > 0.f ? n1 : 0.f;
        zr[j]      = f2bf(p0, p1);
        zr[16 + j] = f2bf(n0, n1);
    }
}

// ---------------- per-edge classifier -> semantic mask (bf16 z rows in zA) ----------------
__global__ __launch_bounds__(256) void k_val(const int* __restrict__ ei,
                                             const float* __restrict__ lw,
                                             const float* __restrict__ lb)
{
    __shared__ __align__(8) u64 sl01[128];
    __shared__ float sl2[128];
    if (threadIdx.x < 128) {
        int i = threadIdx.x;
        sl01[i] = pk2(lw[i * 3 + 0], lw[i * 3 + 1]);
        sl2[i]  = lw[i * 3 + 2];
    }
    __syncthreads();
    int t = blockIdx.x * 256 + threadIdx.x;
    float m = 0.f;
    if (t < E_) {
        int e0 = ei[t], e1 = ei[E_ + t];
        u64 l01 = pk2(lb[0], lb[1]);
        float l2 = lb[2];
        const uint4* za = reinterpret_cast<const uint4*>(g_zA) + (size_t)e0 * 8;
        const uint4* zb = reinterpret_cast<const uint4*>(g_zA) + (size_t)e1 * 8;
        #pragma unroll
        for (int k = 0; k < 8; k++) {
            uint4 aa = za[k], bb = zb[k];
            u32 aw[4] = {aa.x, aa.y, aa.z, aa.w};
            u32 bw[4] = {bb.x, bb.y, bb.z, bb.w};
            #pragma unroll
            for (int w = 0; w < 4; w++) {
                int idx = k * 4 + w;
                float2 al = bf2f(aw[w]), bl = bf2f(bw[w]);
                l01 = fma2(dup2(al.x), sl01[2 * idx],
                      fma2(dup2(al.y), sl01[2 * idx + 1],
                      fma2(dup2(bl.x), sl01[64 + 2 * idx],
                      fma2(dup2(bl.y), sl01[64 + 2 * idx + 1], l01))));
                l2 = fmaf(al.x, sl2[2 * idx],
                     fmaf(al.y, sl2[2 * idx + 1],
                     fmaf(bl.x, sl2[64 + 2 * idx],
                     fmaf(bl.y, sl2[64 + 2 * idx + 1], l2))));
            }
        }
        float l0, l1;
        up2(l01, l0, l1);
        int cls = 0; float best = l0;
        if (l1 > best) { best = l1; cls = 1; }
        if (l2 > best) { cls = 2; }
        m = (float)(cls - 1);
        g_maskS[t] = m;
    }
    float tot = block_reduce_sum_256(fabsf(m));
    if (threadIdx.x == 0) atomicAdd(&g_sums[1], tot);
}

// ---------------- mask fusion -> binary edge weight + degree ----------------
__global__ void k_fuse(const int* __restrict__ ei, const float* __restrict__ fw) {
    int t = blockIdx.x * blockDim.x + threadIdx.x;
    if (t >= E_) return;
    float w0 = fw[0], w1 = fw[1], w2 = fw[2];
    float mx = fmaxf(w0, fmaxf(w1, w2));
    float x0 = expf(w0 - mx), x1 = expf(w1 - mx), x2 = expf(w2 - mx);
    float si = 1.f / (x0 + x1 + x2);
    float Sf = fmaxf(g_sums[0], 1e-12f);
    float Ss = fmaxf(g_sums[1], 1e-12f);
    float fused = x0 * si * (1.0f / (float)E_)
                + x1 * si * g_maskF[t] / Sf
                + x2 * si * g_maskS[t] / Ss;
    float w = (fused > 0.5f) ? 1.f : 0.f;
    g_w[t] = w;
    if (w != 0.f) atomicAdd(&g_deg[ei[t]], w);
}

__global__ void k_normc(const int* __restrict__ ei) {
    int t = blockIdx.x * blockDim.x + threadIdx.x;
    if (t >= E_) return;
    float w = g_w[t];
    if (w == 0.f) { g_norm[t] = 0.f; return; }
    int a = ei[t], b = ei[E_ + t];
    float d0 = g_deg[a], d1 = g_deg[b];
    float dis0 = d0 > 0.f ? rsqrtf(fmaxf(d0, 1e-12f)) : 0.f;
    float dis1 = d1 > 0.f ? rsqrtf(fmaxf(d1, 1e-12f)) : 0.f;
    g_norm[t] = dis0 * w * dis1;
}

// ---------------- LightGCN hops (pre-zeroed outputs; skip zero-weight edges) ----------------
__global__ __launch_bounds__(256) void k_prop1(const int* __restrict__ ei,
                                               const float* __restrict__ lgu,
                                               const float* __restrict__ lgi)
{
    int e = blockIdx.x * 256 + threadIdx.x;
    if (e >= E_) return;
    float nv = g_norm[e];
    if (nv == 0.f) return;
    int d = ei[e], s = ei[E_ + e];
    const float4* xs = (s < NU_)
        ? reinterpret_cast<const float4*>(lgu) + (size_t)s * 16
        : reinterpret_cast<const float4*>(lgi) + (size_t)(s - NU_) * 16;
    float* ob = g_xkA + (size_t)d * 64;
    #pragma unroll
    for (int c = 0; c < 16; c++) {
        float4 v = xs[c];
        atomicAdd(ob + c * 4 + 0, nv * v.x);
        atomicAdd(ob + c * 4 + 1, nv * v.y);
        atomicAdd(ob + c * 4 + 2, nv * v.z);
        atomicAdd(ob + c * 4 + 3, nv * v.w);
    }
}

__global__ __launch_bounds__(256) void k_prop(const int* __restrict__ ei,
                                              const float* __restrict__ xin,
                                              float* __restrict__ xout)
{
    int e = blockIdx.x * 256 + threadIdx.x;
    if (e >= E_) return;
    float nv = g_norm[e];
    if (nv == 0.f) return;
    int d = ei[e], s = ei[E_ + e];
    const float4* xs = reinterpret_cast<const float4*>(xin + (size_t)s * 64);
    float* ob = xout + (size_t)d * 64;
    #pragma unroll
    for (int c = 0; c < 16; c++) {
        float4 v = xs[c];
        atomicAdd(ob + c * 4 + 0, nv * v.x);
        atomicAdd(ob + c * 4 + 1, nv * v.y);
        atomicAdd(ob + c * 4 + 2, nv * v.z);
        atomicAdd(ob + c * 4 + 3, nv * v.w);
    }
}

// ---------------- final output: out = (emb + A + B + C)/4 + emb passthrough ----------------
__global__ void k_output(float* __restrict__ out,
                         const float* __restrict__ lgu, const float* __restrict__ lgi)
{
    int t = blockIdx.x * blockDim.x + threadIdx.x;
    if (t >= NND_) return;
    float embv = (t < NUD_) ? lgu[t] : lgi[t - NUD_];
    float fv = (embv + g_xkA[t] + g_xkB[t] + g_xkC[t]) * 0.25f;
    if (t < NUD_) {
        out[t]        = fv;
        out[NUD_ + t] = embv;
    } else {
        int j = t - NUD_;
        out[2 * NUD_ + j]        = fv;
        out[2 * NUD_ + NFD_ + j] = embv;
    }
}

// ---------------- host orchestration ----------------
extern "C" void kernel_launch(void* const* d_in, const int* in_sizes, int n_in,
                              void* d_out, int out_size)
{
    (void)in_sizes; (void)n_in; (void)out_size;
    const float* user_feat = (const float*)d_in[0];
    const float* food_feat = (const float*)d_in[1];
    const int*   edge      = (const int*)d_in[2];
    const int*   pedge     = (const int*)d_in[3];
    const int*   nedge     = (const int*)d_in[4];
    const float* W_user    = (const float*)d_in[5];
    const float* b_user    = (const float*)d_in[6];
    const float* W_food    = (const float*)d_in[7];
    const float* b_food    = (const float*)d_in[8];
    const float* metric    = (const float*)d_in[9];
    const float* fusion    = (const float*)d_in[10];
    const float* sg_u      = (const float*)d_in[11];
    const float* sg_i      = (const float*)d_in[12];
    const float* c1pl      = (const float*)d_in[13];
    const float* c1pr      = (const float*)d_in[14];
    const float* c1pb      = (const float*)d_in[15];
    const float* c1nl      = (const float*)d_in[16];
    const float* c1nr      = (const float*)d_in[17];
    const float* c1nb      = (const float*)d_in[18];
    const float* cspl      = (const float*)d_in[19];
    const float* cspr      = (const float*)d_in[20];
    const float* cspb      = (const float*)d_in[21];
    const float* csnl      = (const float*)d_in[22];
    const float* csnr      = (const float*)d_in[23];
    const float* csnb      = (const float*)d_in[24];
    const float* linw      = (const float*)d_in[25];
    const float* linb      = (const float*)d_in[26];
    const float* lg_u      = (const float*)d_in[27];
    const float* lg_i      = (const float*)d_in[28];
    float* out = (float*)d_out;

    float *pxkA, *pxkB, *pxkC;
    unsigned short *pzA, *pzB;
    cudaGetSymbolAddress((void**)&pxkA, g_xkA);
    cudaGetSymbolAddress((void**)&pxkB, g_xkB);
    cudaGetSymbolAddress((void**)&pxkC, g_xkC);
    cudaGetSymbolAddress((void**)&pzA,  g_zA);
    cudaGetSymbolAddress((void**)&pzB,  g_zB);

    const int SB = cdiv(NN_, 1024);

    cudaStream_t s1;
    cudaStreamCreateWithFlags(&s1, cudaStreamNonBlocking);
    cudaEvent_t evFork, evJoin;
    cudaEventCreateWithFlags(&evFork, cudaEventDisableTiming);
    cudaEventCreateWithFlags(&evJoin, cudaEventDisableTiming);

    // fused init (hop buffers zero, counters, sums, tails)
    k_init<<<cdiv(NND_ / 4, 256), 256>>>();
    cudaEventRecord(evFork, 0);
    cudaStreamWaitEvent(s1, evFork, 0);

    // ---- branch A (stream 0): GEMMs + edge similarity ----
    k_gemm_relu<<<dim3(cdiv(NU_, 64), 2), 256>>>(user_feat, W_user, b_user,
                                                 food_feat, W_food, b_food, metric);
    k_edge_sim<<<cdiv(E_, 256), 256>>>(edge, metric);

    // ---- branch B (stream s1): CSR + signed conv + classifier ----
    k_countboth<<<cdiv(EP_ + EN_, 256), 256, 0, s1>>>(pedge, nedge);
    k_scan1<<<dim3(SB, 2), 1024, 0, s1>>>();
    k_scan2<<<2, 128, 0, s1>>>(SB);
    k_scan3<<<dim3(SB, 2), 1024, 0, s1>>>();
    k_fillboth<<<cdiv(EP_ + EN_, 256), 256, 0, s1>>>(pedge, nedge);

    const int GG = cdiv(NN_ * 32, 256);
    k_gather2<1><<<dim3(GG, 2), 256, 0, s1>>>(sg_u, sg_i, nullptr);
    k_layer1<<<cdiv(NN_, 128), 128, 0, s1>>>(c1pl, c1pr, c1pb, c1nl, c1nr, c1nb, sg_u, sg_i);
    k_gather2<0><<<dim3(GG, 2), 256, 0, s1>>>(nullptr, nullptr, pzA);
    k_layer23<<<cdiv(NN_, 128), 128, 0, s1>>>(cspl, cspr, cspb, csnl, csnr, csnb, pzA, pzB);
    k_gather2<0><<<dim3(GG, 2), 256, 0, s1>>>(nullptr, nullptr, pzB);
    k_layer23<<<cdiv(NN_, 128), 128, 0, s1>>>(cspl + 2048, cspr + 1024, cspb + 32,
                                              csnl + 2048, csnr + 1024, csnb + 32, pzB, pzA);
    k_val<<<cdiv(E_, 256), 256, 0, s1>>>(edge, linw, linb);
    cudaEventRecord(evJoin, s1);
    cudaStreamWaitEvent(0, evJoin, 0);

    // ---- join: fusion + propagation + output (stream 0) ----
    k_fuse<<<cdiv(E_, 256), 256>>>(edge, fusion);
    k_normc<<<cdiv(E_, 256), 256>>>(edge);

    k_prop1<<<cdiv(E_, 256), 256>>>(edge, lg_u, lg_i);
    k_prop<<<cdiv(E_, 256), 256>>>(edge, pxkA, pxkB);
    k_prop<<<cdiv(E_, 256), 256>>>(edge, pxkB, pxkC);

    k_output<<<cdiv(NND_, 256), 256>>>(out, lg_u, lg_i);
}

// round 8
// speedup vs baseline: 2.7971x; 1.0084x over previous
#include <cuda_runtime.h>
#include <cuda_bf16.h>
#include <cstdint>

#define NU_ 50000
#define NF_ 50000
#define NN_ 100000
#define D_ 64
#define H2_ 32
#define K_ 256
#define E_ 500000
#define EP_ 500000
#define EN_ 500000
#define NND_ (NN_*D_)
#define NUD_ (NU_*D_)
#define NFD_ (NF_*D_)

typedef unsigned long long u64;
typedef unsigned int u32;

// ---------------- f32x2 / bf16 helpers ----------------
__device__ __forceinline__ u64 pk2(float lo, float hi) {
    u64 r; asm("mov.b64 %0, {%1,%2};" : "=l"(r) : "f"(lo), "f"(hi)); return r;
}
__device__ __forceinline__ u64 dup2(float v) {
    u64 r; asm("mov.b64 %0, {%1,%1};" : "=l"(r) : "f"(v)); return r;
}
__device__ __forceinline__ void up2(u64 v, float& lo, float& hi) {
    asm("mov.b64 {%0,%1}, %2;" : "=f"(lo), "=f"(hi) : "l"(v));
}
__device__ __forceinline__ u64 fma2(u64 a, u64 b, u64 c) {
    u64 d; asm("fma.rn.f32x2 %0, %1, %2, %3;" : "=l"(d) : "l"(a), "l"(b), "l"(c)); return d;
}
__device__ __forceinline__ u64 mul2(u64 a, u64 b) {
    u64 d; asm("mul.rn.f32x2 %0, %1, %2;" : "=l"(d) : "l"(a), "l"(b)); return d;
}
__device__ __forceinline__ float2 bf2f(u32 w) {
    __nv_bfloat162 h = *reinterpret_cast<__nv_bfloat162*>(&w);
    return __bfloat1622float2(h);
}
__device__ __forceinline__ u32 f2bf(float a, float b) {
    __nv_bfloat162 h = __floats2bfloat162_rn(a, b);
    return *reinterpret_cast<u32*>(&h);
}

// ---------------- scratch (static device globals; no allocation) ----------------
__device__ unsigned short g_u16[NUD_];   // bf16 user features (sim only)
__device__ unsigned short g_f16[NFD_];   // bf16 food features (sim only)
__device__ float g_nau[NU_ * 4];         // per-user per-head norms
__device__ float g_naf[NF_ * 4];         // per-food per-head norms
__device__ unsigned short g_zA[NND_];    // bf16 z (layers 1,3 out; val reads this)
__device__ unsigned short g_zB[NND_];    // bf16 z (layer 2 out)
__device__ unsigned short g_aggP16[NND_];
__device__ unsigned short g_aggN16[NND_];
__device__ int   g_cntp[NN_];
__device__ int   g_cntn[NN_];
__device__ int   g_offP[NN_ + 1];
__device__ int   g_offN[NN_ + 1];
__device__ int   g_curP[NN_];
__device__ int   g_curN[NN_];
__device__ int   g_adjP[EP_];
__device__ int   g_adjN[EN_];
__device__ int   g_bsum[256];            // [2][128]
__device__ float g_maskF[E_];
__device__ float g_maskS[E_];
__device__ float g_w[E_];
__device__ float g_norm[E_];
__device__ float g_deg[NN_];
__device__ float g_xkA[NND_];            // hop-1 result
__device__ float g_xkB[NND_];            // hop-2 result
__device__ float g_xkC[NND_];            // hop-3 result
__device__ float g_sums[4];

static inline int cdiv(int a, int b) { return (a + b - 1) / b; }

// ---------------- fused init: zero hop buffers + counters + sums + tails ----------------
__global__ void k_init() {
    int i = blockIdx.x * blockDim.x + threadIdx.x;
    if (i < NND_ / 4) {
        float4 z4 = make_float4(0.f, 0.f, 0.f, 0.f);
        reinterpret_cast<float4*>(g_xkA)[i] = z4;
        reinterpret_cast<float4*>(g_xkB)[i] = z4;
        reinterpret_cast<float4*>(g_xkC)[i] = z4;
    }
    if (i < NN_) { g_cntp[i] = 0; g_cntn[i] = 0; g_deg[i] = 0.f; }
    if (i == 0) {
        g_sums[0] = 0.f; g_sums[1] = 0.f; g_sums[2] = 0.f; g_sums[3] = 0.f;
        g_offP[NN_] = EP_; g_offN[NN_] = EN_;
    }
}

__device__ __forceinline__ float block_reduce_sum_256(float v) {
    __shared__ float sh[8];
    int lane = threadIdx.x & 31, w = threadIdx.x >> 5;
    #pragma unroll
    for (int o = 16; o > 0; o >>= 1) v += __shfl_down_sync(0xffffffffu, v, o);
    if (lane == 0) sh[w] = v;
    __syncthreads();
    if (w == 0) {
        v = (lane < 8) ? sh[lane] : 0.f;
        #pragma unroll
        for (int o = 4; o > 0; o >>= 1) v += __shfl_down_sync(0xffffffffu, v, o);
    }
    return v;
}

// ---------------- CSR build ----------------
__global__ void k_countboth(const int* __restrict__ pe, const int* __restrict__ ne) {
    int t = blockIdx.x * blockDim.x + threadIdx.x;
    if (t < EP_) atomicAdd(&g_cntp[pe[EP_ + t]], 1);
    else if (t < EP_ + EN_) atomicAdd(&g_cntn[ne[EN_ + (t - EP_)]], 1);
}

__device__ __forceinline__ int warp_scan_incl(int v, int lane) {
    #pragma unroll
    for (int o = 1; o < 32; o <<= 1) {
        int u = __shfl_up_sync(0xffffffffu, v, o);
        if (lane >= o) v += u;
    }
    return v;
}

__global__ __launch_bounds__(1024) void k_scan1() {
    __shared__ int wsum[32];
    int y = blockIdx.y;
    const int* cnt = y ? g_cntn : g_cntp;
    int* out = y ? g_offN : g_offP;
    int t = threadIdx.x, lane = t & 31, w = t >> 5;
    int i = blockIdx.x * 1024 + t;
    int v = (i < NN_) ? cnt[i] : 0;
    int s = warp_scan_incl(v, lane);
    if (lane == 31) wsum[w] = s;
    __syncthreads();
    if (w == 0) {
        int x = wsum[lane];
        x = warp_scan_incl(x, lane);
        wsum[lane] = x;
    }
    __syncthreads();
    int base = (w > 0) ? wsum[w - 1] : 0;
    if (i < NN_) out[i] = base + s - v;
    if (t == 1023) g_bsum[y * 128 + blockIdx.x] = base + s;
}

__global__ __launch_bounds__(128) void k_scan2(int nb) {
    __shared__ int wsum[4];
    int* bsum = g_bsum + blockIdx.x * 128;
    int t = threadIdx.x, lane = t & 31, w = t >> 5;
    int v = (t < nb) ? bsum[t] : 0;
    int s = warp_scan_incl(v, lane);
    if (lane == 31) wsum[w] = s;
    __syncthreads();
    int add = 0;
    #pragma unroll
    for (int k = 0; k < 4; k++) if (k < w) add += wsum[k];
    if (t < nb) bsum[t] = add + s - v;
}

__global__ __launch_bounds__(1024) void k_scan3() {
    int y = blockIdx.y;
    int* out = y ? g_offN : g_offP;
    int* cur = y ? g_curN : g_curP;
    int i = blockIdx.x * 1024 + threadIdx.x;
    if (i < NN_) {
        int v = out[i] + g_bsum[y * 128 + blockIdx.x];
        out[i] = v;
        cur[i] = v;
    }
}

__global__ void k_fillboth(const int* __restrict__ pe, const int* __restrict__ ne) {
    int t = blockIdx.x * blockDim.x + threadIdx.x;
    if (t < EP_) {
        int d = pe[EP_ + t];
        int slot = atomicAdd(&g_curP[d], 1);
        g_adjP[slot] = pe[t];
    } else if (t < EP_ + EN_) {
        int u = t - EP_;
        int d = ne[EN_ + u];
        int slot = atomicAdd(&g_curN[d], 1);
        g_adjN[slot] = ne[u];
    }
}

// ---------------- dual warp-per-node segment MEAN gather -> bf16 agg ----------------
// FIRST=1: source is fp32 sg_u/sg_i tables; FIRST=0: source is a bf16 z table.
template<int FIRST>
__global__ __launch_bounds__(256) void k_gather2(const float* __restrict__ su,
                                                 const float* __restrict__ si,
                                                 const unsigned short* __restrict__ zsrc)
{
    int y = blockIdx.y;
    const int* off = y ? g_offN : g_offP;
    const int* adj = y ? g_adjN : g_adjP;
    u32* outm = reinterpret_cast<u32*>(y ? g_aggN16 : g_aggP16);
    int g = blockIdx.x * 256 + threadIdx.x;
    int node = g >> 5, lane = g & 31;
    if (node >= NN_) return;
    int s = off[node], e = off[node + 1];
    float2 acc = make_float2(0.f, 0.f);
    if (FIRST) {
        for (int k = s; k < e; k++) {
            int sr = adj[k];
            const float2* row = (sr < NU_)
                ? reinterpret_cast<const float2*>(su) + (size_t)sr * 32
                : reinterpret_cast<const float2*>(si) + (size_t)(sr - NU_) * 32;
            float2 v = row[lane];
            acc.x += v.x; acc.y += v.y;
        }
    } else {
        const u32* zb = reinterpret_cast<const u32*>(zsrc);
        for (int k = s; k < e; k++) {
            int sr = adj[k];
            float2 v = bf2f(zb[(size_t)sr * 32 + lane]);
            acc.x += v.x; acc.y += v.y;
        }
    }
    float inv = 1.f / (float)max(e - s, 1);
    outm[(size_t)node * 32 + lane] = f2bf(acc.x * inv, acc.y * inv);
}

// ---------------- merged feature GEMM (user+food via blockIdx.y), bf16 out + norms ----------------
__global__ __launch_bounds__(256) void k_gemm_relu(
    const float* __restrict__ Au, const float* __restrict__ Wu, const float* __restrict__ bu,
    const float* __restrict__ Af, const float* __restrict__ Wf, const float* __restrict__ bf,
    const float* __restrict__ mw)
{
    __shared__ __align__(16) float AsT[64][68];
    __shared__ __align__(16) float Ws[64][64];
    __shared__ float sW[256];
    int yb = blockIdx.y;
    const float* A = yb ? Af : Au;
    const float* W = yb ? Wf : Wu;
    const float* bias = yb ? bf : bu;
    unsigned short* C = yb ? g_f16 : g_u16;
    float* NA = yb ? g_naf : g_nau;
    const int M = yb ? NF_ : NU_;

    int tid = threadIdx.x;
    if (tid < 256) sW[tid] = mw[tid];
    int r0 = blockIdx.x * 64;
    int tr = tid >> 4, tc = tid & 15;
    u64 acc2[4][2];
    #pragma unroll
    for (int i = 0; i < 4; i++) { acc2[i][0] = 0ull; acc2[i][1] = 0ull; }

    for (int kc = 0; kc < K_; kc += 64) {
        #pragma unroll
        for (int it = 0; it < 16; it++) {
            int idx = tid + it * 256;
            int lr = idx >> 6, lk = idx & 63;
            int gr = r0 + lr;
            AsT[lk][lr] = (gr < M) ? A[(size_t)gr * K_ + kc + lk] : 0.f;
        }
        #pragma unroll
        for (int it = 0; it < 16; it++) {
            int idx = tid + it * 256;
            int lk = idx >> 6, n = idx & 63;
            Ws[lk][n] = W[(size_t)(kc + lk) * 64 + n];
        }
        __syncthreads();
        #pragma unroll 4
        for (int kk = 0; kk < 64; kk++) {
            float4 a4 = *reinterpret_cast<const float4*>(&AsT[kk][tr * 4]);
            const u64* w2 = reinterpret_cast<const u64*>(&Ws[kk][tc * 4]);
            u64 wlo = w2[0], whi = w2[1];
            u64 a0 = dup2(a4.x), a1 = dup2(a4.y), a2 = dup2(a4.z), a3 = dup2(a4.w);
            acc2[0][0] = fma2(a0, wlo, acc2[0][0]); acc2[0][1] = fma2(a0, whi, acc2[0][1]);
            acc2[1][0] = fma2(a1, wlo, acc2[1][0]); acc2[1][1] = fma2(a1, whi, acc2[1][1]);
            acc2[2][0] = fma2(a2, wlo, acc2[2][0]); acc2[2][1] = fma2(a2, whi, acc2[2][1]);
            acc2[3][0] = fma2(a3, wlo, acc2[3][0]); acc2[3][1] = fma2(a3, whi, acc2[3][1]);
        }
        __syncthreads();
    }
    int col = tc * 4;
    #pragma unroll
    for (int i = 0; i < 4; i++) {
        int row = r0 + tr * 4 + i;
        float v0, v1, v2, v3;
        up2(acc2[i][0], v0, v1);
        up2(acc2[i][1], v2, v3);
        v0 += bias[col + 0]; v1 += bias[col + 1];
        v2 += bias[col + 2]; v3 += bias[col + 3];
        v0 = v0 > 0.f ? v0 : 0.f; v1 = v1 > 0.f ? v1 : 0.f;
        v2 = v2 > 0.f ? v2 : 0.f; v3 = v3 > 0.f ? v3 : 0.f;
        float p[4];
        #pragma unroll
        for (int h = 0; h < 4; h++) {
            float w0 = sW[h * 64 + col + 0] * v0;
            float w1 = sW[h * 64 + col + 1] * v1;
            float w2_ = sW[h * 64 + col + 2] * v2;
            float w3 = sW[h * 64 + col + 3] * v3;
            p[h] = w0 * w0 + w1 * w1 + w2_ * w2_ + w3 * w3;
            #pragma unroll
            for (int o = 8; o > 0; o >>= 1)
                p[h] += __shfl_down_sync(0xffffffffu, p[h], o, 16);
        }
        if (row < M) {
            u32 w0 = f2bf(v0, v1), w1 = f2bf(v2, v3);
            *reinterpret_cast<uint2*>(&reinterpret_cast<u32*>(C)[(size_t)row * 32 + tc * 2]) =
                make_uint2(w0, w1);
            if (tc == 0) {
                float4 na = make_float4(fmaxf(sqrtf(p[0]), 1e-8f), fmaxf(sqrtf(p[1]), 1e-8f),
                                        fmaxf(sqrtf(p[2]), 1e-8f), fmaxf(sqrtf(p[3]), 1e-8f));
                *reinterpret_cast<float4*>(&NA[(size_t)row * 4]) = na;
            }
        }
    }
}

// ---------------- per-edge similarity mask: bf16 rows + precomputed norms ----------------
__global__ __launch_bounds__(256) void k_edge_sim(const int* __restrict__ ei,
                                                  const float* __restrict__ mw)
{
    __shared__ __align__(8) u64 swsq[4][32];
    if (threadIdx.x < 128) {
        int h = threadIdx.x >> 5, ip = threadIdx.x & 31;
        float wa = mw[h * 64 + 2 * ip], wb = mw[h * 64 + 2 * ip + 1];
        swsq[h][ip] = pk2(wa * wa, wb * wb);
    }
    __syncthreads();
    int t = blockIdx.x * 256 + threadIdx.x;
    float m = 0.f;
    if (t < E_) {
        int e0 = ei[t], e1 = ei[E_ + t];
        const uint4* ur = reinterpret_cast<const uint4*>(g_u16) + (size_t)e0 * 8;
        const uint4* fr = reinterpret_cast<const uint4*>(g_f16) + (size_t)e1 * 8;
        float4 na = *reinterpret_cast<const float4*>(&g_nau[(size_t)e0 * 4]);
        float4 nb = *reinterpret_cast<const float4*>(&g_naf[(size_t)e1 * 4]);
        u64 d0 = 0ull, d1 = 0ull, d2 = 0ull, d3 = 0ull;
        #pragma unroll
        for (int k = 0; k < 8; k++) {
            uint4 uu = ur[k], ff = fr[k];
            u32 uw[4] = {uu.x, uu.y, uu.z, uu.w};
            u32 fw[4] = {ff.x, ff.y, ff.z, ff.w};
            #pragma unroll
            for (int w = 0; w < 4; w++) {
                float2 ul = bf2f(uw[w]), fl = bf2f(fw[w]);
                u64 uf = mul2(pk2(ul.x, ul.y), pk2(fl.x, fl.y));
                int ip = k * 4 + w;
                d0 = fma2(uf, swsq[0][ip], d0);
                d1 = fma2(uf, swsq[1][ip], d1);
                d2 = fma2(uf, swsq[2][ip], d2);
                d3 = fma2(uf, swsq[3][ip], d3);
            }
        }
        float a, b;
        float dh0, dh1, dh2, dh3;
        up2(d0, a, b); dh0 = a + b;
        up2(d1, a, b); dh1 = a + b;
        up2(d2, a, b); dh2 = a + b;
        up2(d3, a, b); dh3 = a + b;
        float sim = __fdividef(dh0, na.x * nb.x) + __fdividef(dh1, na.y * nb.y)
                  + __fdividef(dh2, na.z * nb.z) + __fdividef(dh3, na.w * nb.w);
        sim *= 0.25f;
        m = (sim < 0.3f) ? 0.f : sim;
        g_maskF[t] = m;
    }
    float tot = block_reduce_sum_256(fabsf(m));
    if (threadIdx.x == 0) atomicAdd(&g_sums[0], tot);
}

// ---------------- signed conv layer 1 (x from sg tables fp32; agg bf16; out bf16 zA) ----------------
__global__ __launch_bounds__(128) void k_layer1(
    const float* __restrict__ pl, const float* __restrict__ prw, const float* __restrict__ pb,
    const float* __restrict__ nl, const float* __restrict__ nrw, const float* __restrict__ nb,
    const float* __restrict__ su, const float* __restrict__ si)
{
    __shared__ __align__(8) float sPl[2048], sPr[2048], sNl[2048], sNr[2048];
    __shared__ float sPb[32], sNb[32];
    int tid = threadIdx.x;
    for (int i = tid; i < 2048; i += 128) {
        sPl[i] = pl[i]; sPr[i] = prw[i]; sNl[i] = nl[i]; sNr[i] = nrw[i];
    }
    if (tid < 32) { sPb[tid] = pb[tid]; sNb[tid] = nb[tid]; }
    __syncthreads();
    int n = blockIdx.x * 128 + tid;
    if (n >= NN_) return;
    u64 accP[16], accN[16];
    #pragma unroll
    for (int j = 0; j < 16; j++) { accP[j] = 0ull; accN[j] = 0ull; }
    const float4* xr = (n < NU_)
        ? reinterpret_cast<const float4*>(su) + (size_t)n * 16
        : reinterpret_cast<const float4*>(si) + (size_t)(n - NU_) * 16;
    const uint2* pr = reinterpret_cast<const uint2*>(g_aggP16) + (size_t)n * 16;
    const uint2* nr = reinterpret_cast<const uint2*>(g_aggN16) + (size_t)n * 16;
    #pragma unroll 1
    for (int i4 = 0; i4 < 16; i4++) {
        float4 xv4 = xr[i4];
        uint2 mpw = pr[i4], mnw = nr[i4];
        float2 mplo = bf2f(mpw.x), mphi = bf2f(mpw.y);
        float2 mnlo = bf2f(mnw.x), mnhi = bf2f(mnw.y);
        float xs[4] = {xv4.x, xv4.y, xv4.z, xv4.w};
        float ms[4] = {mplo.x, mplo.y, mphi.x, mphi.y};
        float ns[4] = {mnlo.x, mnlo.y, mnhi.x, mnhi.y};
        #pragma unroll
        for (int c = 0; c < 4; c++) {
            int i = i4 * 4 + c;
            u64 xv2 = dup2(xs[c]), mv2 = dup2(ms[c]), nv2 = dup2(ns[c]);
            const u64* wpl = reinterpret_cast<const u64*>(&sPl[i * 32]);
            const u64* wpr = reinterpret_cast<const u64*>(&sPr[i * 32]);
            const u64* wnl = reinterpret_cast<const u64*>(&sNl[i * 32]);
            const u64* wnr = reinterpret_cast<const u64*>(&sNr[i * 32]);
            #pragma unroll
            for (int j = 0; j < 16; j++) {
                accP[j] = fma2(mv2, wpl[j], fma2(xv2, wpr[j], accP[j]));
                accN[j] = fma2(nv2, wnl[j], fma2(xv2, wnr[j], accN[j]));
            }
        }
    }
    u32* zr = reinterpret_cast<u32*>(g_zA) + (size_t)n * 32;
    #pragma unroll
    for (int j = 0; j < 16; j++) {
        float p0, p1, n0, n1;
        up2(accP[j], p0, p1); up2(accN[j], n0, n1);
        p0 += sPb[2 * j]; p1 += sPb[2 * j + 1];
        n0 += sNb[2 * j]; n1 += sNb[2 * j + 1];
        p0 = p0 > 0.f ? p0 : 0.f; p1 = p1 > 0.f ? p1 : 0.f;
        n0 = n0 > 0.f ? n0 : 0.f; n1 = n1 > 0.f ? n1 : 0.f;
        zr[j]      = f2bf(p0, p1);
        zr[16 + j] = f2bf(n0, n1);
    }
}

// ---------------- signed conv layers 2/3 (all bf16 in/out) ----------------
__global__ __launch_bounds__(128) void k_layer23(
    const float* __restrict__ pl, const float* __restrict__ prw, const float* __restrict__ pb,
    const float* __restrict__ nl, const float* __restrict__ nrw, const float* __restrict__ nb,
    const unsigned short* __restrict__ zin, unsigned short* __restrict__ zout)
{
    __shared__ __align__(8) float sPl[2048], sNl[2048], sPr[1024], sNr[1024];
    __shared__ float sPb[32], sNb[32];
    int tid = threadIdx.x;
    for (int i = tid; i < 2048; i += 128) { sPl[i] = pl[i]; sNl[i] = nl[i]; }
    for (int i = tid; i < 1024; i += 128) { sPr[i] = prw[i]; sNr[i] = nrw[i]; }
    if (tid < 32) { sPb[tid] = pb[tid]; sNb[tid] = nb[tid]; }
    __syncthreads();
    int n = blockIdx.x * 128 + tid;
    if (n >= NN_) return;
    u64 accP[16], accN[16];
    #pragma unroll
    for (int j = 0; j < 16; j++) { accP[j] = 0ull; accN[j] = 0ull; }
    const uint2* z2 = reinterpret_cast<const uint2*>(zin) + (size_t)n * 16;
    const uint2* aP = reinterpret_cast<const uint2*>(g_aggP16) + (size_t)n * 16;
    const uint2* aN = reinterpret_cast<const uint2*>(g_aggN16) + (size_t)n * 16;
    #pragma unroll 1
    for (int i4 = 0; i4 < 8; i4++) {
        uint2 zpw = z2[i4], znw = z2[8 + i4];
        uint2 aplw = aP[i4], aphw = aP[8 + i4];
        uint2 anlw = aN[i4], anhw = aN[8 + i4];
        float2 zp0 = bf2f(zpw.x), zp1 = bf2f(zpw.y);
        float2 zn0 = bf2f(znw.x), zn1 = bf2f(znw.y);
        float2 apl0 = bf2f(aplw.x), apl1 = bf2f(aplw.y);   // mean_pos(xp)
        float2 aph0 = bf2f(aphw.x), aph1 = bf2f(aphw.y);   // mean_pos(xn)
        float2 anl0 = bf2f(anlw.x), anl1 = bf2f(anlw.y);   // mean_neg(xp)
        float2 anh0 = bf2f(anhw.x), anh1 = bf2f(anhw.y);   // mean_neg(xn)
        float zps[4] = {zp0.x, zp0.y, zp1.x, zp1.y};
        float zns[4] = {zn0.x, zn0.y, zn1.x, zn1.y};
        float aplo[4] = {apl0.x, apl0.y, apl1.x, apl1.y};  // ap[i]    = mean_pos(xp)
        float anlo[4] = {aph0.x, aph0.y, aph1.x, aph1.y};  // an[i]    = mean_pos(xn)
        float aphi[4] = {anh0.x, anh0.y, anh1.x, anh1.y};  // ap[i+32] = mean_neg(xn)
        float anhi[4] = {anl0.x, anl0.y, anl1.x, anl1.y};  // an[i+32] = mean_neg(xp)
        #pragma unroll
        for (int c = 0; c < 4; c++) {
            int i = i4 * 4 + c;
            const u64* wPlo = reinterpret_cast<const u64*>(&sPl[i * 32]);
            const u64* wPhi = reinterpret_cast<const u64*>(&sPl[(i + 32) * 32]);
            const u64* wNlo = reinterpret_cast<const u64*>(&sNl[i * 32]);
            const u64* wNhi = reinterpret_cast<const u64*>(&sNl[(i + 32) * 32]);
            const u64* wPr  = reinterpret_cast<const u64*>(&sPr[i * 32]);
            const u64* wNr  = reinterpret_cast<const u64*>(&sNr[i * 32]);
            u64 apl = dup2(aplo[c]), aph = dup2(aphi[c]);
            u64 anl_ = dup2(anlo[c]), anh = dup2(anhi[c]);
            u64 xp2 = dup2(zps[c]), xn2 = dup2(zns[c]);
            #pragma unroll
            for (int j = 0; j < 16; j++) {
                accP[j] = fma2(apl, wPlo[j], fma2(aph, wPhi[j], fma2(xp2, wPr[j], accP[j])));
                accN[j] = fma2(anl_, wNlo[j], fma2(anh, wNhi[j], fma2(xn2, wNr[j], accN[j])));
            }
        }
    }
    u32* zr = reinterpret_cast<u32*>(zout) + (size_t)n * 32;
    #pragma unroll
    for (int j = 0; j < 16; j++) {
        float p0, p1, n0, n1;
        up2(accP[j], p0, p1); up2(accN[j], n0, n1);
        p0 += sPb[2 * j]; p1 += sPb[2 * j + 1];
        n0 += sNb[2 * j]; n1 += sNb[2 * j + 1];
        p0 = p0 > 0.f ? p0 : 0.f; p1 = p1 > 0.f ? p1 : 0.f;
        n0 = n0 > 0.f ? n0 : 0.f; n1 = n1 > 0.f ? n1 : 0.f;
        zr[j]      = f2bf(p0, p1);
        zr[16 + j] = f2bf(n0, n1);
    }
}

// ---------------- per-edge classifier -> semantic mask (bf16 z rows in zA) ----------------
__global__ __launch_bounds__(256) void k_val(const int* __restrict__ ei,
                                             const float* __restrict__ lw,
                                             const float* __restrict__ lb)
{
    __shared__ __align__(8) u64 sl01[128];
    __shared__ float sl2[128];
    if (threadIdx.x < 128) {
        int i = threadIdx.x;
        sl01[i] = pk2(lw[i * 3 + 0], lw[i * 3 + 1]);
        sl2[i]  = lw[i * 3 + 2];
    }
    __syncthreads();
    int t = blockIdx.x * 256 + threadIdx.x;
    float m = 0.f;
    if (t < E_) {
        int e0 = ei[t], e1 = ei[E_ + t];
        u64 l01 = pk2(lb[0], lb[1]);
        float l2 = lb[2];
        const uint4* za = reinterpret_cast<const uint4*>(g_zA) + (size_t)e0 * 8;
        const uint4* zb = reinterpret_cast<const uint4*>(g_zA) + (size_t)e1 * 8;
        #pragma unroll
        for (int k = 0; k < 8; k++) {
            uint4 aa = za[k], bb = zb[k];
            u32 aw[4] = {aa.x, aa.y, aa.z, aa.w};
            u32 bw[4] = {bb.x, bb.y, bb.z, bb.w};
            #pragma unroll
            for (int w = 0; w < 4; w++) {
                int idx = k * 4 + w;
                float2 al = bf2f(aw[w]), bl = bf2f(bw[w]);
                l01 = fma2(dup2(al.x), sl01[2 * idx],
                      fma2(dup2(al.y), sl01[2 * idx + 1],
                      fma2(dup2(bl.x), sl01[64 + 2 * idx],
                      fma2(dup2(bl.y), sl01[64 + 2 * idx + 1], l01))));
                l2 = fmaf(al.x, sl2[2 * idx],
                     fmaf(al.y, sl2[2 * idx + 1],
                     fmaf(bl.x, sl2[64 + 2 * idx],
                     fmaf(bl.y, sl2[64 + 2 * idx + 1], l2))));
            }
        }
        float l0, l1;
        up2(l01, l0, l1);
        int cls = 0; float best = l0;
        if (l1 > best) { best = l1; cls = 1; }
        if (l2 > best) { cls = 2; }
        m = (float)(cls - 1);
        g_maskS[t] = m;
    }
    float tot = block_reduce_sum_256(fabsf(m));
    if (threadIdx.x == 0) atomicAdd(&g_sums[1], tot);
}

// ---------------- mask fusion -> binary edge weight + degree ----------------
__global__ void k_fuse(const int* __restrict__ ei, const float* __restrict__ fw) {
    int t = blockIdx.x * blockDim.x + threadIdx.x;
    if (t >= E_) return;
    float w0 = fw[0], w1 = fw[1], w2 = fw[2];
    float mx = fmaxf(w0, fmaxf(w1, w2));
    float x0 = expf(w0 - mx), x1 = expf(w1 - mx), x2 = expf(w2 - mx);
    float si = 1.f / (x0 + x1 + x2);
    float Sf = fmaxf(g_sums[0], 1e-12f);
    float Ss = fmaxf(g_sums[1], 1e-12f);
    float fused = x0 * si * (1.0f / (float)E_)
                + x1 * si * g_maskF[t] / Sf
                + x2 * si * g_maskS[t] / Ss;
    float w = (fused > 0.5f) ? 1.f : 0.f;
    g_w[t] = w;
    if (w != 0.f) atomicAdd(&g_deg[ei[t]], w);
}

__global__ void k_normc(const int* __restrict__ ei) {
    int t = blockIdx.x * blockDim.x + threadIdx.x;
    if (t >= E_) return;
    float w = g_w[t];
    if (w == 0.f) { g_norm[t] = 0.f; return; }
    int a = ei[t], b = ei[E_ + t];
    float d0 = g_deg[a], d1 = g_deg[b];
    float dis0 = d0 > 0.f ? rsqrtf(fmaxf(d0, 1e-12f)) : 0.f;
    float dis1 = d1 > 0.f ? rsqrtf(fmaxf(d1, 1e-12f)) : 0.f;
    g_norm[t] = dis0 * w * dis1;
}

// ---------------- LightGCN hops (pre-zeroed outputs; skip zero-weight edges) ----------------
__global__ __launch_bounds__(256) void k_prop1(const int* __restrict__ ei,
                                               const float* __restrict__ lgu,
                                               const float* __restrict__ lgi)
{
    int e = blockIdx.x * 256 + threadIdx.x;
    if (e >= E_) return;
    float nv = g_norm[e];
    if (nv == 0.f) return;
    int d = ei[e], s = ei[E_ + e];
    const float4* xs = (s < NU_)
        ? reinterpret_cast<const float4*>(lgu) + (size_t)s * 16
        : reinterpret_cast<const float4*>(lgi) + (size_t)(s - NU_) * 16;
    float* ob = g_xkA + (size_t)d * 64;
    #pragma unroll
    for (int c = 0; c < 16; c++) {
        float4 v = xs[c];
        atomicAdd(ob + c * 4 + 0, nv * v.x);
        atomicAdd(ob + c * 4 + 1, nv * v.y);
        atomicAdd(ob + c * 4 + 2, nv * v.z);
        atomicAdd(ob + c * 4 + 3, nv * v.w);
    }
}

__global__ __launch_bounds__(256) void k_prop(const int* __restrict__ ei,
                                              const float* __restrict__ xin,
                                              float* __restrict__ xout)
{
    int e = blockIdx.x * 256 + threadIdx.x;
    if (e >= E_) return;
    float nv = g_norm[e];
    if (nv == 0.f) return;
    int d = ei[e], s = ei[E_ + e];
    const float4* xs = reinterpret_cast<const float4*>(xin + (size_t)s * 64);
    float* ob = xout + (size_t)d * 64;
    #pragma unroll
    for (int c = 0; c < 16; c++) {
        float4 v = xs[c];
        atomicAdd(ob + c * 4 + 0, nv * v.x);
        atomicAdd(ob + c * 4 + 1, nv * v.y);
        atomicAdd(ob + c * 4 + 2, nv * v.z);
        atomicAdd(ob + c * 4 + 3, nv * v.w);
    }
}

// ---------------- final output: out = (emb + A + B + C)/4 + emb passthrough ----------------
__global__ void k_output(float* __restrict__ out,
                         const float* __restrict__ lgu, const float* __restrict__ lgi)
{
    int t = blockIdx.x * blockDim.x + threadIdx.x;
    if (t >= NND_) return;
    float embv = (t < NUD_) ? lgu[t] : lgi[t - NUD_];
    float fv = (embv + g_xkA[t] + g_xkB[t] + g_xkC[t]) * 0.25f;
    if (t < NUD_) {
        out[t]        = fv;
        out[NUD_ + t] = embv;
    } else {
        int j = t - NUD_;
        out[2 * NUD_ + j]        = fv;
        out[2 * NUD_ + NFD_ + j] = embv;
    }
}

// ---------------- host orchestration ----------------
extern "C" void kernel_launch(void* const* d_in, const int* in_sizes, int n_in,
                              void* d_out, int out_size)
{
    (void)in_sizes; (void)n_in; (void)out_size;
    const float* user_feat = (const float*)d_in[0];
    const float* food_feat = (const float*)d_in[1];
    const int*   edge      = (const int*)d_in[2];
    const int*   pedge     = (const int*)d_in[3];
    const int*   nedge     = (const int*)d_in[4];
    const float* W_user    = (const float*)d_in[5];
    const float* b_user    = (const float*)d_in[6];
    const float* W_food    = (const float*)d_in[7];
    const float* b_food    = (const float*)d_in[8];
    const float* metric    = (const float*)d_in[9];
    const float* fusion    = (const float*)d_in[10];
    const float* sg_u      = (const float*)d_in[11];
    const float* sg_i      = (const float*)d_in[12];
    const float* c1pl      = (const float*)d_in[13];
    const float* c1pr      = (const float*)d_in[14];
    const float* c1pb      = (const float*)d_in[15];
    const float* c1nl      = (const float*)d_in[16];
    const float* c1nr      = (const float*)d_in[17];
    const float* c1nb      = (const float*)d_in[18];
    const float* cspl      = (const float*)d_in[19];
    const float* cspr      = (const float*)d_in[20];
    const float* cspb      = (const float*)d_in[21];
    const float* csnl      = (const float*)d_in[22];
    const float* csnr      = (const float*)d_in[23];
    const float* csnb      = (const float*)d_in[24];
    const float* linw      = (const float*)d_in[25];
    const float* linb      = (const float*)d_in[26];
    const float* lg_u      = (const float*)d_in[27];
    const float* lg_i      = (const float*)d_in[28];
    float* out = (float*)d_out;

    float *pxkA, *pxkB, *pxkC;
    unsigned short *pzA, *pzB;
    cudaGetSymbolAddress((void**)&pxkA, g_xkA);
    cudaGetSymbolAddress((void**)&pxkB, g_xkB);
    cudaGetSymbolAddress((void**)&pxkC, g_xkC);
    cudaGetSymbolAddress((void**)&pzA,  g_zA);
    cudaGetSymbolAddress((void**)&pzB,  g_zB);

    const int SB = cdiv(NN_, 1024);

    cudaStream_t s1;
    cudaStreamCreateWithFlags(&s1, cudaStreamNonBlocking);
    cudaEvent_t evFork, evJoin;
    cudaEventCreateWithFlags(&evFork, cudaEventDisableTiming);
    cudaEventCreateWithFlags(&evJoin, cudaEventDisableTiming);

    // fused init (hop buffers zero, counters, sums, tails)
    k_init<<<cdiv(NND_ / 4, 256), 256>>>();
    cudaEventRecord(evFork, 0);
    cudaStreamWaitEvent(s1, evFork, 0);

    // ---- branch A (stream 0): GEMMs + edge similarity ----
    k_gemm_relu<<<dim3(cdiv(NU_, 64), 2), 256>>>(user_feat, W_user, b_user,
                                                 food_feat, W_food, b_food, metric);
    k_edge_sim<<<cdiv(E_, 256), 256>>>(edge, metric);

    // ---- branch B (stream s1): CSR + signed conv + classifier ----
    k_countboth<<<cdiv(EP_ + EN_, 256), 256, 0, s1>>>(pedge, nedge);
    k_scan1<<<dim3(SB, 2), 1024, 0, s1>>>();
    k_scan2<<<2, 128, 0, s1>>>(SB);
    k_scan3<<<dim3(SB, 2), 1024, 0, s1>>>();
    k_fillboth<<<cdiv(EP_ + EN_, 256), 256, 0, s1>>>(pedge, nedge);

    const int GG = cdiv(NN_ * 32, 256);
    k_gather2<1><<<dim3(GG, 2), 256, 0, s1>>>(sg_u, sg_i, nullptr);
    k_layer1<<<cdiv(NN_, 128), 128, 0, s1>>>(c1pl, c1pr, c1pb, c1nl, c1nr, c1nb, sg_u, sg_i);
    k_gather2<0><<<dim3(GG, 2), 256, 0, s1>>>(nullptr, nullptr, pzA);
    k_layer23<<<cdiv(NN_, 128), 128, 0, s1>>>(cspl, cspr, cspb, csnl, csnr, csnb, pzA, pzB);
    k_gather2<0><<<dim3(GG, 2), 256, 0, s1>>>(nullptr, nullptr, pzB);
    k_layer23<<<cdiv(NN_, 128), 128, 0, s1>>>(cspl + 2048, cspr + 1024, cspb + 32,
                                              csnl + 2048, csnr + 1024, csnb + 32, pzB, pzA);
    k_val<<<cdiv(E_, 256), 256, 0, s1>>>(edge, linw, linb);
    cudaEventRecord(evJoin, s1);
    cudaStreamWaitEvent(0, evJoin, 0);

    // ---- join: fusion + propagation + output (stream 0) ----
    k_fuse<<<cdiv(E_, 256), 256>>>(edge, fusion);
    k_normc<<<cdiv(E_, 256), 256>>>(edge);

    k_prop1<<<cdiv(E_, 256), 256>>>(edge, lg_u, lg_i);
    k_prop<<<cdiv(E_, 256), 256>>>(edge, pxkA, pxkB);
    k_prop<<<cdiv(E_, 256), 256>>>(edge, pxkB, pxkC);

    k_output<<<cdiv(NND_, 256), 256>>>(out, lg_u, lg_i);
}